// round 6
// baseline (speedup 1.0000x reference)
#include <cuda_runtime.h>
#include <cuda_bf16.h>
#include <math.h>
#include <stdint.h>

// Problem constants
#define S_LEN 2048
#define DIM   2048
#define NHEAD 16
#define QL    1536
#define KVL   512
#define NOPE  128
#define ROPE_D 64
#define VH    128
#define QKD   192   // NOPE + ROPE
#define EPS   1e-6f

// ---------------- scratch (device globals; no allocation allowed) ----------
__device__ float g_qdown[S_LEN * QL];
__device__ float g_kv   [S_LEN * (KVL + ROPE_D)];
__device__ float g_kvnorm[S_LEN * KVL];
__device__ float g_q    [S_LEN * NHEAD * QKD];     // roped in place
__device__ float g_kvu  [S_LEN * NHEAD * (NOPE + VH)];
__device__ float g_kpe  [S_LEN * ROPE_D];

// bf16x3 operand scratch
__device__ __nv_bfloat16 g_A3[(size_t)S_LEN * 3 * DIM];          // 12.58M elems
__device__ __nv_bfloat16 g_B3[(size_t)3072 * 3 * 1536];          // 14.16M elems

// ---------------- fp32 -> (hi,lo) bf16 split kernels -----------------------
// A mode: dst row layout [hi(K) | lo(K) | hi(K)]
// B mode: dst row layout [hi(K) | hi(K) | lo(K)]
__global__ void split3_kernel(const float* __restrict__ src,
                              __nv_bfloat16* __restrict__ dst,
                              int K, int modeB)
{
    const int r = blockIdx.y;
    const int k = blockIdx.x * 256 + threadIdx.x;
    if (k >= K) return;
    const float v = src[(size_t)r * K + k];
    const __nv_bfloat16 h = __float2bfloat16(v);
    const __nv_bfloat16 l = __float2bfloat16(v - __bfloat162float(h));
    __nv_bfloat16* d = dst + (size_t)r * 3 * K;
    d[k] = h;
    d[K + k]     = modeB ? h : l;
    d[2 * K + k] = modeB ? l : h;
}

// ---------------- RMSNorm (fp32 out) ---------------------------------------
__global__ void rms_kernel(const float* __restrict__ in, const float* __restrict__ w,
                           float* __restrict__ out, int n, int istride, int ostride)
{
    const int row = blockIdx.x;
    const float* x = in + (size_t)row * istride;

    float ss = 0.f;
    for (int i = threadIdx.x; i < n; i += blockDim.x) {
        float v = x[i];
        ss += v * v;
    }
#pragma unroll
    for (int o = 16; o; o >>= 1) ss += __shfl_xor_sync(0xffffffffu, ss, o);

    __shared__ float warpsum[8];
    __shared__ float sScale;
    const int wid = threadIdx.x >> 5;
    if ((threadIdx.x & 31) == 0) warpsum[wid] = ss;
    __syncthreads();
    if (threadIdx.x == 0) {
        float tot = 0.f;
        for (int i = 0; i < (int)(blockDim.x >> 5); i++) tot += warpsum[i];
        sScale = rsqrtf(tot / (float)n + EPS);
    }
    __syncthreads();
    const float sc = sScale;
    for (int i = threadIdx.x; i < n; i += blockDim.x)
        out[(size_t)row * ostride + i] = x[i] * sc * w[i];
}

// ---------------- RMSNorm fused with bf16x3 A-split ------------------------
__global__ void rms_split_kernel(const float* __restrict__ in, const float* __restrict__ w,
                                 __nv_bfloat16* __restrict__ dst, int n)
{
    const int row = blockIdx.x;
    const float* x = in + (size_t)row * n;

    float ss = 0.f;
    for (int i = threadIdx.x; i < n; i += blockDim.x) {
        float v = x[i];
        ss += v * v;
    }
#pragma unroll
    for (int o = 16; o; o >>= 1) ss += __shfl_xor_sync(0xffffffffu, ss, o);

    __shared__ float warpsum[8];
    __shared__ float sScale;
    const int wid = threadIdx.x >> 5;
    if ((threadIdx.x & 31) == 0) warpsum[wid] = ss;
    __syncthreads();
    if (threadIdx.x == 0) {
        float tot = 0.f;
        for (int i = 0; i < (int)(blockDim.x >> 5); i++) tot += warpsum[i];
        sScale = rsqrtf(tot / (float)n + EPS);
    }
    __syncthreads();
    const float sc = sScale;
    __nv_bfloat16* d = dst + (size_t)row * 3 * n;
    for (int i = threadIdx.x; i < n; i += blockDim.x) {
        const float v = x[i] * sc * w[i];
        const __nv_bfloat16 h = __float2bfloat16(v);
        const __nv_bfloat16 l = __float2bfloat16(v - __bfloat162float(h));
        d[i] = h; d[n + i] = l; d[2 * n + i] = h;
    }
}

// ---------------- bf16x3 tensor-core GEMM (v4: frag-pipelined) -------------
// C[M,N] = A3[M,K3] * B3[N,K3]^T  (bf16 operands, fp32 accumulate)
#define TBM 128
#define TBN 128
#define TBK 32
#define AP  40      // smem pitch in bf16 (80B = 5 x 16B units -> conflict-free)
#define STAGES 5
#define GEMM_SMEM (STAGES * 2 * TBM * AP * 2)   // bytes = 102400

__device__ __forceinline__ unsigned smem_u32(const void* p) {
    return (unsigned)__cvta_generic_to_shared(p);
}
__device__ __forceinline__ void cp16(unsigned s, const void* g, bool pred) {
    int sz = pred ? 16 : 0;
    asm volatile("cp.async.cg.shared.global [%0], [%1], 16, %2;\n"
                 :: "r"(s), "l"(g), "r"(sz));
}
__device__ __forceinline__ void ldsm_x4(uint32_t& r0, uint32_t& r1,
                                        uint32_t& r2, uint32_t& r3, unsigned addr) {
    asm volatile("ldmatrix.sync.aligned.m8n8.x4.shared.b16 {%0,%1,%2,%3}, [%4];"
                 : "=r"(r0), "=r"(r1), "=r"(r2), "=r"(r3) : "r"(addr));
}
__device__ __forceinline__ void mma16816(float* c, const uint32_t* a, const uint32_t* b) {
    asm volatile(
        "mma.sync.aligned.m16n8k16.row.col.f32.bf16.bf16.f32 "
        "{%0,%1,%2,%3}, {%4,%5,%6,%7}, {%8,%9}, {%0,%1,%2,%3};"
        : "+f"(c[0]), "+f"(c[1]), "+f"(c[2]), "+f"(c[3])
        : "r"(a[0]), "r"(a[1]), "r"(a[2]), "r"(a[3]), "r"(b[0]), "r"(b[1]));
}

// load one k=16 sub-step's fragments (4 A ldsm.x4 + 2 B ldsm.x4)
__device__ __forceinline__ void ldsm_sub(unsigned aAddr, unsigned bAddr,
                                         uint32_t af[4][4], uint32_t bfr[4][2])
{
#pragma unroll
    for (int mt = 0; mt < 4; ++mt)
        ldsm_x4(af[mt][0], af[mt][1], af[mt][2], af[mt][3],
                aAddr + (unsigned)(mt * 16 * AP * 2));
    {
        uint32_t r0, r1, r2, r3;
        ldsm_x4(r0, r1, r2, r3, bAddr);
        bfr[0][0] = r0; bfr[0][1] = r1; bfr[1][0] = r2; bfr[1][1] = r3;
        ldsm_x4(r0, r1, r2, r3, bAddr + (unsigned)(16 * AP * 2));
        bfr[2][0] = r0; bfr[2][1] = r1; bfr[3][0] = r2; bfr[3][1] = r3;
    }
}
__device__ __forceinline__ void mma_sub(float acc[4][4][4],
                                        uint32_t af[4][4], uint32_t bfr[4][2])
{
#pragma unroll
    for (int mt = 0; mt < 4; ++mt)
#pragma unroll
        for (int nt = 0; nt < 4; ++nt)
            mma16816(acc[mt][nt], af[mt], bfr[nt]);
}

__global__ void __launch_bounds__(256) gemm_bf16x3_kernel(
    const __nv_bfloat16* __restrict__ A,   // [M, K3]
    const __nv_bfloat16* __restrict__ B,   // [N, K3]
    float* __restrict__ C, int M, int N, int K3)
{
    extern __shared__ __nv_bfloat16 smem[];
    __nv_bfloat16* As = smem;                       // [STAGES][TBM*AP]
    __nv_bfloat16* Bs = smem + STAGES * TBM * AP;   // [STAGES][TBM*AP]

    const int tid = threadIdx.x, lane = tid & 31, wid = tid >> 5;
    const int wm = wid & 1;          // 0..1 : 64-row slab
    const int wn = wid >> 1;         // 0..3 : 32-col slab
    const int row0 = blockIdx.y * TBM, col0 = blockIdx.x * TBN;

    // gmem->smem mapping: thread owns 2 consecutive 16B chunks of one 32-col row
    const int c0 = tid * 2;
    const int lr = c0 >> 2;          // tile row (0..127)
    const int lu = c0 & 3;           // first 16B unit (0 or 2)
    const bool aval = (row0 + lr) < M;
    const bool bval = (col0 + lr) < N;
    const __nv_bfloat16* Ag = A + (size_t)(row0 + lr) * K3 + lu * 8;
    const __nv_bfloat16* Bg = B + (size_t)(col0 + lr) * K3 + lu * 8;
    const unsigned soff = (unsigned)((lr * AP + lu * 8) * 2);

    float acc[4][4][4];
#pragma unroll
    for (int i = 0; i < 4; i++)
#pragma unroll
        for (int j = 0; j < 4; j++)
#pragma unroll
            for (int k = 0; k < 4; k++) acc[i][j][k] = 0.f;

    const int NKB = K3 / TBK;

#define ISSUE_STAGE(KB, ST) do {                                              \
        unsigned sa = smem_u32(As + (ST) * TBM * AP) + soff;                  \
        unsigned sb = smem_u32(Bs + (ST) * TBM * AP) + soff;                  \
        const __nv_bfloat16* ga = Ag + (size_t)(KB) * TBK;                    \
        const __nv_bfloat16* gb = Bg + (size_t)(KB) * TBK;                    \
        cp16(sa, ga, aval);  cp16(sa + 16, ga + 8, aval);                     \
        cp16(sb, gb, bval);  cp16(sb + 16, gb + 8, bval);                     \
        asm volatile("cp.async.commit_group;\n" ::: "memory");                \
    } while (0)

    // prologue: 4 groups in flight
    ISSUE_STAGE(0, 0);
    ISSUE_STAGE(1, 1);
    ISSUE_STAGE(2, 2);
    ISSUE_STAGE(3, 3);

    const unsigned aoff = (unsigned)(((wm * 64 + (lane & 15)) * AP + (lane >> 4) * 8) * 2);
    const unsigned boff = (unsigned)(((wn * 32 + (lane >> 4) * 8 + (lane & 7)) * AP
                                      + ((lane >> 3) & 1) * 8) * 2);
    const unsigned KKOFF = (unsigned)(16 * 2);   // 16 bf16 along K

    uint32_t af[2][4][4];
    uint32_t bfr[2][4][2];

    // wait for stage 0, preload sub-step (0,0) into buffer 0
    asm volatile("cp.async.wait_group 3;\n" ::: "memory");
    __syncthreads();
    ldsm_sub(smem_u32(As) + aoff, smem_u32(Bs) + boff, af[0], bfr[0]);

    int st = 0;          // stage of kb
    int issue_st = 4;    // stage slot for kb+4

    for (int kb = 0; kb < NKB; ++kb) {
        // guarantee stage kb+1 resident (2 newest groups may still fly)
        asm volatile("cp.async.wait_group 2;\n" ::: "memory");
        __syncthreads();

        if (kb + 4 < NKB) { ISSUE_STAGE(kb + 4, issue_st); }
        else { asm volatile("cp.async.commit_group;\n" ::: "memory"); }

        const int stn = (st + 1 == STAGES) ? 0 : st + 1;
        const unsigned aCur = smem_u32(As + st * TBM * AP) + aoff;
        const unsigned bCur = smem_u32(Bs + st * TBM * AP) + boff;

        // sub-step 0: prefetch (kb,1) frags, MMA (kb,0)
        ldsm_sub(aCur + KKOFF, bCur + KKOFF, af[1], bfr[1]);
        mma_sub(acc, af[0], bfr[0]);

        // sub-step 1: prefetch (kb+1,0) frags, MMA (kb,1)
        if (kb + 1 < NKB) {
            const unsigned aNxt = smem_u32(As + stn * TBM * AP) + aoff;
            const unsigned bNxt = smem_u32(Bs + stn * TBM * AP) + boff;
            ldsm_sub(aNxt, bNxt, af[0], bfr[0]);
        }
        mma_sub(acc, af[1], bfr[1]);

        st = stn;
        issue_st = (issue_st + 1 == STAGES) ? 0 : issue_st + 1;
    }

    // epilogue
#pragma unroll
    for (int mt = 0; mt < 4; ++mt) {
#pragma unroll
        for (int nt = 0; nt < 4; ++nt) {
            const int r = row0 + wm * 64 + mt * 16 + (lane >> 2);
            const int c = col0 + wn * 32 + nt * 8 + (lane & 3) * 2;
            if (c < N) {
                if (r < M)
                    *(float2*)(C + (size_t)r * N + c) =
                        make_float2(acc[mt][nt][0], acc[mt][nt][1]);
                if (r + 8 < M)
                    *(float2*)(C + (size_t)(r + 8) * N + c) =
                        make_float2(acc[mt][nt][2], acc[mt][nt][3]);
            }
        }
    }
#undef ISSUE_STAGE
}

// ---------------- RoPE ------------------------------------------------------
__global__ void rope_kernel(float* __restrict__ q, const float* __restrict__ kv,
                            float* __restrict__ kpe)
{
    const int s = blockIdx.x;
    const int tid = threadIdx.x;        // 544 = 17 warps
    const int h = tid >> 5;             // 0..16
    const int i = tid & 31;             // freq index 0..31
    if (h > 16) return;

    const float invf = powf(10000.f, -(float)i / 32.f);
    const float ang = (float)s * invf;
    float sn, c;
    sincosf(ang, &sn, &c);

    if (h < 16) {
        float* p = q + (size_t)s * (NHEAD * QKD) + h * QKD + NOPE + 2 * i;
        const float x0 = p[0], x1 = p[1];
        p[0] = x0 * c - x1 * sn;
        p[1] = x0 * sn + x1 * c;
    } else {
        const float* p = kv + (size_t)s * (KVL + ROPE_D) + KVL + 2 * i;
        const float x0 = p[0], x1 = p[1];
        kpe[(size_t)s * ROPE_D + 2 * i]     = x0 * c - x1 * sn;
        kpe[(size_t)s * ROPE_D + 2 * i + 1] = x0 * sn + x1 * c;
    }
}

// ---------------- Flash attention (causal; epilogue fused bf16x3 split) ----
#define LDT 68
#define LDV 132
#define ATTN_SMEM_FLOATS (QKD*LDT*2 + 64*LDV + 64*LDT + 128)
#define AK (NHEAD * VH)    // 2048 = K of the wo GEMM

__global__ void __launch_bounds__(256) attn_kernel(
    const float* __restrict__ q,     // [S, H*QKD] roped
    const float* __restrict__ kvu,   // [S, H*256] (k_nope | v)
    const float* __restrict__ kpe,   // [S, 64]
    __nv_bfloat16* __restrict__ outA3)  // [S, 3*2048] bf16x3 A-layout
{
    const int qt = blockIdx.x;
    const int h  = blockIdx.y;
    extern __shared__ float sm[];
    float* Qt = sm;                          // [192][68] transposed
    float* Kt = Qt + QKD * LDT;              // [192][68] transposed
    float* Vs = Kt + QKD * LDT;              // [64][132] row-major
    float* Pt = Vs + 64 * LDV;               // [64][68]  Pt[t][i]
    float* sAlpha = Pt + 64 * LDT;           // [64]
    float* sL     = sAlpha + 64;             // [64]

    const int tid = threadIdx.x;
    const int tx = tid & 15;     // 0..15
    const int ty = tid >> 4;     // 0..15

    for (int e = tid; e < 64 * (QKD / 4); e += 256) {
        int i = e / (QKD / 4), c4 = (e % (QKD / 4)) * 4;
        float4 v = *(const float4*)(q + (size_t)(qt * 64 + i) * (NHEAD * QKD) + h * QKD + c4);
        Qt[(c4 + 0) * LDT + i] = v.x; Qt[(c4 + 1) * LDT + i] = v.y;
        Qt[(c4 + 2) * LDT + i] = v.z; Qt[(c4 + 3) * LDT + i] = v.w;
    }

    float accO[4][8];
#pragma unroll
    for (int i = 0; i < 4; i++)
#pragma unroll
        for (int j = 0; j < 8; j++) accO[i][j] = 0.f;

    float m_i = -INFINITY, l_i = 0.f;
    const float scale = rsqrtf((float)QKD);

    for (int kt = 0; kt <= qt; ++kt) {
        __syncthreads();
        for (int e = tid; e < 64 * (QKD / 4); e += 256) {
            int t = e / (QKD / 4), c4 = (e % (QKD / 4)) * 4;
            int tg = kt * 64 + t;
            float4 v;
            if (c4 < NOPE)
                v = *(const float4*)(kvu + (size_t)tg * (NHEAD * 256) + h * 256 + c4);
            else
                v = *(const float4*)(kpe + (size_t)tg * ROPE_D + (c4 - NOPE));
            Kt[(c4 + 0) * LDT + t] = v.x; Kt[(c4 + 1) * LDT + t] = v.y;
            Kt[(c4 + 2) * LDT + t] = v.z; Kt[(c4 + 3) * LDT + t] = v.w;
        }
        for (int e = tid; e < 64 * (VH / 4); e += 256) {
            int t = e / (VH / 4), c4 = (e % (VH / 4)) * 4;
            int tg = kt * 64 + t;
            *(float4*)&Vs[t * LDV + c4] =
                *(const float4*)(kvu + (size_t)tg * (NHEAD * 256) + h * 256 + NOPE + c4);
        }
        __syncthreads();

        float s[4][4];
#pragma unroll
        for (int a = 0; a < 4; a++)
#pragma unroll
            for (int b = 0; b < 4; b++) s[a][b] = 0.f;

        for (int d = 0; d < QKD; ++d) {
            float a[4], b[4];
            *(float4*)a = *(const float4*)&Qt[d * LDT + 4 * ty];
            *(float4*)b = *(const float4*)&Kt[d * LDT + 4 * tx];
#pragma unroll
            for (int ii = 0; ii < 4; ii++)
#pragma unroll
                for (int jj = 0; jj < 4; jj++)
                    s[ii][jj] += a[ii] * b[jj];
        }
#pragma unroll
        for (int jj = 0; jj < 4; jj++)
            *(float4*)&Pt[(4 * tx + jj) * LDT + 4 * ty] =
                make_float4(s[0][jj], s[1][jj], s[2][jj], s[3][jj]);
        __syncthreads();

        if (tid < 64) {
            const int i = tid;
            const int tlim = (kt == qt) ? (i + 1) : 64;
            float tmax = -INFINITY;
            for (int t = 0; t < tlim; t++)
                tmax = fmaxf(tmax, Pt[t * LDT + i]);
            tmax *= scale;
            const float mn = fmaxf(m_i, tmax);
            const float alpha = (m_i == -INFINITY) ? 0.f : expf(m_i - mn);
            float lsum = 0.f;
            for (int t = 0; t < 64; t++) {
                float p = (t < tlim) ? expf(Pt[t * LDT + i] * scale - mn) : 0.f;
                Pt[t * LDT + i] = p;
                lsum += p;
            }
            l_i = l_i * alpha + lsum;
            m_i = mn;
            sAlpha[i] = alpha;
        }
        __syncthreads();

        {
            float al[4];
#pragma unroll
            for (int ii = 0; ii < 4; ii++) al[ii] = sAlpha[4 * ty + ii];
#pragma unroll
            for (int ii = 0; ii < 4; ii++)
#pragma unroll
                for (int cc = 0; cc < 8; cc++) accO[ii][cc] *= al[ii];

            for (int t = 0; t < 64; t++) {
                float a[4], b[8];
                *(float4*)a = *(const float4*)&Pt[t * LDT + 4 * ty];
                *(float4*)(b)     = *(const float4*)&Vs[t * LDV + 8 * tx];
                *(float4*)(b + 4) = *(const float4*)&Vs[t * LDV + 8 * tx + 4];
#pragma unroll
                for (int ii = 0; ii < 4; ii++)
#pragma unroll
                    for (int cc = 0; cc < 8; cc++)
                        accO[ii][cc] += a[ii] * b[cc];
            }
        }
    }

    if (tid < 64) sL[tid] = l_i;
    __syncthreads();

    // fused epilogue: write bf16x3 A-operand layout [hi | lo | hi], K = 2048
#pragma unroll
    for (int ii = 0; ii < 4; ii++) {
        const int i = 4 * ty + ii;
        const float inv_l = 1.f / sL[i];
        const int row = qt * 64 + i;
        __nv_bfloat16* d = outA3 + (size_t)row * 3 * AK;
#pragma unroll
        for (int cc = 0; cc < 8; cc++) {
            const float v = accO[ii][cc] * inv_l;
            const int col = h * VH + 8 * tx + cc;
            const __nv_bfloat16 hv = __float2bfloat16(v);
            const __nv_bfloat16 lv = __float2bfloat16(v - __bfloat162float(hv));
            d[col] = hv; d[AK + col] = lv; d[2 * AK + col] = hv;
        }
    }
}

// ---------------- host orchestration ---------------------------------------
static inline void launch_split(const float* src, __nv_bfloat16* dst,
                                int rows, int K, int modeB)
{
    dim3 grid((K + 255) / 256, rows);
    split3_kernel<<<grid, 256>>>(src, dst, K, modeB);
}

static inline void launch_gemm3(const __nv_bfloat16* A3, const __nv_bfloat16* B3,
                                float* C, int M, int N, int K)
{
    cudaFuncSetAttribute(gemm_bf16x3_kernel,
                         cudaFuncAttributeMaxDynamicSharedMemorySize, GEMM_SMEM);
    dim3 grid((N + TBN - 1) / TBN, (M + TBM - 1) / TBM);
    gemm_bf16x3_kernel<<<grid, 256, GEMM_SMEM>>>(A3, B3, C, M, N, 3 * K);
}

extern "C" void kernel_launch(void* const* d_in, const int* in_sizes, int n_in,
                              void* d_out, int out_size)
{
    const float* x        = (const float*)d_in[0];   // [S, DIM]
    const float* wq_down  = (const float*)d_in[1];   // [QL, DIM]
    const float* q_norm_w = (const float*)d_in[2];   // [QL]
    const float* wq_up    = (const float*)d_in[3];   // [H*QKD, QL]
    const float* wkv_down = (const float*)d_in[4];   // [KVL+ROPE, DIM]
    const float* kv_norm_w= (const float*)d_in[5];   // [KVL]
    const float* wkv_up   = (const float*)d_in[6];   // [H*(NOPE+VH), KVL]
    const float* wo       = (const float*)d_in[7];   // [DIM, H*VH]
    float* out = (float*)d_out;

    float *qdown, *kv, *kvnorm, *qbuf, *kvu, *kpe;
    __nv_bfloat16 *A3, *B3;
    cudaGetSymbolAddress((void**)&qdown,  g_qdown);
    cudaGetSymbolAddress((void**)&kv,     g_kv);
    cudaGetSymbolAddress((void**)&kvnorm, g_kvnorm);
    cudaGetSymbolAddress((void**)&qbuf,   g_q);
    cudaGetSymbolAddress((void**)&kvu,    g_kvu);
    cudaGetSymbolAddress((void**)&kpe,    g_kpe);
    cudaGetSymbolAddress((void**)&A3,     g_A3);
    cudaGetSymbolAddress((void**)&B3,     g_B3);

    // B3 second region for wkv_down (fits: 9.44M + 3.54M < 14.16M elems)
    __nv_bfloat16* B3b = B3 + (size_t)QL * 3 * DIM;

    // 1) splits for down-projections
    launch_split(x, A3, S_LEN, DIM, 0);                       // launch 1
    launch_split(wq_down, B3, QL, DIM, 1);                    // launch 2
    launch_split(wkv_down, B3b, KVL + ROPE_D, DIM, 1);        // launch 3

    // 2) down-projections (kv first so a GEMM lands at ncu slot)
    launch_gemm3(A3, B3b, kv, S_LEN, KVL + ROPE_D, DIM);      // launch 4
    rms_kernel<<<S_LEN, 256>>>(kv, kv_norm_w, kvnorm, KVL, KVL + ROPE_D, KVL); // 5
    launch_gemm3(A3, B3, qdown, S_LEN, QL, DIM);              // launch 6

    // 3) q up-projection (rms fused with split)
    rms_split_kernel<<<S_LEN, 256>>>(qdown, q_norm_w, A3, QL);
    launch_split(wq_up, B3, NHEAD * QKD, QL, 1);
    launch_gemm3(A3, B3, qbuf, S_LEN, NHEAD * QKD, QL);

    // 4) kv up-projection
    launch_split(kvnorm, A3, S_LEN, KVL, 0);
    launch_split(wkv_up, B3, NHEAD * (NOPE + VH), KVL, 1);
    launch_gemm3(A3, B3, kvu, S_LEN, NHEAD * (NOPE + VH), KVL);

    // 5) rope (q in place, k_pe to g_kpe)
    rope_kernel<<<S_LEN, 544>>>(qbuf, kv, kpe);

    // 6) causal flash attention (epilogue writes bf16x3 into A3)
    size_t attn_smem = (size_t)ATTN_SMEM_FLOATS * sizeof(float);
    cudaFuncSetAttribute(attn_kernel, cudaFuncAttributeMaxDynamicSharedMemorySize,
                         (int)attn_smem);
    dim3 agrid(S_LEN / 64, NHEAD);
    attn_kernel<<<agrid, 256, attn_smem>>>(qbuf, kvu, kpe, A3);

    // 7) output projection
    launch_split(wo, B3, DIM, NHEAD * VH, 1);
    launch_gemm3(A3, B3, out, S_LEN, DIM, NHEAD * VH);
}

// round 7
// speedup vs baseline: 1.0698x; 1.0698x over previous
#include <cuda_runtime.h>
#include <cuda_bf16.h>
#include <math.h>
#include <stdint.h>

// Problem constants
#define S_LEN 2048
#define DIM   2048
#define NHEAD 16
#define QL    1536
#define KVL   512
#define NOPE  128
#define ROPE_D 64
#define VH    128
#define QKD   192   // NOPE + ROPE
#define EPS   1e-6f
#define NDOWN (QL + KVL + ROPE_D)   // 2112 : merged down-proj output cols

// ---------------- scratch (device globals; no allocation allowed) ----------
__device__ float g_down [S_LEN * NDOWN];           // [2048, 2112] = qdown | kv
__device__ float g_kvnorm[S_LEN * KVL];
__device__ float g_q    [S_LEN * NHEAD * QKD];     // roped in place
__device__ float g_kvu  [S_LEN * NHEAD * (NOPE + VH)];
__device__ float g_kpe  [S_LEN * ROPE_D];

// bf16x3 operand scratch
__device__ __nv_bfloat16 g_A3[(size_t)S_LEN * 3 * DIM];          // 12.58M elems
__device__ __nv_bfloat16 g_B3[(size_t)3072 * 3 * 1536];          // 14.16M elems

// ---------------- fp32 -> (hi,lo) bf16 split kernels -----------------------
// A mode: dst row layout [hi(K) | lo(K) | hi(K)]
// B mode: dst row layout [hi(K) | hi(K) | lo(K)]
__global__ void split3_kernel(const float* __restrict__ src,
                              __nv_bfloat16* __restrict__ dst,
                              int K, int modeB)
{
    const int r = blockIdx.y;
    const int k = blockIdx.x * 256 + threadIdx.x;
    if (k >= K) return;
    const float v = src[(size_t)r * K + k];
    const __nv_bfloat16 h = __float2bfloat16(v);
    const __nv_bfloat16 l = __float2bfloat16(v - __bfloat162float(h));
    __nv_bfloat16* d = dst + (size_t)r * 3 * K;
    d[k] = h;
    d[K + k]     = modeB ? h : l;
    d[2 * K + k] = modeB ? l : h;
}

// ---------------- RMSNorm (fp32 out, strided input) ------------------------
__global__ void rms_kernel(const float* __restrict__ in, const float* __restrict__ w,
                           float* __restrict__ out, int n, int istride, int ostride)
{
    const int row = blockIdx.x;
    const float* x = in + (size_t)row * istride;

    float ss = 0.f;
    for (int i = threadIdx.x; i < n; i += blockDim.x) {
        float v = x[i];
        ss += v * v;
    }
#pragma unroll
    for (int o = 16; o; o >>= 1) ss += __shfl_xor_sync(0xffffffffu, ss, o);

    __shared__ float warpsum[8];
    __shared__ float sScale;
    const int wid = threadIdx.x >> 5;
    if ((threadIdx.x & 31) == 0) warpsum[wid] = ss;
    __syncthreads();
    if (threadIdx.x == 0) {
        float tot = 0.f;
        for (int i = 0; i < (int)(blockDim.x >> 5); i++) tot += warpsum[i];
        sScale = rsqrtf(tot / (float)n + EPS);
    }
    __syncthreads();
    const float sc = sScale;
    for (int i = threadIdx.x; i < n; i += blockDim.x)
        out[(size_t)row * ostride + i] = x[i] * sc * w[i];
}

// ---------------- RMSNorm fused with bf16x3 A-split (strided input) --------
__global__ void rms_split_kernel(const float* __restrict__ in, const float* __restrict__ w,
                                 __nv_bfloat16* __restrict__ dst, int n, int istride)
{
    const int row = blockIdx.x;
    const float* x = in + (size_t)row * istride;

    float ss = 0.f;
    for (int i = threadIdx.x; i < n; i += blockDim.x) {
        float v = x[i];
        ss += v * v;
    }
#pragma unroll
    for (int o = 16; o; o >>= 1) ss += __shfl_xor_sync(0xffffffffu, ss, o);

    __shared__ float warpsum[8];
    __shared__ float sScale;
    const int wid = threadIdx.x >> 5;
    if ((threadIdx.x & 31) == 0) warpsum[wid] = ss;
    __syncthreads();
    if (threadIdx.x == 0) {
        float tot = 0.f;
        for (int i = 0; i < (int)(blockDim.x >> 5); i++) tot += warpsum[i];
        sScale = rsqrtf(tot / (float)n + EPS);
    }
    __syncthreads();
    const float sc = sScale;
    __nv_bfloat16* d = dst + (size_t)row * 3 * n;
    for (int i = threadIdx.x; i < n; i += blockDim.x) {
        const float v = x[i] * sc * w[i];
        const __nv_bfloat16 h = __float2bfloat16(v);
        const __nv_bfloat16 l = __float2bfloat16(v - __bfloat162float(h));
        d[i] = h; d[n + i] = l; d[2 * n + i] = h;
    }
}

// ---------------- bf16x3 tensor-core GEMM (v5: 2 CTAs/SM) ------------------
// C[M,N] = A3[M,K3] * B3[N,K3]^T  (bf16 operands, fp32 accumulate)
#define TBM 128
#define TBN 128
#define TBK 32
#define AP  40      // smem pitch in bf16 (80B = 5 x 16B units -> conflict-free)
#define STAGES 4
#define GEMM_SMEM (STAGES * 2 * TBM * AP * 2)   // bytes = 81920 -> 2 CTAs/SM

__device__ __forceinline__ unsigned smem_u32(const void* p) {
    return (unsigned)__cvta_generic_to_shared(p);
}
__device__ __forceinline__ void cp16(unsigned s, const void* g, bool pred) {
    int sz = pred ? 16 : 0;
    asm volatile("cp.async.cg.shared.global [%0], [%1], 16, %2;\n"
                 :: "r"(s), "l"(g), "r"(sz));
}
__device__ __forceinline__ void ldsm_x4(uint32_t& r0, uint32_t& r1,
                                        uint32_t& r2, uint32_t& r3, unsigned addr) {
    asm volatile("ldmatrix.sync.aligned.m8n8.x4.shared.b16 {%0,%1,%2,%3}, [%4];"
                 : "=r"(r0), "=r"(r1), "=r"(r2), "=r"(r3) : "r"(addr));
}
__device__ __forceinline__ void mma16816(float* c, const uint32_t* a, const uint32_t* b) {
    asm volatile(
        "mma.sync.aligned.m16n8k16.row.col.f32.bf16.bf16.f32 "
        "{%0,%1,%2,%3}, {%4,%5,%6,%7}, {%8,%9}, {%0,%1,%2,%3};"
        : "+f"(c[0]), "+f"(c[1]), "+f"(c[2]), "+f"(c[3])
        : "r"(a[0]), "r"(a[1]), "r"(a[2]), "r"(a[3]), "r"(b[0]), "r"(b[1]));
}

__global__ void __launch_bounds__(256, 2) gemm_bf16x3_kernel(
    const __nv_bfloat16* __restrict__ A,   // [M, K3]
    const __nv_bfloat16* __restrict__ B,   // [N, K3]
    float* __restrict__ C, int M, int N, int K3)
{
    extern __shared__ __nv_bfloat16 smem[];
    __nv_bfloat16* As = smem;                       // [STAGES][TBM*AP]
    __nv_bfloat16* Bs = smem + STAGES * TBM * AP;   // [STAGES][TBM*AP]

    const int tid = threadIdx.x, lane = tid & 31, wid = tid >> 5;
    const int wm = wid & 1;          // 0..1 : 64-row slab
    const int wn = wid >> 1;         // 0..3 : 32-col slab
    const int row0 = blockIdx.y * TBM, col0 = blockIdx.x * TBN;

    // gmem->smem mapping: thread owns 2 consecutive 16B chunks of one 32-col row
    const int c0 = tid * 2;
    const int lr = c0 >> 2;          // tile row (0..127)
    const int lu = c0 & 3;           // first 16B unit (0 or 2)
    const bool aval = (row0 + lr) < M;
    const bool bval = (col0 + lr) < N;
    const __nv_bfloat16* Ag = A + (size_t)(row0 + lr) * K3 + lu * 8;
    const __nv_bfloat16* Bg = B + (size_t)(col0 + lr) * K3 + lu * 8;
    const unsigned soff = (unsigned)((lr * AP + lu * 8) * 2);

    float acc[4][4][4];
#pragma unroll
    for (int i = 0; i < 4; i++)
#pragma unroll
        for (int j = 0; j < 4; j++)
#pragma unroll
            for (int k = 0; k < 4; k++) acc[i][j][k] = 0.f;

    const int NKB = K3 / TBK;

#define ISSUE_STAGE(KB, ST) do {                                              \
        unsigned sa = smem_u32(As + (ST) * TBM * AP) + soff;                  \
        unsigned sb = smem_u32(Bs + (ST) * TBM * AP) + soff;                  \
        const __nv_bfloat16* ga = Ag + (size_t)(KB) * TBK;                    \
        const __nv_bfloat16* gb = Bg + (size_t)(KB) * TBK;                    \
        cp16(sa, ga, aval);  cp16(sa + 16, ga + 8, aval);                     \
        cp16(sb, gb, bval);  cp16(sb + 16, gb + 8, bval);                     \
        asm volatile("cp.async.commit_group;\n" ::: "memory");                \
    } while (0)

    // prologue: 3 groups in flight
    ISSUE_STAGE(0, 0);
    ISSUE_STAGE(1, 1);
    ISSUE_STAGE(2, 2);

    const unsigned aoff = (unsigned)(((wm * 64 + (lane & 15)) * AP + (lane >> 4) * 8) * 2);
    const unsigned boff = (unsigned)(((wn * 32 + (lane >> 4) * 8 + (lane & 7)) * AP
                                      + ((lane >> 3) & 1) * 8) * 2);

    for (int kb = 0; kb < NKB; ++kb) {
        asm volatile("cp.async.wait_group 2;\n" ::: "memory");
        __syncthreads();

        if (kb + 3 < NKB) { ISSUE_STAGE(kb + 3, (kb + 3) & 3); }
        else { asm volatile("cp.async.commit_group;\n" ::: "memory"); }

        const int st = kb & 3;
        const unsigned aAddr = smem_u32(As + st * TBM * AP) + aoff;
        const unsigned bAddr = smem_u32(Bs + st * TBM * AP) + boff;

        // batch-load ALL fragments of this K-chunk (both kk halves)
        uint32_t af[2][4][4];
        uint32_t bfr[2][4][2];
#pragma unroll
        for (int kk = 0; kk < 2; ++kk) {
#pragma unroll
            for (int mt = 0; mt < 4; ++mt)
                ldsm_x4(af[kk][mt][0], af[kk][mt][1], af[kk][mt][2], af[kk][mt][3],
                        aAddr + (unsigned)((mt * 16 * AP + kk * 16) * 2));
#pragma unroll
            for (int bp = 0; bp < 2; ++bp) {
                uint32_t r0, r1, r2, r3;
                ldsm_x4(r0, r1, r2, r3,
                        bAddr + (unsigned)((bp * 16 * AP + kk * 16) * 2));
                bfr[kk][2 * bp][0] = r0;      bfr[kk][2 * bp][1] = r1;
                bfr[kk][2 * bp + 1][0] = r2;  bfr[kk][2 * bp + 1][1] = r3;
            }
        }
#pragma unroll
        for (int kk = 0; kk < 2; ++kk)
#pragma unroll
            for (int mt = 0; mt < 4; ++mt)
#pragma unroll
                for (int nt = 0; nt < 4; ++nt)
                    mma16816(acc[mt][nt], af[kk][mt], bfr[kk][nt]);
    }

    // epilogue
#pragma unroll
    for (int mt = 0; mt < 4; ++mt) {
#pragma unroll
        for (int nt = 0; nt < 4; ++nt) {
            const int r = row0 + wm * 64 + mt * 16 + (lane >> 2);
            const int c = col0 + wn * 32 + nt * 8 + (lane & 3) * 2;
            if (c < N) {
                if (r < M)
                    *(float2*)(C + (size_t)r * N + c) =
                        make_float2(acc[mt][nt][0], acc[mt][nt][1]);
                if (r + 8 < M)
                    *(float2*)(C + (size_t)(r + 8) * N + c) =
                        make_float2(acc[mt][nt][2], acc[mt][nt][3]);
            }
        }
    }
#undef ISSUE_STAGE
}

// ---------------- RoPE ------------------------------------------------------
// q roped in place; k_pe read from merged down buffer (stride NDOWN, offset QL+KVL)
__global__ void rope_kernel(float* __restrict__ q, const float* __restrict__ down,
                            float* __restrict__ kpe)
{
    const int s = blockIdx.x;
    const int tid = threadIdx.x;        // 544 = 17 warps
    const int h = tid >> 5;             // 0..16
    const int i = tid & 31;             // freq index 0..31
    if (h > 16) return;

    const float invf = powf(10000.f, -(float)i / 32.f);
    const float ang = (float)s * invf;
    float sn, c;
    sincosf(ang, &sn, &c);

    if (h < 16) {
        float* p = q + (size_t)s * (NHEAD * QKD) + h * QKD + NOPE + 2 * i;
        const float x0 = p[0], x1 = p[1];
        p[0] = x0 * c - x1 * sn;
        p[1] = x0 * sn + x1 * c;
    } else {
        const float* p = down + (size_t)s * NDOWN + QL + KVL + 2 * i;
        const float x0 = p[0], x1 = p[1];
        kpe[(size_t)s * ROPE_D + 2 * i]     = x0 * c - x1 * sn;
        kpe[(size_t)s * ROPE_D + 2 * i + 1] = x0 * sn + x1 * c;
    }
}

// ---------------- Flash attention (causal; epilogue fused bf16x3 split) ----
#define LDT 68
#define LDV 132
#define ATTN_SMEM_FLOATS (QKD*LDT*2 + 64*LDV + 64*LDT + 128)
#define AK (NHEAD * VH)    // 2048 = K of the wo GEMM

__global__ void __launch_bounds__(256) attn_kernel(
    const float* __restrict__ q,     // [S, H*QKD] roped
    const float* __restrict__ kvu,   // [S, H*256] (k_nope | v)
    const float* __restrict__ kpe,   // [S, 64]
    __nv_bfloat16* __restrict__ outA3)  // [S, 3*2048] bf16x3 A-layout
{
    const int qt = blockIdx.x;
    const int h  = blockIdx.y;
    extern __shared__ float sm[];
    float* Qt = sm;                          // [192][68] transposed
    float* Kt = Qt + QKD * LDT;              // [192][68] transposed
    float* Vs = Kt + QKD * LDT;              // [64][132] row-major
    float* Pt = Vs + 64 * LDV;               // [64][68]  Pt[t][i]
    float* sAlpha = Pt + 64 * LDT;           // [64]
    float* sL     = sAlpha + 64;             // [64]

    const int tid = threadIdx.x;
    const int tx = tid & 15;     // 0..15
    const int ty = tid >> 4;     // 0..15

    for (int e = tid; e < 64 * (QKD / 4); e += 256) {
        int i = e / (QKD / 4), c4 = (e % (QKD / 4)) * 4;
        float4 v = *(const float4*)(q + (size_t)(qt * 64 + i) * (NHEAD * QKD) + h * QKD + c4);
        Qt[(c4 + 0) * LDT + i] = v.x; Qt[(c4 + 1) * LDT + i] = v.y;
        Qt[(c4 + 2) * LDT + i] = v.z; Qt[(c4 + 3) * LDT + i] = v.w;
    }

    float accO[4][8];
#pragma unroll
    for (int i = 0; i < 4; i++)
#pragma unroll
        for (int j = 0; j < 8; j++) accO[i][j] = 0.f;

    float m_i = -INFINITY, l_i = 0.f;
    const float scale = rsqrtf((float)QKD);

    for (int kt = 0; kt <= qt; ++kt) {
        __syncthreads();
        for (int e = tid; e < 64 * (QKD / 4); e += 256) {
            int t = e / (QKD / 4), c4 = (e % (QKD / 4)) * 4;
            int tg = kt * 64 + t;
            float4 v;
            if (c4 < NOPE)
                v = *(const float4*)(kvu + (size_t)tg * (NHEAD * 256) + h * 256 + c4);
            else
                v = *(const float4*)(kpe + (size_t)tg * ROPE_D + (c4 - NOPE));
            Kt[(c4 + 0) * LDT + t] = v.x; Kt[(c4 + 1) * LDT + t] = v.y;
            Kt[(c4 + 2) * LDT + t] = v.z; Kt[(c4 + 3) * LDT + t] = v.w;
        }
        for (int e = tid; e < 64 * (VH / 4); e += 256) {
            int t = e / (VH / 4), c4 = (e % (VH / 4)) * 4;
            int tg = kt * 64 + t;
            *(float4*)&Vs[t * LDV + c4] =
                *(const float4*)(kvu + (size_t)tg * (NHEAD * 256) + h * 256 + NOPE + c4);
        }
        __syncthreads();

        float s[4][4];
#pragma unroll
        for (int a = 0; a < 4; a++)
#pragma unroll
            for (int b = 0; b < 4; b++) s[a][b] = 0.f;

        for (int d = 0; d < QKD; ++d) {
            float a[4], b[4];
            *(float4*)a = *(const float4*)&Qt[d * LDT + 4 * ty];
            *(float4*)b = *(const float4*)&Kt[d * LDT + 4 * tx];
#pragma unroll
            for (int ii = 0; ii < 4; ii++)
#pragma unroll
                for (int jj = 0; jj < 4; jj++)
                    s[ii][jj] += a[ii] * b[jj];
        }
#pragma unroll
        for (int jj = 0; jj < 4; jj++)
            *(float4*)&Pt[(4 * tx + jj) * LDT + 4 * ty] =
                make_float4(s[0][jj], s[1][jj], s[2][jj], s[3][jj]);
        __syncthreads();

        if (tid < 64) {
            const int i = tid;
            const int tlim = (kt == qt) ? (i + 1) : 64;
            float tmax = -INFINITY;
            for (int t = 0; t < tlim; t++)
                tmax = fmaxf(tmax, Pt[t * LDT + i]);
            tmax *= scale;
            const float mn = fmaxf(m_i, tmax);
            const float alpha = (m_i == -INFINITY) ? 0.f : expf(m_i - mn);
            float lsum = 0.f;
            for (int t = 0; t < 64; t++) {
                float p = (t < tlim) ? expf(Pt[t * LDT + i] * scale - mn) : 0.f;
                Pt[t * LDT + i] = p;
                lsum += p;
            }
            l_i = l_i * alpha + lsum;
            m_i = mn;
            sAlpha[i] = alpha;
        }
        __syncthreads();

        {
            float al[4];
#pragma unroll
            for (int ii = 0; ii < 4; ii++) al[ii] = sAlpha[4 * ty + ii];
#pragma unroll
            for (int ii = 0; ii < 4; ii++)
#pragma unroll
                for (int cc = 0; cc < 8; cc++) accO[ii][cc] *= al[ii];

            for (int t = 0; t < 64; t++) {
                float a[4], b[8];
                *(float4*)a = *(const float4*)&Pt[t * LDT + 4 * ty];
                *(float4*)(b)     = *(const float4*)&Vs[t * LDV + 8 * tx];
                *(float4*)(b + 4) = *(const float4*)&Vs[t * LDV + 8 * tx + 4];
#pragma unroll
                for (int ii = 0; ii < 4; ii++)
#pragma unroll
                    for (int cc = 0; cc < 8; cc++)
                        accO[ii][cc] += a[ii] * b[cc];
            }
        }
    }

    if (tid < 64) sL[tid] = l_i;
    __syncthreads();

    // fused epilogue: write bf16x3 A-operand layout [hi | lo | hi], K = 2048
#pragma unroll
    for (int ii = 0; ii < 4; ii++) {
        const int i = 4 * ty + ii;
        const float inv_l = 1.f / sL[i];
        const int row = qt * 64 + i;
        __nv_bfloat16* d = outA3 + (size_t)row * 3 * AK;
#pragma unroll
        for (int cc = 0; cc < 8; cc++) {
            const float v = accO[ii][cc] * inv_l;
            const int col = h * VH + 8 * tx + cc;
            const __nv_bfloat16 hv = __float2bfloat16(v);
            const __nv_bfloat16 lv = __float2bfloat16(v - __bfloat162float(hv));
            d[col] = hv; d[AK + col] = lv; d[2 * AK + col] = hv;
        }
    }
}

// ---------------- host orchestration ---------------------------------------
static inline void launch_split(const float* src, __nv_bfloat16* dst,
                                int rows, int K, int modeB)
{
    dim3 grid((K + 255) / 256, rows);
    split3_kernel<<<grid, 256>>>(src, dst, K, modeB);
}

static inline void launch_gemm3(const __nv_bfloat16* A3, const __nv_bfloat16* B3,
                                float* C, int M, int N, int K)
{
    cudaFuncSetAttribute(gemm_bf16x3_kernel,
                         cudaFuncAttributeMaxDynamicSharedMemorySize, GEMM_SMEM);
    dim3 grid((N + TBN - 1) / TBN, (M + TBM - 1) / TBM);
    gemm_bf16x3_kernel<<<grid, 256, GEMM_SMEM>>>(A3, B3, C, M, N, 3 * K);
}

extern "C" void kernel_launch(void* const* d_in, const int* in_sizes, int n_in,
                              void* d_out, int out_size)
{
    const float* x        = (const float*)d_in[0];   // [S, DIM]
    const float* wq_down  = (const float*)d_in[1];   // [QL, DIM]
    const float* q_norm_w = (const float*)d_in[2];   // [QL]
    const float* wq_up    = (const float*)d_in[3];   // [H*QKD, QL]
    const float* wkv_down = (const float*)d_in[4];   // [KVL+ROPE, DIM]
    const float* kv_norm_w= (const float*)d_in[5];   // [KVL]
    const float* wkv_up   = (const float*)d_in[6];   // [H*(NOPE+VH), KVL]
    const float* wo       = (const float*)d_in[7];   // [DIM, H*VH]
    float* out = (float*)d_out;

    float *down, *kvnorm, *qbuf, *kvu, *kpe;
    __nv_bfloat16 *A3, *B3;
    cudaGetSymbolAddress((void**)&down,   g_down);
    cudaGetSymbolAddress((void**)&kvnorm, g_kvnorm);
    cudaGetSymbolAddress((void**)&qbuf,   g_q);
    cudaGetSymbolAddress((void**)&kvu,    g_kvu);
    cudaGetSymbolAddress((void**)&kpe,    g_kpe);
    cudaGetSymbolAddress((void**)&A3,     g_A3);
    cudaGetSymbolAddress((void**)&B3,     g_B3);

    // merged down-proj B: rows [0,QL) = wq_down, rows [QL, NDOWN) = wkv_down
    __nv_bfloat16* B3kv = B3 + (size_t)QL * 3 * DIM;

    // 1) splits for merged down-projection
    launch_split(x, A3, S_LEN, DIM, 0);
    launch_split(wq_down, B3, QL, DIM, 1);
    launch_split(wkv_down, B3kv, KVL + ROPE_D, DIM, 1);

    // 2) ONE merged down-projection GEMM: [2048, 2112], grid 272 CTAs
    launch_gemm3(A3, B3, down, S_LEN, NDOWN, DIM);

    // 3) norms (strided reads from merged buffer)
    rms_kernel<<<S_LEN, 256>>>(down + QL, kv_norm_w, kvnorm, KVL, NDOWN, KVL);
    rms_split_kernel<<<S_LEN, 256>>>(down, q_norm_w, A3, QL, NDOWN);

    // 4) q up-projection
    launch_split(wq_up, B3, NHEAD * QKD, QL, 1);
    launch_gemm3(A3, B3, qbuf, S_LEN, NHEAD * QKD, QL);

    // 5) kv up-projection
    launch_split(kvnorm, A3, S_LEN, KVL, 0);
    launch_split(wkv_up, B3, NHEAD * (NOPE + VH), KVL, 1);
    launch_gemm3(A3, B3, kvu, S_LEN, NHEAD * (NOPE + VH), KVL);

    // 6) rope (q in place, k_pe from merged down buffer)
    rope_kernel<<<S_LEN, 544>>>(qbuf, down, kpe);

    // 7) causal flash attention (epilogue writes bf16x3 into A3)
    size_t attn_smem = (size_t)ATTN_SMEM_FLOATS * sizeof(float);
    cudaFuncSetAttribute(attn_kernel, cudaFuncAttributeMaxDynamicSharedMemorySize,
                         (int)attn_smem);
    dim3 agrid(S_LEN / 64, NHEAD);
    attn_kernel<<<agrid, 256, attn_smem>>>(qbuf, kvu, kpe, A3);

    // 8) output projection
    launch_split(wo, B3, DIM, NHEAD * VH, 1);
    launch_gemm3(A3, B3, out, S_LEN, DIM, NHEAD * VH);
}

// round 8
// speedup vs baseline: 1.2418x; 1.1607x over previous
#include <cuda_runtime.h>
#include <cuda_bf16.h>
#include <math.h>
#include <stdint.h>

// Problem constants
#define S_LEN 2048
#define DIM   2048
#define NHEAD 16
#define QL    1536
#define KVL   512
#define NOPE  128
#define ROPE_D 64
#define VH    128
#define QKD   192   // NOPE + ROPE
#define EPS   1e-6f
#define NDOWN (QL + KVL + ROPE_D)   // 2112 : merged down-proj output cols
#define AK (NHEAD * VH)             // 2048

// ---------------- scratch (device globals; no allocation allowed) ----------
__device__ float g_down [S_LEN * NDOWN];           // [2048, 2112] = qdown | kv
__device__ float g_kvnorm[S_LEN * KVL];
__device__ float g_q    [S_LEN * NHEAD * QKD];     // roped in place
__device__ float g_kvu  [S_LEN * NHEAD * (NOPE + VH)];
__device__ float g_kpe  [S_LEN * ROPE_D];

// bf16x3 operand scratch
__device__ __nv_bfloat16 g_A3[(size_t)S_LEN * 3 * DIM];
__device__ __nv_bfloat16 g_B3[(size_t)3072 * 3 * 1536];

// ---------------- fp32 -> (hi,lo) bf16 split kernels -----------------------
__global__ void split3_kernel(const float* __restrict__ src,
                              __nv_bfloat16* __restrict__ dst,
                              int K, int modeB)
{
    const int r = blockIdx.y;
    const int k = blockIdx.x * 256 + threadIdx.x;
    if (k >= K) return;
    const float v = src[(size_t)r * K + k];
    const __nv_bfloat16 h = __float2bfloat16(v);
    const __nv_bfloat16 l = __float2bfloat16(v - __bfloat162float(h));
    __nv_bfloat16* d = dst + (size_t)r * 3 * K;
    d[k] = h;
    d[K + k]     = modeB ? h : l;
    d[2 * K + k] = modeB ? l : h;
}

// ---------------- RMSNorm (fp32 out, strided input) ------------------------
__global__ void rms_kernel(const float* __restrict__ in, const float* __restrict__ w,
                           float* __restrict__ out, int n, int istride, int ostride)
{
    const int row = blockIdx.x;
    const float* x = in + (size_t)row * istride;

    float ss = 0.f;
    for (int i = threadIdx.x; i < n; i += blockDim.x) {
        float v = x[i];
        ss += v * v;
    }
#pragma unroll
    for (int o = 16; o; o >>= 1) ss += __shfl_xor_sync(0xffffffffu, ss, o);

    __shared__ float warpsum[8];
    __shared__ float sScale;
    const int wid = threadIdx.x >> 5;
    if ((threadIdx.x & 31) == 0) warpsum[wid] = ss;
    __syncthreads();
    if (threadIdx.x == 0) {
        float tot = 0.f;
        for (int i = 0; i < (int)(blockDim.x >> 5); i++) tot += warpsum[i];
        sScale = rsqrtf(tot / (float)n + EPS);
    }
    __syncthreads();
    const float sc = sScale;
    for (int i = threadIdx.x; i < n; i += blockDim.x)
        out[(size_t)row * ostride + i] = x[i] * sc * w[i];
}

// ---------------- RMSNorm fused with bf16x3 A-split ------------------------
__global__ void rms_split_kernel(const float* __restrict__ in, const float* __restrict__ w,
                                 __nv_bfloat16* __restrict__ dst, int n, int istride)
{
    const int row = blockIdx.x;
    const float* x = in + (size_t)row * istride;

    float ss = 0.f;
    for (int i = threadIdx.x; i < n; i += blockDim.x) {
        float v = x[i];
        ss += v * v;
    }
#pragma unroll
    for (int o = 16; o; o >>= 1) ss += __shfl_xor_sync(0xffffffffu, ss, o);

    __shared__ float warpsum[8];
    __shared__ float sScale;
    const int wid = threadIdx.x >> 5;
    if ((threadIdx.x & 31) == 0) warpsum[wid] = ss;
    __syncthreads();
    if (threadIdx.x == 0) {
        float tot = 0.f;
        for (int i = 0; i < (int)(blockDim.x >> 5); i++) tot += warpsum[i];
        sScale = rsqrtf(tot / (float)n + EPS);
    }
    __syncthreads();
    const float sc = sScale;
    __nv_bfloat16* d = dst + (size_t)row * 3 * n;
    for (int i = threadIdx.x; i < n; i += blockDim.x) {
        const float v = x[i] * sc * w[i];
        const __nv_bfloat16 h = __float2bfloat16(v);
        const __nv_bfloat16 l = __float2bfloat16(v - __bfloat162float(h));
        d[i] = h; d[n + i] = l; d[2 * n + i] = h;
    }
}

// ---------------- shared mma helpers ----------------------------------------
__device__ __forceinline__ unsigned smem_u32(const void* p) {
    return (unsigned)__cvta_generic_to_shared(p);
}
__device__ __forceinline__ void cp16(unsigned s, const void* g, bool pred) {
    int sz = pred ? 16 : 0;
    asm volatile("cp.async.cg.shared.global [%0], [%1], 16, %2;\n"
                 :: "r"(s), "l"(g), "r"(sz));
}
__device__ __forceinline__ void ldsm_x4(uint32_t& r0, uint32_t& r1,
                                        uint32_t& r2, uint32_t& r3, unsigned addr) {
    asm volatile("ldmatrix.sync.aligned.m8n8.x4.shared.b16 {%0,%1,%2,%3}, [%4];"
                 : "=r"(r0), "=r"(r1), "=r"(r2), "=r"(r3) : "r"(addr));
}
__device__ __forceinline__ void mma16816(float* c, const uint32_t* a, const uint32_t* b) {
    asm volatile(
        "mma.sync.aligned.m16n8k16.row.col.f32.bf16.bf16.f32 "
        "{%0,%1,%2,%3}, {%4,%5,%6,%7}, {%8,%9}, {%0,%1,%2,%3};"
        : "+f"(c[0]), "+f"(c[1]), "+f"(c[2]), "+f"(c[3])
        : "r"(a[0]), "r"(a[1]), "r"(a[2]), "r"(a[3]), "r"(b[0]), "r"(b[1]));
}

// ---------------- bf16x3 tensor-core GEMM (v5: 2 CTAs/SM) ------------------
#define TBM 128
#define TBN 128
#define TBK 32
#define AP  40
#define STAGES 4
#define GEMM_SMEM (STAGES * 2 * TBM * AP * 2)   // 81920 B -> 2 CTAs/SM

__global__ void __launch_bounds__(256, 2) gemm_bf16x3_kernel(
    const __nv_bfloat16* __restrict__ A,   // [M, K3]
    const __nv_bfloat16* __restrict__ B,   // [N, K3]
    float* __restrict__ C, int M, int N, int K3)
{
    extern __shared__ __nv_bfloat16 smem[];
    __nv_bfloat16* As = smem;
    __nv_bfloat16* Bs = smem + STAGES * TBM * AP;

    const int tid = threadIdx.x, lane = tid & 31, wid = tid >> 5;
    const int wm = wid & 1;
    const int wn = wid >> 1;
    const int row0 = blockIdx.y * TBM, col0 = blockIdx.x * TBN;

    const int c0 = tid * 2;
    const int lr = c0 >> 2;
    const int lu = c0 & 3;
    const bool aval = (row0 + lr) < M;
    const bool bval = (col0 + lr) < N;
    const __nv_bfloat16* Ag = A + (size_t)(row0 + lr) * K3 + lu * 8;
    const __nv_bfloat16* Bg = B + (size_t)(col0 + lr) * K3 + lu * 8;
    const unsigned soff = (unsigned)((lr * AP + lu * 8) * 2);

    float acc[4][4][4];
#pragma unroll
    for (int i = 0; i < 4; i++)
#pragma unroll
        for (int j = 0; j < 4; j++)
#pragma unroll
            for (int k = 0; k < 4; k++) acc[i][j][k] = 0.f;

    const int NKB = K3 / TBK;

#define ISSUE_STAGE(KB, ST) do {                                              \
        unsigned sa = smem_u32(As + (ST) * TBM * AP) + soff;                  \
        unsigned sb = smem_u32(Bs + (ST) * TBM * AP) + soff;                  \
        const __nv_bfloat16* ga = Ag + (size_t)(KB) * TBK;                    \
        const __nv_bfloat16* gb = Bg + (size_t)(KB) * TBK;                    \
        cp16(sa, ga, aval);  cp16(sa + 16, ga + 8, aval);                     \
        cp16(sb, gb, bval);  cp16(sb + 16, gb + 8, bval);                     \
        asm volatile("cp.async.commit_group;\n" ::: "memory");                \
    } while (0)

    ISSUE_STAGE(0, 0);
    ISSUE_STAGE(1, 1);
    ISSUE_STAGE(2, 2);

    const unsigned aoff = (unsigned)(((wm * 64 + (lane & 15)) * AP + (lane >> 4) * 8) * 2);
    const unsigned boff = (unsigned)(((wn * 32 + (lane >> 4) * 8 + (lane & 7)) * AP
                                      + ((lane >> 3) & 1) * 8) * 2);

    for (int kb = 0; kb < NKB; ++kb) {
        asm volatile("cp.async.wait_group 2;\n" ::: "memory");
        __syncthreads();

        if (kb + 3 < NKB) { ISSUE_STAGE(kb + 3, (kb + 3) & 3); }
        else { asm volatile("cp.async.commit_group;\n" ::: "memory"); }

        const int st = kb & 3;
        const unsigned aAddr = smem_u32(As + st * TBM * AP) + aoff;
        const unsigned bAddr = smem_u32(Bs + st * TBM * AP) + boff;

        uint32_t af[2][4][4];
        uint32_t bfr[2][4][2];
#pragma unroll
        for (int kk = 0; kk < 2; ++kk) {
#pragma unroll
            for (int mt = 0; mt < 4; ++mt)
                ldsm_x4(af[kk][mt][0], af[kk][mt][1], af[kk][mt][2], af[kk][mt][3],
                        aAddr + (unsigned)((mt * 16 * AP + kk * 16) * 2));
#pragma unroll
            for (int bp = 0; bp < 2; ++bp) {
                uint32_t r0, r1, r2, r3;
                ldsm_x4(r0, r1, r2, r3,
                        bAddr + (unsigned)((bp * 16 * AP + kk * 16) * 2));
                bfr[kk][2 * bp][0] = r0;      bfr[kk][2 * bp][1] = r1;
                bfr[kk][2 * bp + 1][0] = r2;  bfr[kk][2 * bp + 1][1] = r3;
            }
        }
#pragma unroll
        for (int kk = 0; kk < 2; ++kk)
#pragma unroll
            for (int mt = 0; mt < 4; ++mt)
#pragma unroll
                for (int nt = 0; nt < 4; ++nt)
                    mma16816(acc[mt][nt], af[kk][mt], bfr[kk][nt]);
    }

#pragma unroll
    for (int mt = 0; mt < 4; ++mt) {
#pragma unroll
        for (int nt = 0; nt < 4; ++nt) {
            const int r = row0 + wm * 64 + mt * 16 + (lane >> 2);
            const int c = col0 + wn * 32 + nt * 8 + (lane & 3) * 2;
            if (c < N) {
                if (r < M)
                    *(float2*)(C + (size_t)r * N + c) =
                        make_float2(acc[mt][nt][0], acc[mt][nt][1]);
                if (r + 8 < M)
                    *(float2*)(C + (size_t)(r + 8) * N + c) =
                        make_float2(acc[mt][nt][2], acc[mt][nt][3]);
            }
        }
    }
#undef ISSUE_STAGE
}

// ---------------- RoPE ------------------------------------------------------
__global__ void rope_kernel(float* __restrict__ q, const float* __restrict__ down,
                            float* __restrict__ kpe)
{
    const int s = blockIdx.x;
    const int tid = threadIdx.x;
    const int h = tid >> 5;
    const int i = tid & 31;
    if (h > 16) return;

    const float invf = powf(10000.f, -(float)i / 32.f);
    const float ang = (float)s * invf;
    float sn, c;
    sincosf(ang, &sn, &c);

    if (h < 16) {
        float* p = q + (size_t)s * (NHEAD * QKD) + h * QKD + NOPE + 2 * i;
        const float x0 = p[0], x1 = p[1];
        p[0] = x0 * c - x1 * sn;
        p[1] = x0 * sn + x1 * c;
    } else {
        const float* p = down + (size_t)s * NDOWN + QL + KVL + 2 * i;
        const float x0 = p[0], x1 = p[1];
        kpe[(size_t)s * ROPE_D + 2 * i]     = x0 * c - x1 * sn;
        kpe[(size_t)s * ROPE_D + 2 * i + 1] = x0 * sn + x1 * c;
    }
}

// ---------------- MMA flash attention (bf16x3, causal) ----------------------
// grid (32, 16), block 256.  64 queries x 32-key tiles.
#define QP 584          // Qs/Ks pitch in bf16 (1168 B = 73 x16B units, odd -> conflict-free)
#define VP 104          // Vs/Ps3 pitch in bf16 (13 units, odd)
#define FP 36           // Pf pitch in floats
#define OFF_QS  0
#define OFF_KS  74752
#define OFF_VS  112128
#define OFF_PS3 138752
#define OFF_PF  152064
#define OFF_AL  161280
#define OFF_SL  161536
#define ATTN_SMEM 161792

__device__ __forceinline__ float fexp2(float x) {
    x = fmaxf(x, -126.f);
    const float fl = floorf(x);
    const float f = x - fl;
    float p =          1.525273380e-5f;
    p = fmaf(p, f, 1.540353039e-4f);
    p = fmaf(p, f, 1.333355815e-3f);
    p = fmaf(p, f, 9.618129107e-3f);
    p = fmaf(p, f, 5.550410866e-2f);
    p = fmaf(p, f, 2.402265070e-1f);
    p = fmaf(p, f, 6.931471806e-1f);
    p = fmaf(p, f, 1.0f);
    const int i = (int)fl;
    return __int_as_float((i + 127) << 23) * p;
}

// split a float pair into (hi2, lo2) bf16x2
__device__ __forceinline__ void split2(float a, float b,
                                       __nv_bfloat162& h2, __nv_bfloat162& l2) {
    __nv_bfloat16 ha = __float2bfloat16(a), hb = __float2bfloat16(b);
    h2 = __halves2bfloat162(ha, hb);
    l2 = __halves2bfloat162(__float2bfloat16(a - __bfloat162float(ha)),
                            __float2bfloat16(b - __bfloat162float(hb)));
}

__global__ void __launch_bounds__(256) attn_mma_kernel(
    const float* __restrict__ q,     // [S, H*192] roped
    const float* __restrict__ kvu,   // [S, H*256] (k_nope | v)
    const float* __restrict__ kpe,   // [S, 64]
    __nv_bfloat16* __restrict__ outA3)  // [S, 3*2048] bf16x3 A-layout
{
    const int qt = (int)gridDim.x - 1 - (int)blockIdx.x;   // heavy blocks first
    const int h  = blockIdx.y;
    extern __shared__ char sm8[];
    __nv_bfloat16* Qs  = (__nv_bfloat16*)(sm8 + OFF_QS);   // [64][QP]  A: [Qh|Ql|Qh]
    __nv_bfloat16* Ks  = (__nv_bfloat16*)(sm8 + OFF_KS);   // [32][QP]  B: [Kh|Kh|Kl]
    __nv_bfloat16* Vs  = (__nv_bfloat16*)(sm8 + OFF_VS);   // [128][VP] B: [Vh|Vh|Vl] (vh-major)
    __nv_bfloat16* Ps3 = (__nv_bfloat16*)(sm8 + OFF_PS3);  // [64][VP]  A: [Ph|Pl|Ph]
    float* Pf     = (float*)(sm8 + OFF_PF);                // [64][FP] scores
    float* sAlpha = (float*)(sm8 + OFF_AL);
    float* sL     = (float*)(sm8 + OFF_SL);

    const int tid = threadIdx.x, lane = tid & 31, wid = tid >> 5;
    const int wm = wid >> 1;     // 0..3 : 16-row slab
    const int wn = wid & 1;      // 0..1
    const float SCL = 0.07216878364870323f * 1.4426950408889634f; // rsqrt(192)*log2(e)

    // ---- load Q3 once ----
    {
        const float* qb = q + (size_t)(qt * 64) * (NHEAD * QKD) + h * QKD;
        for (int e = tid; e < 64 * 32; e += 256) {            // nope: d = u*4
            int i = e >> 5, u = e & 31;
            float4 v = *(const float4*)(qb + (size_t)i * (NHEAD * QKD) + u * 4);
            __nv_bfloat16* p = Qs + i * QP + u * 4;
            __nv_bfloat162 h2, l2;
            split2(v.x, v.y, h2, l2);
            *(__nv_bfloat162*)(p) = h2; *(__nv_bfloat162*)(p + 192) = l2;
            *(__nv_bfloat162*)(p + 384) = h2;
            split2(v.z, v.w, h2, l2);
            *(__nv_bfloat162*)(p + 2) = h2; *(__nv_bfloat162*)(p + 194) = l2;
            *(__nv_bfloat162*)(p + 386) = h2;
        }
        for (int e = tid; e < 64 * 16; e += 256) {            // pe: d = 128 + u*4
            int i = e >> 4, u = e & 15;
            float4 v = *(const float4*)(q + (size_t)(qt * 64 + i) * (NHEAD * QKD)
                                        + h * QKD + 128 + u * 4);
            __nv_bfloat16* p = Qs + i * QP + 128 + u * 4;
            __nv_bfloat162 h2, l2;
            split2(v.x, v.y, h2, l2);
            *(__nv_bfloat162*)(p) = h2; *(__nv_bfloat162*)(p + 192) = l2;
            *(__nv_bfloat162*)(p + 384) = h2;
            split2(v.z, v.w, h2, l2);
            *(__nv_bfloat162*)(p + 2) = h2; *(__nv_bfloat162*)(p + 194) = l2;
            *(__nv_bfloat162*)(p + 386) = h2;
        }
    }

    float accO[8][4];
#pragma unroll
    for (int i = 0; i < 8; i++)
#pragma unroll
        for (int j = 0; j < 4; j++) accO[i][j] = 0.f;

    // softmax role: 4 threads per row
    const int r_sm = tid >> 2, q_sm = tid & 3;
    const int qglob = qt * 64 + r_sm;
    float m_i = -1e30f, l_i = 0.f;

    const unsigned aQ = smem_u32(Qs) + (unsigned)(((wm * 16 + (lane & 15)) * QP
                                                   + (lane >> 4) * 8) * 2);
    const unsigned bK = smem_u32(Ks) + (unsigned)(((wn * 16 + (lane >> 4) * 8 + (lane & 7)) * QP
                                                   + ((lane >> 3) & 1) * 8) * 2);
    const unsigned aP = smem_u32(Ps3) + (unsigned)(((wm * 16 + (lane & 15)) * VP
                                                    + (lane >> 4) * 8) * 2);
    const unsigned bV = smem_u32(Vs) + (unsigned)(((wn * 64 + (lane >> 4) * 8 + (lane & 7)) * VP
                                                   + ((lane >> 3) & 1) * 8) * 2);

    const int nkt = 2 * (qt + 1);
    for (int kt = 0; kt < nkt; ++kt) {
        __syncthreads();   // A: prev PV done, safe to overwrite Ks/Vs

        // ---- load K3 + V3 (32 keys) ----
        const int tg0 = kt * 32;
        const float* knb = kvu + (size_t)tg0 * (NHEAD * 256) + h * 256;
        for (int e = tid; e < 32 * 32; e += 256) {            // k_nope
            int t = e >> 5, u = e & 31;
            float4 v = *(const float4*)(knb + (size_t)t * (NHEAD * 256) + u * 4);
            __nv_bfloat16* p = Ks + t * QP + u * 4;
            __nv_bfloat162 h2, l2;
            split2(v.x, v.y, h2, l2);
            *(__nv_bfloat162*)(p) = h2; *(__nv_bfloat162*)(p + 192) = h2;
            *(__nv_bfloat162*)(p + 384) = l2;
            split2(v.z, v.w, h2, l2);
            *(__nv_bfloat162*)(p + 2) = h2; *(__nv_bfloat162*)(p + 194) = h2;
            *(__nv_bfloat162*)(p + 386) = l2;
        }
        for (int e = tid; e < 32 * 16; e += 256) {            // k_pe
            int t = e >> 4, u = e & 15;
            float4 v = *(const float4*)(kpe + (size_t)(tg0 + t) * ROPE_D + u * 4);
            __nv_bfloat16* p = Ks + t * QP + 128 + u * 4;
            __nv_bfloat162 h2, l2;
            split2(v.x, v.y, h2, l2);
            *(__nv_bfloat162*)(p) = h2; *(__nv_bfloat162*)(p + 192) = h2;
            *(__nv_bfloat162*)(p + 384) = l2;
            split2(v.z, v.w, h2, l2);
            *(__nv_bfloat162*)(p + 2) = h2; *(__nv_bfloat162*)(p + 194) = h2;
            *(__nv_bfloat162*)(p + 386) = l2;
        }
        for (int e = tid; e < 32 * 32; e += 256) {            // V transposed
            int t = e >> 5, u = e & 31;
            float4 v = *(const float4*)(knb + (size_t)t * (NHEAD * 256) + 128 + u * 4);
            const int c = u * 4;
            float vv[4] = {v.x, v.y, v.z, v.w};
#pragma unroll
            for (int j = 0; j < 4; j++) {
                __nv_bfloat16 hv = __float2bfloat16(vv[j]);
                __nv_bfloat16 lv = __float2bfloat16(vv[j] - __bfloat162float(hv));
                __nv_bfloat16* p = Vs + (c + j) * VP;
                p[t] = hv; p[32 + t] = hv; p[64 + t] = lv;
            }
        }
        __syncthreads();   // B

        // ---- QK mma: 64x32 over K3=576 ----
        float acc[2][4] = {{0.f,0.f,0.f,0.f},{0.f,0.f,0.f,0.f}};
#pragma unroll 6
        for (int ck = 0; ck < 36; ++ck) {
            uint32_t a[4];
            ldsm_x4(a[0], a[1], a[2], a[3], aQ + (unsigned)(ck * 32));
            uint32_t b0, b1, b2, b3;
            ldsm_x4(b0, b1, b2, b3, bK + (unsigned)(ck * 32));
            uint32_t bb0[2] = {b0, b1}, bb1[2] = {b2, b3};
            mma16816(acc[0], a, bb0);
            mma16816(acc[1], a, bb1);
        }
        {
            const int rr = wm * 16 + (lane >> 2);
            const int cc = wn * 16 + (lane & 3) * 2;
#pragma unroll
            for (int nt = 0; nt < 2; ++nt) {
                Pf[rr * FP + cc + nt * 8]           = acc[nt][0] * SCL;
                Pf[rr * FP + cc + nt * 8 + 1]       = acc[nt][1] * SCL;
                Pf[(rr + 8) * FP + cc + nt * 8]     = acc[nt][2] * SCL;
                Pf[(rr + 8) * FP + cc + nt * 8 + 1] = acc[nt][3] * SCL;
            }
        }
        __syncthreads();   // C

        // ---- softmax (4 threads per row, 8 cols each) ----
        {
            float s[8];
            float lmax = -1e30f;
            const int cbase = q_sm * 8;
#pragma unroll
            for (int j = 0; j < 8; j++) {
                const int tglob = tg0 + cbase + j;
                float sv = Pf[r_sm * FP + cbase + j];
                s[j] = (tglob <= qglob) ? sv : -1e30f;
                lmax = fmaxf(lmax, s[j]);
            }
            lmax = fmaxf(lmax, __shfl_xor_sync(0xffffffffu, lmax, 1));
            lmax = fmaxf(lmax, __shfl_xor_sync(0xffffffffu, lmax, 2));
            const float m_new = fmaxf(m_i, lmax);
            const float alpha = fexp2(m_i - m_new);
            float lsum = 0.f;
            float pv[8];
#pragma unroll
            for (int j = 0; j < 8; j++) {
                pv[j] = fexp2(s[j] - m_new);
                lsum += pv[j];
            }
            // write P3: [Ph|Pl|Ph]
            __nv_bfloat16* pd = Ps3 + r_sm * VP + cbase;
#pragma unroll
            for (int j = 0; j < 8; j += 2) {
                __nv_bfloat162 h2, l2;
                split2(pv[j], pv[j + 1], h2, l2);
                *(__nv_bfloat162*)(pd + j)      = h2;
                *(__nv_bfloat162*)(pd + 32 + j) = l2;
                *(__nv_bfloat162*)(pd + 64 + j) = h2;
            }
            lsum += __shfl_xor_sync(0xffffffffu, lsum, 1);
            lsum += __shfl_xor_sync(0xffffffffu, lsum, 2);
            l_i = l_i * alpha + lsum;
            m_i = m_new;
            if (q_sm == 0) { sAlpha[r_sm] = alpha; sL[r_sm] = l_i; }
        }
        __syncthreads();   // D

        // ---- accO rescale + PV mma: 64x128 over K3=96 ----
        {
            const float al0 = sAlpha[wm * 16 + (lane >> 2)];
            const float al1 = sAlpha[wm * 16 + (lane >> 2) + 8];
#pragma unroll
            for (int nt = 0; nt < 8; ++nt) {
                accO[nt][0] *= al0; accO[nt][1] *= al0;
                accO[nt][2] *= al1; accO[nt][3] *= al1;
            }
#pragma unroll
            for (int ck = 0; ck < 6; ++ck) {
                uint32_t a[4];
                ldsm_x4(a[0], a[1], a[2], a[3], aP + (unsigned)(ck * 32));
#pragma unroll
                for (int bp = 0; bp < 4; ++bp) {
                    uint32_t r0, r1, r2, r3;
                    ldsm_x4(r0, r1, r2, r3,
                            bV + (unsigned)((bp * 16 * VP + ck * 16) * 2));
                    uint32_t bb0[2] = {r0, r1}, bb1[2] = {r2, r3};
                    mma16816(accO[bp * 2],     a, bb0);
                    mma16816(accO[bp * 2 + 1], a, bb1);
                }
            }
        }
    }

    __syncthreads();
    // ---- epilogue: /l, write bf16x3 A layout into outA3 ----
    {
        const int rr = wm * 16 + (lane >> 2);
        const float il0 = 1.f / sL[rr];
        const float il1 = 1.f / sL[rr + 8];
        const int row0 = qt * 64 + rr;
        __nv_bfloat16* d0 = outA3 + (size_t)row0 * 3 * AK;
        __nv_bfloat16* d1 = outA3 + (size_t)(row0 + 8) * 3 * AK;
#pragma unroll
        for (int nt = 0; nt < 8; ++nt) {
            const int col = h * VH + wn * 64 + nt * 8 + (lane & 3) * 2;
            __nv_bfloat162 h2, l2;
            split2(accO[nt][0] * il0, accO[nt][1] * il0, h2, l2);
            *(__nv_bfloat162*)(d0 + col)          = h2;
            *(__nv_bfloat162*)(d0 + AK + col)     = l2;
            *(__nv_bfloat162*)(d0 + 2 * AK + col) = h2;
            split2(accO[nt][2] * il1, accO[nt][3] * il1, h2, l2);
            *(__nv_bfloat162*)(d1 + col)          = h2;
            *(__nv_bfloat162*)(d1 + AK + col)     = l2;
            *(__nv_bfloat162*)(d1 + 2 * AK + col) = h2;
        }
    }
}

// ---------------- host orchestration ---------------------------------------
static inline void launch_split(const float* src, __nv_bfloat16* dst,
                                int rows, int K, int modeB)
{
    dim3 grid((K + 255) / 256, rows);
    split3_kernel<<<grid, 256>>>(src, dst, K, modeB);
}

static inline void launch_gemm3(const __nv_bfloat16* A3, const __nv_bfloat16* B3,
                                float* C, int M, int N, int K)
{
    cudaFuncSetAttribute(gemm_bf16x3_kernel,
                         cudaFuncAttributeMaxDynamicSharedMemorySize, GEMM_SMEM);
    dim3 grid((N + TBN - 1) / TBN, (M + TBM - 1) / TBM);
    gemm_bf16x3_kernel<<<grid, 256, GEMM_SMEM>>>(A3, B3, C, M, N, 3 * K);
}

extern "C" void kernel_launch(void* const* d_in, const int* in_sizes, int n_in,
                              void* d_out, int out_size)
{
    const float* x        = (const float*)d_in[0];
    const float* wq_down  = (const float*)d_in[1];
    const float* q_norm_w = (const float*)d_in[2];
    const float* wq_up    = (const float*)d_in[3];
    const float* wkv_down = (const float*)d_in[4];
    const float* kv_norm_w= (const float*)d_in[5];
    const float* wkv_up   = (const float*)d_in[6];
    const float* wo       = (const float*)d_in[7];
    float* out = (float*)d_out;

    float *down, *kvnorm, *qbuf, *kvu, *kpe;
    __nv_bfloat16 *A3, *B3;
    cudaGetSymbolAddress((void**)&down,   g_down);
    cudaGetSymbolAddress((void**)&kvnorm, g_kvnorm);
    cudaGetSymbolAddress((void**)&qbuf,   g_q);
    cudaGetSymbolAddress((void**)&kvu,    g_kvu);
    cudaGetSymbolAddress((void**)&kpe,    g_kpe);
    cudaGetSymbolAddress((void**)&A3,     g_A3);
    cudaGetSymbolAddress((void**)&B3,     g_B3);

    __nv_bfloat16* B3kv = B3 + (size_t)QL * 3 * DIM;

    // 1) splits for merged down-projection
    launch_split(x, A3, S_LEN, DIM, 0);
    launch_split(wq_down, B3, QL, DIM, 1);
    launch_split(wkv_down, B3kv, KVL + ROPE_D, DIM, 1);

    // 2) merged down-projection GEMM: [2048, 2112]
    launch_gemm3(A3, B3, down, S_LEN, NDOWN, DIM);

    // 3) norms
    rms_kernel<<<S_LEN, 256>>>(down + QL, kv_norm_w, kvnorm, KVL, NDOWN, KVL);
    rms_split_kernel<<<S_LEN, 256>>>(down, q_norm_w, A3, QL, NDOWN);

    // 4) q up-projection
    launch_split(wq_up, B3, NHEAD * QKD, QL, 1);
    launch_gemm3(A3, B3, qbuf, S_LEN, NHEAD * QKD, QL);

    // 5) kv up-projection
    launch_split(kvnorm, A3, S_LEN, KVL, 0);
    launch_split(wkv_up, B3, NHEAD * (NOPE + VH), KVL, 1);
    launch_gemm3(A3, B3, kvu, S_LEN, NHEAD * (NOPE + VH), KVL);

    // 6) rope
    rope_kernel<<<S_LEN, 544>>>(qbuf, down, kpe);

    // 7) mma flash attention (epilogue writes bf16x3 into A3)
    cudaFuncSetAttribute(attn_mma_kernel, cudaFuncAttributeMaxDynamicSharedMemorySize,
                         ATTN_SMEM);
    dim3 agrid(S_LEN / 64, NHEAD);
    attn_mma_kernel<<<agrid, 256, ATTN_SMEM>>>(qbuf, kvu, kpe, A3);

    // 8) output projection
    launch_split(wo, B3, DIM, NHEAD * VH, 1);
    launch_gemm3(A3, B3, out, S_LEN, DIM, NHEAD * VH);
}

// round 9
// speedup vs baseline: 1.2436x; 1.0015x over previous
#include <cuda_runtime.h>
#include <cuda_bf16.h>
#include <math.h>
#include <stdint.h>

// Problem constants
#define S_LEN 2048
#define DIM   2048
#define NHEAD 16
#define QL    1536
#define KVL   512
#define NOPE  128
#define ROPE_D 64
#define VH    128
#define QKD   192   // NOPE + ROPE
#define EPS   1e-6f
#define NDOWN (QL + KVL + ROPE_D)   // 2112 : merged down-proj output cols
#define AK (NHEAD * VH)             // 2048

// ---------------- scratch (device globals; no allocation allowed) ----------
__device__ float g_down [S_LEN * NDOWN];           // [2048, 2112] = qdown | kv
__device__ float g_kvnorm[S_LEN * KVL];
__device__ float g_q    [S_LEN * NHEAD * QKD];     // roped in place
__device__ float g_kvu  [S_LEN * NHEAD * (NOPE + VH)];
__device__ float g_kpe  [S_LEN * ROPE_D];

// bf16x3 operand scratch
__device__ __nv_bfloat16 g_A3[(size_t)S_LEN * 3 * DIM];
__device__ __nv_bfloat16 g_B3[(size_t)3072 * 3 * 1536];

// ---------------- fp32 -> (hi,lo) bf16 split kernels -----------------------
__global__ void split3_kernel(const float* __restrict__ src,
                              __nv_bfloat16* __restrict__ dst,
                              int K, int modeB)
{
    const int r = blockIdx.y;
    const int k = blockIdx.x * 256 + threadIdx.x;
    if (k >= K) return;
    const float v = src[(size_t)r * K + k];
    const __nv_bfloat16 h = __float2bfloat16(v);
    const __nv_bfloat16 l = __float2bfloat16(v - __bfloat162float(h));
    __nv_bfloat16* d = dst + (size_t)r * 3 * K;
    d[k] = h;
    d[K + k]     = modeB ? h : l;
    d[2 * K + k] = modeB ? l : h;
}

// ---------------- RMSNorm (fp32 out, strided input) ------------------------
__global__ void rms_kernel(const float* __restrict__ in, const float* __restrict__ w,
                           float* __restrict__ out, int n, int istride, int ostride)
{
    const int row = blockIdx.x;
    const float* x = in + (size_t)row * istride;

    float ss = 0.f;
    for (int i = threadIdx.x; i < n; i += blockDim.x) {
        float v = x[i];
        ss += v * v;
    }
#pragma unroll
    for (int o = 16; o; o >>= 1) ss += __shfl_xor_sync(0xffffffffu, ss, o);

    __shared__ float warpsum[8];
    __shared__ float sScale;
    const int wid = threadIdx.x >> 5;
    if ((threadIdx.x & 31) == 0) warpsum[wid] = ss;
    __syncthreads();
    if (threadIdx.x == 0) {
        float tot = 0.f;
        for (int i = 0; i < (int)(blockDim.x >> 5); i++) tot += warpsum[i];
        sScale = rsqrtf(tot / (float)n + EPS);
    }
    __syncthreads();
    const float sc = sScale;
    for (int i = threadIdx.x; i < n; i += blockDim.x)
        out[(size_t)row * ostride + i] = x[i] * sc * w[i];
}

// ---------------- RMSNorm fused with bf16x3 A-split ------------------------
__global__ void rms_split_kernel(const float* __restrict__ in, const float* __restrict__ w,
                                 __nv_bfloat16* __restrict__ dst, int n, int istride)
{
    const int row = blockIdx.x;
    const float* x = in + (size_t)row * istride;

    float ss = 0.f;
    for (int i = threadIdx.x; i < n; i += blockDim.x) {
        float v = x[i];
        ss += v * v;
    }
#pragma unroll
    for (int o = 16; o; o >>= 1) ss += __shfl_xor_sync(0xffffffffu, ss, o);

    __shared__ float warpsum[8];
    __shared__ float sScale;
    const int wid = threadIdx.x >> 5;
    if ((threadIdx.x & 31) == 0) warpsum[wid] = ss;
    __syncthreads();
    if (threadIdx.x == 0) {
        float tot = 0.f;
        for (int i = 0; i < (int)(blockDim.x >> 5); i++) tot += warpsum[i];
        sScale = rsqrtf(tot / (float)n + EPS);
    }
    __syncthreads();
    const float sc = sScale;
    __nv_bfloat16* d = dst + (size_t)row * 3 * n;
    for (int i = threadIdx.x; i < n; i += blockDim.x) {
        const float v = x[i] * sc * w[i];
        const __nv_bfloat16 h = __float2bfloat16(v);
        const __nv_bfloat16 l = __float2bfloat16(v - __bfloat162float(h));
        d[i] = h; d[n + i] = l; d[2 * n + i] = h;
    }
}

// ---------------- shared mma helpers ----------------------------------------
__device__ __forceinline__ unsigned smem_u32(const void* p) {
    return (unsigned)__cvta_generic_to_shared(p);
}
__device__ __forceinline__ void cp16(unsigned s, const void* g, bool pred) {
    int sz = pred ? 16 : 0;
    asm volatile("cp.async.cg.shared.global [%0], [%1], 16, %2;\n"
                 :: "r"(s), "l"(g), "r"(sz));
}
__device__ __forceinline__ void ldsm_x4(uint32_t& r0, uint32_t& r1,
                                        uint32_t& r2, uint32_t& r3, unsigned addr) {
    asm volatile("ldmatrix.sync.aligned.m8n8.x4.shared.b16 {%0,%1,%2,%3}, [%4];"
                 : "=r"(r0), "=r"(r1), "=r"(r2), "=r"(r3) : "r"(addr));
}
__device__ __forceinline__ void mma16816(float* c, const uint32_t* a, const uint32_t* b) {
    asm volatile(
        "mma.sync.aligned.m16n8k16.row.col.f32.bf16.bf16.f32 "
        "{%0,%1,%2,%3}, {%4,%5,%6,%7}, {%8,%9}, {%0,%1,%2,%3};"
        : "+f"(c[0]), "+f"(c[1]), "+f"(c[2]), "+f"(c[3])
        : "r"(a[0]), "r"(a[1]), "r"(a[2]), "r"(a[3]), "r"(b[0]), "r"(b[1]));
}

// ---------------- bf16x3 tensor-core GEMM (v5: 2 CTAs/SM) ------------------
#define TBM 128
#define TBN 128
#define TBK 32
#define AP  40
#define STAGES 4
#define GEMM_SMEM (STAGES * 2 * TBM * AP * 2)   // 81920 B -> 2 CTAs/SM

__global__ void __launch_bounds__(256, 2) gemm_bf16x3_kernel(
    const __nv_bfloat16* __restrict__ A,   // [M, K3]
    const __nv_bfloat16* __restrict__ B,   // [N, K3]
    float* __restrict__ C, int M, int N, int K3)
{
    extern __shared__ __nv_bfloat16 smem[];
    __nv_bfloat16* As = smem;
    __nv_bfloat16* Bs = smem + STAGES * TBM * AP;

    const int tid = threadIdx.x, lane = tid & 31, wid = tid >> 5;
    const int wm = wid & 1;
    const int wn = wid >> 1;
    const int row0 = blockIdx.y * TBM, col0 = blockIdx.x * TBN;

    const int c0 = tid * 2;
    const int lr = c0 >> 2;
    const int lu = c0 & 3;
    const bool aval = (row0 + lr) < M;
    const bool bval = (col0 + lr) < N;
    const __nv_bfloat16* Ag = A + (size_t)(row0 + lr) * K3 + lu * 8;
    const __nv_bfloat16* Bg = B + (size_t)(col0 + lr) * K3 + lu * 8;
    const unsigned soff = (unsigned)((lr * AP + lu * 8) * 2);

    float acc[4][4][4];
#pragma unroll
    for (int i = 0; i < 4; i++)
#pragma unroll
        for (int j = 0; j < 4; j++)
#pragma unroll
            for (int k = 0; k < 4; k++) acc[i][j][k] = 0.f;

    const int NKB = K3 / TBK;

#define ISSUE_STAGE(KB, ST) do {                                              \
        unsigned sa = smem_u32(As + (ST) * TBM * AP) + soff;                  \
        unsigned sb = smem_u32(Bs + (ST) * TBM * AP) + soff;                  \
        const __nv_bfloat16* ga = Ag + (size_t)(KB) * TBK;                    \
        const __nv_bfloat16* gb = Bg + (size_t)(KB) * TBK;                    \
        cp16(sa, ga, aval);  cp16(sa + 16, ga + 8, aval);                     \
        cp16(sb, gb, bval);  cp16(sb + 16, gb + 8, bval);                     \
        asm volatile("cp.async.commit_group;\n" ::: "memory");                \
    } while (0)

    ISSUE_STAGE(0, 0);
    ISSUE_STAGE(1, 1);
    ISSUE_STAGE(2, 2);

    const unsigned aoff = (unsigned)(((wm * 64 + (lane & 15)) * AP + (lane >> 4) * 8) * 2);
    const unsigned boff = (unsigned)(((wn * 32 + (lane >> 4) * 8 + (lane & 7)) * AP
                                      + ((lane >> 3) & 1) * 8) * 2);

    for (int kb = 0; kb < NKB; ++kb) {
        asm volatile("cp.async.wait_group 2;\n" ::: "memory");
        __syncthreads();

        if (kb + 3 < NKB) { ISSUE_STAGE(kb + 3, (kb + 3) & 3); }
        else { asm volatile("cp.async.commit_group;\n" ::: "memory"); }

        const int st = kb & 3;
        const unsigned aAddr = smem_u32(As + st * TBM * AP) + aoff;
        const unsigned bAddr = smem_u32(Bs + st * TBM * AP) + boff;

        uint32_t af[2][4][4];
        uint32_t bfr[2][4][2];
#pragma unroll
        for (int kk = 0; kk < 2; ++kk) {
#pragma unroll
            for (int mt = 0; mt < 4; ++mt)
                ldsm_x4(af[kk][mt][0], af[kk][mt][1], af[kk][mt][2], af[kk][mt][3],
                        aAddr + (unsigned)((mt * 16 * AP + kk * 16) * 2));
#pragma unroll
            for (int bp = 0; bp < 2; ++bp) {
                uint32_t r0, r1, r2, r3;
                ldsm_x4(r0, r1, r2, r3,
                        bAddr + (unsigned)((bp * 16 * AP + kk * 16) * 2));
                bfr[kk][2 * bp][0] = r0;      bfr[kk][2 * bp][1] = r1;
                bfr[kk][2 * bp + 1][0] = r2;  bfr[kk][2 * bp + 1][1] = r3;
            }
        }
#pragma unroll
        for (int kk = 0; kk < 2; ++kk)
#pragma unroll
            for (int mt = 0; mt < 4; ++mt)
#pragma unroll
                for (int nt = 0; nt < 4; ++nt)
                    mma16816(acc[mt][nt], af[kk][mt], bfr[kk][nt]);
    }

#pragma unroll
    for (int mt = 0; mt < 4; ++mt) {
#pragma unroll
        for (int nt = 0; nt < 4; ++nt) {
            const int r = row0 + wm * 64 + mt * 16 + (lane >> 2);
            const int c = col0 + wn * 32 + nt * 8 + (lane & 3) * 2;
            if (c < N) {
                if (r < M)
                    *(float2*)(C + (size_t)r * N + c) =
                        make_float2(acc[mt][nt][0], acc[mt][nt][1]);
                if (r + 8 < M)
                    *(float2*)(C + (size_t)(r + 8) * N + c) =
                        make_float2(acc[mt][nt][2], acc[mt][nt][3]);
            }
        }
    }
#undef ISSUE_STAGE
}

// ---------------- RoPE ------------------------------------------------------
__global__ void rope_kernel(float* __restrict__ q, const float* __restrict__ down,
                            float* __restrict__ kpe)
{
    const int s = blockIdx.x;
    const int tid = threadIdx.x;
    const int h = tid >> 5;
    const int i = tid & 31;
    if (h > 16) return;

    const float invf = powf(10000.f, -(float)i / 32.f);
    const float ang = (float)s * invf;
    float sn, c;
    sincosf(ang, &sn, &c);

    if (h < 16) {
        float* p = q + (size_t)s * (NHEAD * QKD) + h * QKD + NOPE + 2 * i;
        const float x0 = p[0], x1 = p[1];
        p[0] = x0 * c - x1 * sn;
        p[1] = x0 * sn + x1 * c;
    } else {
        const float* p = down + (size_t)s * NDOWN + QL + KVL + 2 * i;
        const float x0 = p[0], x1 = p[1];
        kpe[(size_t)s * ROPE_D + 2 * i]     = x0 * c - x1 * sn;
        kpe[(size_t)s * ROPE_D + 2 * i + 1] = x0 * sn + x1 * c;
    }
}

// ---------------- MMA flash attention (bf16x3, causal) ----------------------
// grid (32, 16), block 256.  64 queries x 32-key tiles.
#define QP 584          // Qs/Ks pitch in bf16 (1168 B = 73 x16B units, odd -> conflict-free)
#define VP 104          // Vs/Ps3 pitch in bf16 (13 units, odd)
#define FP 36           // Pf pitch in floats
#define OFF_QS  0
#define OFF_KS  74752
#define OFF_VS  112128
#define OFF_PS3 138752
#define OFF_PF  152064
#define OFF_AL  161280
#define OFF_SL  161536
#define ATTN_SMEM 161792

__device__ __forceinline__ float fexp2(float x) {
    x = fmaxf(x, -126.f);
    const float fl = floorf(x);
    const float f = x - fl;
    float p =          1.525273380e-5f;
    p = fmaf(p, f, 1.540353039e-4f);
    p = fmaf(p, f, 1.333355815e-3f);
    p = fmaf(p, f, 9.618129107e-3f);
    p = fmaf(p, f, 5.550410866e-2f);
    p = fmaf(p, f, 2.402265070e-1f);
    p = fmaf(p, f, 6.931471806e-1f);
    p = fmaf(p, f, 1.0f);
    const int i = (int)fl;
    return __int_as_float((i + 127) << 23) * p;
}

// split a float pair into (hi2, lo2) bf16x2
__device__ __forceinline__ void split2(float a, float b,
                                       __nv_bfloat162& h2, __nv_bfloat162& l2) {
    __nv_bfloat16 ha = __float2bfloat16(a), hb = __float2bfloat16(b);
    h2 = __halves2bfloat162(ha, hb);
    l2 = __halves2bfloat162(__float2bfloat16(a - __bfloat162float(ha)),
                            __float2bfloat16(b - __bfloat162float(hb)));
}

__global__ void __launch_bounds__(256) attn_mma_kernel(
    const float* __restrict__ q,     // [S, H*192] roped
    const float* __restrict__ kvu,   // [S, H*256] (k_nope | v)
    const float* __restrict__ kpe,   // [S, 64]
    __nv_bfloat16* __restrict__ outA3)  // [S, 3*2048] bf16x3 A-layout
{
    const int qt = (int)gridDim.x - 1 - (int)blockIdx.x;   // heavy blocks first
    const int h  = blockIdx.y;
    extern __shared__ char sm8[];
    __nv_bfloat16* Qs  = (__nv_bfloat16*)(sm8 + OFF_QS);   // [64][QP]  A: [Qh|Ql|Qh]
    __nv_bfloat16* Ks  = (__nv_bfloat16*)(sm8 + OFF_KS);   // [32][QP]  B: [Kh|Kh|Kl]
    __nv_bfloat16* Vs  = (__nv_bfloat16*)(sm8 + OFF_VS);   // [128][VP] B: [Vh|Vh|Vl] (vh-major)
    __nv_bfloat16* Ps3 = (__nv_bfloat16*)(sm8 + OFF_PS3);  // [64][VP]  A: [Ph|Pl|Ph]
    float* Pf     = (float*)(sm8 + OFF_PF);                // [64][FP] scores
    float* sAlpha = (float*)(sm8 + OFF_AL);
    float* sL     = (float*)(sm8 + OFF_SL);

    const int tid = threadIdx.x, lane = tid & 31, wid = tid >> 5;
    const int wm = wid >> 1;     // 0..3 : 16-row slab
    const int wn = wid & 1;      // 0..1
    const float SCL = 0.07216878364870323f * 1.4426950408889634f; // rsqrt(192)*log2(e)

    // ---- load Q3 once ----
    {
        const float* qb = q + (size_t)(qt * 64) * (NHEAD * QKD) + h * QKD;
        for (int e = tid; e < 64 * 32; e += 256) {            // nope: d = u*4
            int i = e >> 5, u = e & 31;
            float4 v = *(const float4*)(qb + (size_t)i * (NHEAD * QKD) + u * 4);
            __nv_bfloat16* p = Qs + i * QP + u * 4;
            __nv_bfloat162 h2, l2;
            split2(v.x, v.y, h2, l2);
            *(__nv_bfloat162*)(p) = h2; *(__nv_bfloat162*)(p + 192) = l2;
            *(__nv_bfloat162*)(p + 384) = h2;
            split2(v.z, v.w, h2, l2);
            *(__nv_bfloat162*)(p + 2) = h2; *(__nv_bfloat162*)(p + 194) = l2;
            *(__nv_bfloat162*)(p + 386) = h2;
        }
        for (int e = tid; e < 64 * 16; e += 256) {            // pe: d = 128 + u*4
            int i = e >> 4, u = e & 15;
            float4 v = *(const float4*)(q + (size_t)(qt * 64 + i) * (NHEAD * QKD)
                                        + h * QKD + 128 + u * 4);
            __nv_bfloat16* p = Qs + i * QP + 128 + u * 4;
            __nv_bfloat162 h2, l2;
            split2(v.x, v.y, h2, l2);
            *(__nv_bfloat162*)(p) = h2; *(__nv_bfloat162*)(p + 192) = l2;
            *(__nv_bfloat162*)(p + 384) = h2;
            split2(v.z, v.w, h2, l2);
            *(__nv_bfloat162*)(p + 2) = h2; *(__nv_bfloat162*)(p + 194) = l2;
            *(__nv_bfloat162*)(p + 386) = h2;
        }
    }

    float accO[8][4];
#pragma unroll
    for (int i = 0; i < 8; i++)
#pragma unroll
        for (int j = 0; j < 4; j++) accO[i][j] = 0.f;

    // softmax role: 4 threads per row
    const int r_sm = tid >> 2, q_sm = tid & 3;
    const int qglob = qt * 64 + r_sm;
    float m_i = -1e30f, l_i = 0.f;

    const unsigned aQ = smem_u32(Qs) + (unsigned)(((wm * 16 + (lane & 15)) * QP
                                                   + (lane >> 4) * 8) * 2);
    const unsigned bK = smem_u32(Ks) + (unsigned)(((wn * 16 + (lane >> 4) * 8 + (lane & 7)) * QP
                                                   + ((lane >> 3) & 1) * 8) * 2);
    const unsigned aP = smem_u32(Ps3) + (unsigned)(((wm * 16 + (lane & 15)) * VP
                                                    + (lane >> 4) * 8) * 2);
    const unsigned bV = smem_u32(Vs) + (unsigned)(((wn * 64 + (lane >> 4) * 8 + (lane & 7)) * VP
                                                   + ((lane >> 3) & 1) * 8) * 2);

    const int nkt = 2 * (qt + 1);
    for (int kt = 0; kt < nkt; ++kt) {
        __syncthreads();   // A: prev PV done, safe to overwrite Ks/Vs

        // ---- load K3 + V3 (32 keys) ----
        const int tg0 = kt * 32;
        const float* knb = kvu + (size_t)tg0 * (NHEAD * 256) + h * 256;
        for (int e = tid; e < 32 * 32; e += 256) {            // k_nope
            int t = e >> 5, u = e & 31;
            float4 v = *(const float4*)(knb + (size_t)t * (NHEAD * 256) + u * 4);
            __nv_bfloat16* p = Ks + t * QP + u * 4;
            __nv_bfloat162 h2, l2;
            split2(v.x, v.y, h2, l2);
            *(__nv_bfloat162*)(p) = h2; *(__nv_bfloat162*)(p + 192) = h2;
            *(__nv_bfloat162*)(p + 384) = l2;
            split2(v.z, v.w, h2, l2);
            *(__nv_bfloat162*)(p + 2) = h2; *(__nv_bfloat162*)(p + 194) = h2;
            *(__nv_bfloat162*)(p + 386) = l2;
        }
        for (int e = tid; e < 32 * 16; e += 256) {            // k_pe
            int t = e >> 4, u = e & 15;
            float4 v = *(const float4*)(kpe + (size_t)(tg0 + t) * ROPE_D + u * 4);
            __nv_bfloat16* p = Ks + t * QP + 128 + u * 4;
            __nv_bfloat162 h2, l2;
            split2(v.x, v.y, h2, l2);
            *(__nv_bfloat162*)(p) = h2; *(__nv_bfloat162*)(p + 192) = h2;
            *(__nv_bfloat162*)(p + 384) = l2;
            split2(v.z, v.w, h2, l2);
            *(__nv_bfloat162*)(p + 2) = h2; *(__nv_bfloat162*)(p + 194) = h2;
            *(__nv_bfloat162*)(p + 386) = l2;
        }
        for (int e = tid; e < 32 * 32; e += 256) {            // V transposed
            int t = e >> 5, u = e & 31;
            float4 v = *(const float4*)(knb + (size_t)t * (NHEAD * 256) + 128 + u * 4);
            const int c = u * 4;
            float vv[4] = {v.x, v.y, v.z, v.w};
#pragma unroll
            for (int j = 0; j < 4; j++) {
                __nv_bfloat16 hv = __float2bfloat16(vv[j]);
                __nv_bfloat16 lv = __float2bfloat16(vv[j] - __bfloat162float(hv));
                __nv_bfloat16* p = Vs + (c + j) * VP;
                p[t] = hv; p[32 + t] = hv; p[64 + t] = lv;
            }
        }
        __syncthreads();   // B

        // ---- QK mma: 64x32 over K3=576 ----
        float acc[2][4] = {{0.f,0.f,0.f,0.f},{0.f,0.f,0.f,0.f}};
#pragma unroll 6
        for (int ck = 0; ck < 36; ++ck) {
            uint32_t a[4];
            ldsm_x4(a[0], a[1], a[2], a[3], aQ + (unsigned)(ck * 32));
            uint32_t b0, b1, b2, b3;
            ldsm_x4(b0, b1, b2, b3, bK + (unsigned)(ck * 32));
            uint32_t bb0[2] = {b0, b1}, bb1[2] = {b2, b3};
            mma16816(acc[0], a, bb0);
            mma16816(acc[1], a, bb1);
        }
        {
            const int rr = wm * 16 + (lane >> 2);
            const int cc = wn * 16 + (lane & 3) * 2;
#pragma unroll
            for (int nt = 0; nt < 2; ++nt) {
                Pf[rr * FP + cc + nt * 8]           = acc[nt][0] * SCL;
                Pf[rr * FP + cc + nt * 8 + 1]       = acc[nt][1] * SCL;
                Pf[(rr + 8) * FP + cc + nt * 8]     = acc[nt][2] * SCL;
                Pf[(rr + 8) * FP + cc + nt * 8 + 1] = acc[nt][3] * SCL;
            }
        }
        __syncthreads();   // C

        // ---- softmax (4 threads per row, 8 cols each) ----
        {
            float s[8];
            float lmax = -1e30f;
            const int cbase = q_sm * 8;
#pragma unroll
            for (int j = 0; j < 8; j++) {
                const int tglob = tg0 + cbase + j;
                float sv = Pf[r_sm * FP + cbase + j];
                s[j] = (tglob <= qglob) ? sv : -1e30f;
                lmax = fmaxf(lmax, s[j]);
            }
            lmax = fmaxf(lmax, __shfl_xor_sync(0xffffffffu, lmax, 1));
            lmax = fmaxf(lmax, __shfl_xor_sync(0xffffffffu, lmax, 2));
            const float m_new = fmaxf(m_i, lmax);
            const float alpha = fexp2(m_i - m_new);
            float lsum = 0.f;
            float pv[8];
#pragma unroll
            for (int j = 0; j < 8; j++) {
                pv[j] = fexp2(s[j] - m_new);
                lsum += pv[j];
            }
            // write P3: [Ph|Pl|Ph]
            __nv_bfloat16* pd = Ps3 + r_sm * VP + cbase;
#pragma unroll
            for (int j = 0; j < 8; j += 2) {
                __nv_bfloat162 h2, l2;
                split2(pv[j], pv[j + 1], h2, l2);
                *(__nv_bfloat162*)(pd + j)      = h2;
                *(__nv_bfloat162*)(pd + 32 + j) = l2;
                *(__nv_bfloat162*)(pd + 64 + j) = h2;
            }
            lsum += __shfl_xor_sync(0xffffffffu, lsum, 1);
            lsum += __shfl_xor_sync(0xffffffffu, lsum, 2);
            l_i = l_i * alpha + lsum;
            m_i = m_new;
            if (q_sm == 0) { sAlpha[r_sm] = alpha; sL[r_sm] = l_i; }
        }
        __syncthreads();   // D

        // ---- accO rescale + PV mma: 64x128 over K3=96 ----
        {
            const float al0 = sAlpha[wm * 16 + (lane >> 2)];
            const float al1 = sAlpha[wm * 16 + (lane >> 2) + 8];
#pragma unroll
            for (int nt = 0; nt < 8; ++nt) {
                accO[nt][0] *= al0; accO[nt][1] *= al0;
                accO[nt][2] *= al1; accO[nt][3] *= al1;
            }
#pragma unroll
            for (int ck = 0; ck < 6; ++ck) {
                uint32_t a[4];
                ldsm_x4(a[0], a[1], a[2], a[3], aP + (unsigned)(ck * 32));
#pragma unroll
                for (int bp = 0; bp < 4; ++bp) {
                    uint32_t r0, r1, r2, r3;
                    ldsm_x4(r0, r1, r2, r3,
                            bV + (unsigned)((bp * 16 * VP + ck * 16) * 2));
                    uint32_t bb0[2] = {r0, r1}, bb1[2] = {r2, r3};
                    mma16816(accO[bp * 2],     a, bb0);
                    mma16816(accO[bp * 2 + 1], a, bb1);
                }
            }
        }
    }

    __syncthreads();
    // ---- epilogue: /l, write bf16x3 A layout into outA3 ----
    {
        const int rr = wm * 16 + (lane >> 2);
        const float il0 = 1.f / sL[rr];
        const float il1 = 1.f / sL[rr + 8];
        const int row0 = qt * 64 + rr;
        __nv_bfloat16* d0 = outA3 + (size_t)row0 * 3 * AK;
        __nv_bfloat16* d1 = outA3 + (size_t)(row0 + 8) * 3 * AK;
#pragma unroll
        for (int nt = 0; nt < 8; ++nt) {
            const int col = h * VH + wn * 64 + nt * 8 + (lane & 3) * 2;
            __nv_bfloat162 h2, l2;
            split2(accO[nt][0] * il0, accO[nt][1] * il0, h2, l2);
            *(__nv_bfloat162*)(d0 + col)          = h2;
            *(__nv_bfloat162*)(d0 + AK + col)     = l2;
            *(__nv_bfloat162*)(d0 + 2 * AK + col) = h2;
            split2(accO[nt][2] * il1, accO[nt][3] * il1, h2, l2);
            *(__nv_bfloat162*)(d1 + col)          = h2;
            *(__nv_bfloat162*)(d1 + AK + col)     = l2;
            *(__nv_bfloat162*)(d1 + 2 * AK + col) = h2;
        }
    }
}

// ---------------- host orchestration ---------------------------------------
static inline void launch_split(const float* src, __nv_bfloat16* dst,
                                int rows, int K, int modeB)
{
    dim3 grid((K + 255) / 256, rows);
    split3_kernel<<<grid, 256>>>(src, dst, K, modeB);
}

static inline void launch_gemm3(const __nv_bfloat16* A3, const __nv_bfloat16* B3,
                                float* C, int M, int N, int K)
{
    cudaFuncSetAttribute(gemm_bf16x3_kernel,
                         cudaFuncAttributeMaxDynamicSharedMemorySize, GEMM_SMEM);
    dim3 grid((N + TBN - 1) / TBN, (M + TBM - 1) / TBM);
    gemm_bf16x3_kernel<<<grid, 256, GEMM_SMEM>>>(A3, B3, C, M, N, 3 * K);
}

extern "C" void kernel_launch(void* const* d_in, const int* in_sizes, int n_in,
                              void* d_out, int out_size)
{
    const float* x        = (const float*)d_in[0];
    const float* wq_down  = (const float*)d_in[1];
    const float* q_norm_w = (const float*)d_in[2];
    const float* wq_up    = (const float*)d_in[3];
    const float* wkv_down = (const float*)d_in[4];
    const float* kv_norm_w= (const float*)d_in[5];
    const float* wkv_up   = (const float*)d_in[6];
    const float* wo       = (const float*)d_in[7];
    float* out = (float*)d_out;

    float *down, *kvnorm, *qbuf, *kvu, *kpe;
    __nv_bfloat16 *A3, *B3;
    cudaGetSymbolAddress((void**)&down,   g_down);
    cudaGetSymbolAddress((void**)&kvnorm, g_kvnorm);
    cudaGetSymbolAddress((void**)&qbuf,   g_q);
    cudaGetSymbolAddress((void**)&kvu,    g_kvu);
    cudaGetSymbolAddress((void**)&kpe,    g_kpe);
    cudaGetSymbolAddress((void**)&A3,     g_A3);
    cudaGetSymbolAddress((void**)&B3,     g_B3);

    __nv_bfloat16* B3kv = B3 + (size_t)QL * 3 * DIM;

    // 1) splits for merged down-projection
    launch_split(x, A3, S_LEN, DIM, 0);
    launch_split(wq_down, B3, QL, DIM, 1);
    launch_split(wkv_down, B3kv, KVL + ROPE_D, DIM, 1);

    // 2) merged down-projection GEMM: [2048, 2112]
    launch_gemm3(A3, B3, down, S_LEN, NDOWN, DIM);

    // 3) norms
    rms_kernel<<<S_LEN, 256>>>(down + QL, kv_norm_w, kvnorm, KVL, NDOWN, KVL);
    rms_split_kernel<<<S_LEN, 256>>>(down, q_norm_w, A3, QL, NDOWN);

    // 4) q up-projection
    launch_split(wq_up, B3, NHEAD * QKD, QL, 1);
    launch_gemm3(A3, B3, qbuf, S_LEN, NHEAD * QKD, QL);

    // 5) kv up-projection
    launch_split(kvnorm, A3, S_LEN, KVL, 0);
    launch_split(wkv_up, B3, NHEAD * (NOPE + VH), KVL, 1);
    launch_gemm3(A3, B3, kvu, S_LEN, NHEAD * (NOPE + VH), KVL);

    // 6) rope
    rope_kernel<<<S_LEN, 544>>>(qbuf, down, kpe);

    // 7) mma flash attention (epilogue writes bf16x3 into A3)
    cudaFuncSetAttribute(attn_mma_kernel, cudaFuncAttributeMaxDynamicSharedMemorySize,
                         ATTN_SMEM);
    dim3 agrid(S_LEN / 64, NHEAD);
    attn_mma_kernel<<<agrid, 256, ATTN_SMEM>>>(qbuf, kvu, kpe, A3);

    // 8) output projection
    launch_split(wo, B3, DIM, NHEAD * VH, 1);
    launch_gemm3(A3, B3, out, S_LEN, DIM, NHEAD * VH);
}

// round 10
// speedup vs baseline: 1.9153x; 1.5401x over previous
#include <cuda_runtime.h>
#include <cuda_bf16.h>
#include <math.h>
#include <stdint.h>

// Problem constants
#define S_LEN 2048
#define DIM   2048
#define NHEAD 16
#define QL    1536
#define KVL   512
#define NOPE  128
#define ROPE_D 64
#define VH    128
#define QKD   192
#define EPS   1e-6f
#define NDOWN (QL + KVL + ROPE_D)   // 2112
#define AK (NHEAD * VH)             // 2048

// ---------------- scratch (device globals) ----------------------------------
__device__ float g_down [S_LEN * NDOWN];
__device__ float g_kvnorm[S_LEN * KVL];
__device__ float g_q    [S_LEN * NHEAD * QKD];
__device__ float g_kvu  [S_LEN * NHEAD * (NOPE + VH)];
__device__ float g_kpe  [S_LEN * ROPE_D];

__device__ __nv_bfloat16 g_A3[(size_t)S_LEN * 3 * DIM];
__device__ __nv_bfloat16 g_B3[(size_t)3072 * 3 * 1536];

// pre-split attention operands (hi|lo bf16)
__device__ __nv_bfloat16 g_Q2[(size_t)S_LEN * NHEAD * 384];   // [S][H][hi192|lo192]
__device__ __nv_bfloat16 g_K2[(size_t)NHEAD * S_LEN * 384];   // [H][S][hi192|lo192]
__device__ __nv_bfloat16 g_V2[(size_t)NHEAD * S_LEN * 256];   // [H][S][hi128|lo128]

// ---------------- fp32 -> (hi,lo) bf16 split kernels -------------------------
__global__ void split3_kernel(const float* __restrict__ src,
                              __nv_bfloat16* __restrict__ dst,
                              int K, int modeB)
{
    const int r = blockIdx.y;
    const int k = blockIdx.x * 256 + threadIdx.x;
    if (k >= K) return;
    const float v = src[(size_t)r * K + k];
    const __nv_bfloat16 h = __float2bfloat16(v);
    const __nv_bfloat16 l = __float2bfloat16(v - __bfloat162float(h));
    __nv_bfloat16* d = dst + (size_t)r * 3 * K;
    d[k] = h;
    d[K + k]     = modeB ? h : l;
    d[2 * K + k] = modeB ? l : h;
}

// ---------------- RMSNorm ----------------------------------------------------
__global__ void rms_kernel(const float* __restrict__ in, const float* __restrict__ w,
                           float* __restrict__ out, int n, int istride, int ostride)
{
    const int row = blockIdx.x;
    const float* x = in + (size_t)row * istride;

    float ss = 0.f;
    for (int i = threadIdx.x; i < n; i += blockDim.x) {
        float v = x[i];
        ss += v * v;
    }
#pragma unroll
    for (int o = 16; o; o >>= 1) ss += __shfl_xor_sync(0xffffffffu, ss, o);

    __shared__ float warpsum[8];
    __shared__ float sScale;
    const int wid = threadIdx.x >> 5;
    if ((threadIdx.x & 31) == 0) warpsum[wid] = ss;
    __syncthreads();
    if (threadIdx.x == 0) {
        float tot = 0.f;
        for (int i = 0; i < (int)(blockDim.x >> 5); i++) tot += warpsum[i];
        sScale = rsqrtf(tot / (float)n + EPS);
    }
    __syncthreads();
    const float sc = sScale;
    for (int i = threadIdx.x; i < n; i += blockDim.x)
        out[(size_t)row * ostride + i] = x[i] * sc * w[i];
}

__global__ void rms_split_kernel(const float* __restrict__ in, const float* __restrict__ w,
                                 __nv_bfloat16* __restrict__ dst, int n, int istride)
{
    const int row = blockIdx.x;
    const float* x = in + (size_t)row * istride;

    float ss = 0.f;
    for (int i = threadIdx.x; i < n; i += blockDim.x) {
        float v = x[i];
        ss += v * v;
    }
#pragma unroll
    for (int o = 16; o; o >>= 1) ss += __shfl_xor_sync(0xffffffffu, ss, o);

    __shared__ float warpsum[8];
    __shared__ float sScale;
    const int wid = threadIdx.x >> 5;
    if ((threadIdx.x & 31) == 0) warpsum[wid] = ss;
    __syncthreads();
    if (threadIdx.x == 0) {
        float tot = 0.f;
        for (int i = 0; i < (int)(blockDim.x >> 5); i++) tot += warpsum[i];
        sScale = rsqrtf(tot / (float)n + EPS);
    }
    __syncthreads();
    const float sc = sScale;
    __nv_bfloat16* d = dst + (size_t)row * 3 * n;
    for (int i = threadIdx.x; i < n; i += blockDim.x) {
        const float v = x[i] * sc * w[i];
        const __nv_bfloat16 h = __float2bfloat16(v);
        const __nv_bfloat16 l = __float2bfloat16(v - __bfloat162float(h));
        d[i] = h; d[n + i] = l; d[2 * n + i] = h;
    }
}

// ---------------- mma helpers ------------------------------------------------
__device__ __forceinline__ unsigned smem_u32(const void* p) {
    return (unsigned)__cvta_generic_to_shared(p);
}
__device__ __forceinline__ void cp16(unsigned s, const void* g, bool pred) {
    int sz = pred ? 16 : 0;
    asm volatile("cp.async.cg.shared.global [%0], [%1], 16, %2;\n"
                 :: "r"(s), "l"(g), "r"(sz));
}
__device__ __forceinline__ void ldsm_x4(uint32_t& r0, uint32_t& r1,
                                        uint32_t& r2, uint32_t& r3, unsigned addr) {
    asm volatile("ldmatrix.sync.aligned.m8n8.x4.shared.b16 {%0,%1,%2,%3}, [%4];"
                 : "=r"(r0), "=r"(r1), "=r"(r2), "=r"(r3) : "r"(addr));
}
__device__ __forceinline__ void ldsm_x4_t(uint32_t& r0, uint32_t& r1,
                                          uint32_t& r2, uint32_t& r3, unsigned addr) {
    asm volatile("ldmatrix.sync.aligned.m8n8.x4.trans.shared.b16 {%0,%1,%2,%3}, [%4];"
                 : "=r"(r0), "=r"(r1), "=r"(r2), "=r"(r3) : "r"(addr));
}
__device__ __forceinline__ void mma16816(float* c, const uint32_t* a, const uint32_t* b) {
    asm volatile(
        "mma.sync.aligned.m16n8k16.row.col.f32.bf16.bf16.f32 "
        "{%0,%1,%2,%3}, {%4,%5,%6,%7}, {%8,%9}, {%0,%1,%2,%3};"
        : "+f"(c[0]), "+f"(c[1]), "+f"(c[2]), "+f"(c[3])
        : "r"(a[0]), "r"(a[1]), "r"(a[2]), "r"(a[3]), "r"(b[0]), "r"(b[1]));
}

// ---------------- bf16x3 tensor-core GEMM (2 CTAs/SM) ------------------------
#define TBM 128
#define TBN 128
#define TBK 32
#define AP  40
#define STAGES 4
#define GEMM_SMEM (STAGES * 2 * TBM * AP * 2)

__global__ void __launch_bounds__(256, 2) gemm_bf16x3_kernel(
    const __nv_bfloat16* __restrict__ A,
    const __nv_bfloat16* __restrict__ B,
    float* __restrict__ C, int M, int N, int K3)
{
    extern __shared__ __nv_bfloat16 smem[];
    __nv_bfloat16* As = smem;
    __nv_bfloat16* Bs = smem + STAGES * TBM * AP;

    const int tid = threadIdx.x, lane = tid & 31, wid = tid >> 5;
    const int wm = wid & 1;
    const int wn = wid >> 1;
    const int row0 = blockIdx.y * TBM, col0 = blockIdx.x * TBN;

    const int c0 = tid * 2;
    const int lr = c0 >> 2;
    const int lu = c0 & 3;
    const bool aval = (row0 + lr) < M;
    const bool bval = (col0 + lr) < N;
    const __nv_bfloat16* Ag = A + (size_t)(row0 + lr) * K3 + lu * 8;
    const __nv_bfloat16* Bg = B + (size_t)(col0 + lr) * K3 + lu * 8;
    const unsigned soff = (unsigned)((lr * AP + lu * 8) * 2);

    float acc[4][4][4];
#pragma unroll
    for (int i = 0; i < 4; i++)
#pragma unroll
        for (int j = 0; j < 4; j++)
#pragma unroll
            for (int k = 0; k < 4; k++) acc[i][j][k] = 0.f;

    const int NKB = K3 / TBK;

#define ISSUE_STAGE(KB, ST) do {                                              \
        unsigned sa = smem_u32(As + (ST) * TBM * AP) + soff;                  \
        unsigned sb = smem_u32(Bs + (ST) * TBM * AP) + soff;                  \
        const __nv_bfloat16* ga = Ag + (size_t)(KB) * TBK;                    \
        const __nv_bfloat16* gb = Bg + (size_t)(KB) * TBK;                    \
        cp16(sa, ga, aval);  cp16(sa + 16, ga + 8, aval);                     \
        cp16(sb, gb, bval);  cp16(sb + 16, gb + 8, bval);                     \
        asm volatile("cp.async.commit_group;\n" ::: "memory");                \
    } while (0)

    ISSUE_STAGE(0, 0);
    ISSUE_STAGE(1, 1);
    ISSUE_STAGE(2, 2);

    const unsigned aoff = (unsigned)(((wm * 64 + (lane & 15)) * AP + (lane >> 4) * 8) * 2);
    const unsigned boff = (unsigned)(((wn * 32 + (lane >> 4) * 8 + (lane & 7)) * AP
                                      + ((lane >> 3) & 1) * 8) * 2);

    for (int kb = 0; kb < NKB; ++kb) {
        asm volatile("cp.async.wait_group 2;\n" ::: "memory");
        __syncthreads();

        if (kb + 3 < NKB) { ISSUE_STAGE(kb + 3, (kb + 3) & 3); }
        else { asm volatile("cp.async.commit_group;\n" ::: "memory"); }

        const int st = kb & 3;
        const unsigned aAddr = smem_u32(As + st * TBM * AP) + aoff;
        const unsigned bAddr = smem_u32(Bs + st * TBM * AP) + boff;

        uint32_t af[2][4][4];
        uint32_t bfr[2][4][2];
#pragma unroll
        for (int kk = 0; kk < 2; ++kk) {
#pragma unroll
            for (int mt = 0; mt < 4; ++mt)
                ldsm_x4(af[kk][mt][0], af[kk][mt][1], af[kk][mt][2], af[kk][mt][3],
                        aAddr + (unsigned)((mt * 16 * AP + kk * 16) * 2));
#pragma unroll
            for (int bp = 0; bp < 2; ++bp) {
                uint32_t r0, r1, r2, r3;
                ldsm_x4(r0, r1, r2, r3,
                        bAddr + (unsigned)((bp * 16 * AP + kk * 16) * 2));
                bfr[kk][2 * bp][0] = r0;      bfr[kk][2 * bp][1] = r1;
                bfr[kk][2 * bp + 1][0] = r2;  bfr[kk][2 * bp + 1][1] = r3;
            }
        }
#pragma unroll
        for (int kk = 0; kk < 2; ++kk)
#pragma unroll
            for (int mt = 0; mt < 4; ++mt)
#pragma unroll
                for (int nt = 0; nt < 4; ++nt)
                    mma16816(acc[mt][nt], af[kk][mt], bfr[kk][nt]);
    }

#pragma unroll
    for (int mt = 0; mt < 4; ++mt) {
#pragma unroll
        for (int nt = 0; nt < 4; ++nt) {
            const int r = row0 + wm * 64 + mt * 16 + (lane >> 2);
            const int c = col0 + wn * 32 + nt * 8 + (lane & 3) * 2;
            if (c < N) {
                if (r < M)
                    *(float2*)(C + (size_t)r * N + c) =
                        make_float2(acc[mt][nt][0], acc[mt][nt][1]);
                if (r + 8 < M)
                    *(float2*)(C + (size_t)(r + 8) * N + c) =
                        make_float2(acc[mt][nt][2], acc[mt][nt][3]);
            }
        }
    }
#undef ISSUE_STAGE
}

// ---------------- RoPE -------------------------------------------------------
__global__ void rope_kernel(float* __restrict__ q, const float* __restrict__ down,
                            float* __restrict__ kpe)
{
    const int s = blockIdx.x;
    const int tid = threadIdx.x;
    const int h = tid >> 5;
    const int i = tid & 31;
    if (h > 16) return;

    const float invf = powf(10000.f, -(float)i / 32.f);
    const float ang = (float)s * invf;
    float sn, c;
    sincosf(ang, &sn, &c);

    if (h < 16) {
        float* p = q + (size_t)s * (NHEAD * QKD) + h * QKD + NOPE + 2 * i;
        const float x0 = p[0], x1 = p[1];
        p[0] = x0 * c - x1 * sn;
        p[1] = x0 * sn + x1 * c;
    } else {
        const float* p = down + (size_t)s * NDOWN + QL + KVL + 2 * i;
        const float x0 = p[0], x1 = p[1];
        kpe[(size_t)s * ROPE_D + 2 * i]     = x0 * c - x1 * sn;
        kpe[(size_t)s * ROPE_D + 2 * i + 1] = x0 * sn + x1 * c;
    }
}

// ---------------- pre-split kernels for attention ---------------------------
__global__ void q2split_kernel(const float* __restrict__ q,     // [S][H*192] roped
                               __nv_bfloat16* __restrict__ Q2)  // [S][H][384]
{
    const int s = blockIdx.x;
    const float* row = q + (size_t)s * (NHEAD * QKD);
#pragma unroll
    for (int i = 0; i < 12; i++) {
        const int idx = threadIdx.x + 256 * i;       // 0..3071
        const int h = idx / QKD, d = idx % QKD;
        const float v = row[idx];
        const __nv_bfloat16 hi = __float2bfloat16(v);
        const __nv_bfloat16 lo = __float2bfloat16(v - __bfloat162float(hi));
        __nv_bfloat16* dst = Q2 + ((size_t)s * NHEAD + h) * 384;
        dst[d] = hi; dst[192 + d] = lo;
    }
}

__global__ void kv2split_kernel(const float* __restrict__ kvu,  // [S][H*256]
                                const float* __restrict__ kpe,  // [S][64]
                                __nv_bfloat16* __restrict__ K2, // [H][S][384]
                                __nv_bfloat16* __restrict__ V2) // [H][S][256]
{
    const int s = blockIdx.x, h = blockIdx.y, t = threadIdx.x;  // t < 320
    if (t < 192) {
        const float v = (t < 128) ? kvu[(size_t)s * (NHEAD * 256) + h * 256 + t]
                                  : kpe[(size_t)s * ROPE_D + t - 128];
        const __nv_bfloat16 hi = __float2bfloat16(v);
        const __nv_bfloat16 lo = __float2bfloat16(v - __bfloat162float(hi));
        __nv_bfloat16* dst = K2 + ((size_t)h * S_LEN + s) * 384;
        dst[t] = hi; dst[192 + t] = lo;
    } else {
        const int j = t - 192;
        const float v = kvu[(size_t)s * (NHEAD * 256) + h * 256 + 128 + j];
        const __nv_bfloat16 hi = __float2bfloat16(v);
        const __nv_bfloat16 lo = __float2bfloat16(v - __bfloat162float(hi));
        __nv_bfloat16* dst = V2 + ((size_t)h * S_LEN + s) * 256;
        dst[j] = hi; dst[128 + j] = lo;
    }
}

// ---------------- MMA flash attention v2 ------------------------------------
// grid (32, 16), block 256. 64 queries x 32-key tiles, double-buffered cp.async.
#define QPU 49            // Q/K row pitch in 16B units (48 data + 1 pad)
#define VPU 33            // V row pitch in units (32 + 1)
#define PPU 9             // P row pitch in units (8 + 1)
#define FP  36            // Pf pitch in floats
#define KBUF_B (32 * QPU * 16)    // 25088
#define VBUF_B (32 * VPU * 16)    // 16896
#define OFF_QS  0
#define OFF_KS  (64 * QPU * 16)           // 50176
#define OFF_VS  (OFF_KS + 2 * KBUF_B)     // 100352
#define OFF_PS  (OFF_VS + 2 * VBUF_B)     // 134144
#define OFF_PF  (OFF_PS + 64 * PPU * 16)  // 143360
#define OFF_AL  (OFF_PF + 64 * FP * 4)    // 152576
#define OFF_SL  (OFF_AL + 256)
#define ATTN_SMEM (OFF_SL + 256)          // 153088

__device__ __forceinline__ float fexp2(float x) {
    x = fmaxf(x, -126.f);
    const float fl = floorf(x);
    const float f = x - fl;
    float p =          1.525273380e-5f;
    p = fmaf(p, f, 1.540353039e-4f);
    p = fmaf(p, f, 1.333355815e-3f);
    p = fmaf(p, f, 9.618129107e-3f);
    p = fmaf(p, f, 5.550410866e-2f);
    p = fmaf(p, f, 2.402265070e-1f);
    p = fmaf(p, f, 6.931471806e-1f);
    p = fmaf(p, f, 1.0f);
    const int i = (int)fl;
    return __int_as_float((i + 127) << 23) * p;
}

__device__ __forceinline__ void split2(float a, float b,
                                       __nv_bfloat162& h2, __nv_bfloat162& l2) {
    __nv_bfloat16 ha = __float2bfloat16(a), hb = __float2bfloat16(b);
    h2 = __halves2bfloat162(ha, hb);
    l2 = __halves2bfloat162(__float2bfloat16(a - __bfloat162float(ha)),
                            __float2bfloat16(b - __bfloat162float(hb)));
}

__global__ void __launch_bounds__(256) attn_mma2_kernel(
    const __nv_bfloat16* __restrict__ Q2,   // [S][H][384]
    const __nv_bfloat16* __restrict__ K2,   // [H][S][384]
    const __nv_bfloat16* __restrict__ V2,   // [H][S][256]
    __nv_bfloat16* __restrict__ outA3)      // [S][3*2048] bf16x3 A-layout
{
    const int qt = (int)gridDim.x - 1 - (int)blockIdx.x;   // heavy first
    const int h  = blockIdx.y;
    extern __shared__ char sm8[];
    const unsigned sQS = smem_u32(sm8 + OFF_QS);
    const unsigned sKS = smem_u32(sm8 + OFF_KS);
    const unsigned sVS = smem_u32(sm8 + OFF_VS);
    const unsigned sPS = smem_u32(sm8 + OFF_PS);
    float* Pf     = (float*)(sm8 + OFF_PF);
    float* sAlpha = (float*)(sm8 + OFF_AL);
    float* sL     = (float*)(sm8 + OFF_SL);

    const int tid = threadIdx.x, lane = tid & 31, wid = tid >> 5;
    const int wm = wid >> 1;     // 0..3 : 16-row slab
    const int wn = wid & 1;      // 0..1
    const float SCL = 0.07216878364870323f * 1.4426950408889634f;

#define ISSUE_TILE(KT, BUF) do {                                               \
        const __nv_bfloat16* kb_ = K2 + ((size_t)h * S_LEN + (size_t)(KT) * 32) * 384; \
        const __nv_bfloat16* vb_ = V2 + ((size_t)h * S_LEN + (size_t)(KT) * 32) * 256; \
        _Pragma("unroll")                                                      \
        for (int i_ = 0; i_ < 6; i_++) {                                       \
            int c_ = tid + 256 * i_; int r_ = c_ / 48, u_ = c_ - r_ * 48;      \
            cp16(sKS + (BUF) * KBUF_B + (unsigned)((r_ * QPU + u_) * 16),      \
                 kb_ + (size_t)r_ * 384 + u_ * 8, true); }                     \
        _Pragma("unroll")                                                      \
        for (int i_ = 0; i_ < 4; i_++) {                                       \
            int c_ = tid + 256 * i_; int r_ = c_ >> 5, u_ = c_ & 31;           \
            cp16(sVS + (BUF) * VBUF_B + (unsigned)((r_ * VPU + u_) * 16),      \
                 vb_ + (size_t)r_ * 256 + u_ * 8, true); }                     \
        asm volatile("cp.async.commit_group;\n" ::: "memory");                 \
    } while (0)

    // prologue: Q + tile 0 in one group
    {
        const __nv_bfloat16* qb = Q2 + ((size_t)(qt * 64) * NHEAD + h) * 384;
#pragma unroll
        for (int i = 0; i < 12; i++) {
            int c = tid + 256 * i; int r = c / 48, u = c - r * 48;
            cp16(sQS + (unsigned)((r * QPU + u) * 16),
                 qb + (size_t)r * (NHEAD * 384) + u * 8, true);
        }
        ISSUE_TILE(0, 0);
    }

    float accO[8][4];
#pragma unroll
    for (int i = 0; i < 8; i++)
#pragma unroll
        for (int j = 0; j < 4; j++) accO[i][j] = 0.f;

    const int r_sm = tid >> 2, q_sm = tid & 3;
    const int qglob = qt * 64 + r_sm;
    float m_i = -1e30f, l_i = 0.f;

    const unsigned aQ = sQS + (unsigned)((((wm * 16 + (lane & 15)) * QPU) + (lane >> 4)) * 16);
    const unsigned bKo = (unsigned)((((wn * 16 + (lane >> 4) * 8 + (lane & 7)) * QPU)
                                     + ((lane >> 3) & 1)) * 16);
    const unsigned aP = sPS + (unsigned)((((wm * 16 + (lane & 15)) * PPU) + (lane >> 4)) * 16);

    const int nkt = 2 * (qt + 1);
    for (int kt = 0; kt < nkt; ++kt) {
        asm volatile("cp.async.wait_group 0;\n" ::: "memory");
        __syncthreads();
        const int kbuf = kt & 1;

        // ---- QK: 3 passes x 12 k16-chunks ----
        float acc[2][4] = {{0.f,0.f,0.f,0.f},{0.f,0.f,0.f,0.f}};
        const unsigned bK = sKS + (unsigned)(kbuf * KBUF_B) + bKo;
#pragma unroll
        for (int pass = 0; pass < 3; ++pass) {
            const unsigned qb = (pass == 1) ? 24u * 16u : 0u;
            const unsigned kb = (pass == 2) ? 24u * 16u : 0u;
#pragma unroll 4
            for (int c = 0; c < 12; ++c) {
                uint32_t a[4];
                ldsm_x4(a[0], a[1], a[2], a[3], aQ + qb + (unsigned)(c * 32));
                uint32_t r0, r1, r2, r3;
                ldsm_x4(r0, r1, r2, r3, bK + kb + (unsigned)(c * 32));
                uint32_t bb0[2] = {r0, r1}, bb1[2] = {r2, r3};
                mma16816(acc[0], a, bb0);
                mma16816(acc[1], a, bb1);
            }
        }
        {
            const int rr = wm * 16 + (lane >> 2);
            const int cc = wn * 16 + (lane & 3) * 2;
#pragma unroll
            for (int nt = 0; nt < 2; ++nt) {
                Pf[rr * FP + cc + nt * 8]           = acc[nt][0] * SCL;
                Pf[rr * FP + cc + nt * 8 + 1]       = acc[nt][1] * SCL;
                Pf[(rr + 8) * FP + cc + nt * 8]     = acc[nt][2] * SCL;
                Pf[(rr + 8) * FP + cc + nt * 8 + 1] = acc[nt][3] * SCL;
            }
        }
        __syncthreads();

        // ---- softmax: 4 threads/row ----
        {
            const int tg0 = kt * 32;
            float s[8];
            float lmax = -1e30f;
            const int cbase = q_sm * 8;
#pragma unroll
            for (int j = 0; j < 8; j++) {
                const int tglob = tg0 + cbase + j;
                float sv = Pf[r_sm * FP + cbase + j];
                s[j] = (tglob <= qglob) ? sv : -1e30f;
                lmax = fmaxf(lmax, s[j]);
            }
            lmax = fmaxf(lmax, __shfl_xor_sync(0xffffffffu, lmax, 1));
            lmax = fmaxf(lmax, __shfl_xor_sync(0xffffffffu, lmax, 2));
            const float m_new = fmaxf(m_i, lmax);
            const float alpha = fexp2(m_i - m_new);
            float lsum = 0.f;
            float pv[8];
#pragma unroll
            for (int j = 0; j < 8; j++) {
                pv[j] = fexp2(s[j] - m_new);
                lsum += pv[j];
            }
            // P: hi at cols 0..31, lo at 32..63 (pitch 72 bf16)
            __nv_bfloat16* pd = (__nv_bfloat16*)(sm8 + OFF_PS) + r_sm * (PPU * 8) + cbase;
#pragma unroll
            for (int j = 0; j < 8; j += 2) {
                __nv_bfloat162 h2, l2;
                split2(pv[j], pv[j + 1], h2, l2);
                *(__nv_bfloat162*)(pd + j)      = h2;
                *(__nv_bfloat162*)(pd + 32 + j) = l2;
            }
            lsum += __shfl_xor_sync(0xffffffffu, lsum, 1);
            lsum += __shfl_xor_sync(0xffffffffu, lsum, 2);
            l_i = l_i * alpha + lsum;
            m_i = m_new;
            if (q_sm == 0) { sAlpha[r_sm] = alpha; sL[r_sm] = l_i; }
        }
        __syncthreads();

        // prefetch next tile (overlaps PV below)
        if (kt + 1 < nkt) { ISSUE_TILE(kt + 1, (kt + 1) & 1); }
        else { asm volatile("cp.async.commit_group;\n" ::: "memory"); }

        // ---- PV: rescale + 3 passes x 2 chunks ----
        {
            const float al0 = sAlpha[wm * 16 + (lane >> 2)];
            const float al1 = sAlpha[wm * 16 + (lane >> 2) + 8];
#pragma unroll
            for (int nt = 0; nt < 8; ++nt) {
                accO[nt][0] *= al0; accO[nt][1] *= al0;
                accO[nt][2] *= al1; accO[nt][3] *= al1;
            }
            const unsigned vbase = sVS + (unsigned)(kbuf * VBUF_B);
#pragma unroll
            for (int pass = 0; pass < 3; ++pass) {
                const unsigned ab = (pass == 1) ? 4u * 16u : 0u;
                const unsigned vb = (pass == 2) ? 16u : 0u;   // col-unit base (Vlo)
#pragma unroll
                for (int c = 0; c < 2; ++c) {
                    uint32_t a[4];
                    ldsm_x4(a[0], a[1], a[2], a[3], aP + ab + (unsigned)(c * 32));
                    const unsigned bvrow = vbase
                        + (unsigned)((((c * 16 + (lane & 15)) * VPU) + (lane >> 4)) * 16);
#pragma unroll
                    for (int j = 0; j < 4; ++j) {
                        uint32_t r0, r1, r2, r3;
                        ldsm_x4_t(r0, r1, r2, r3,
                                  bvrow + (unsigned)((vb + wn * 8 + 2 * j) * 16));
                        uint32_t bb0[2] = {r0, r1}, bb1[2] = {r2, r3};
                        mma16816(accO[2 * j],     a, bb0);
                        mma16816(accO[2 * j + 1], a, bb1);
                    }
                }
            }
        }
    }

    __syncthreads();
    // ---- epilogue: /l, write bf16x3 A layout ----
    {
        const int rr = wm * 16 + (lane >> 2);
        const float il0 = 1.f / sL[rr];
        const float il1 = 1.f / sL[rr + 8];
        const int row0 = qt * 64 + rr;
        __nv_bfloat16* d0 = outA3 + (size_t)row0 * 3 * AK;
        __nv_bfloat16* d1 = outA3 + (size_t)(row0 + 8) * 3 * AK;
#pragma unroll
        for (int nt = 0; nt < 8; ++nt) {
            const int col = h * VH + wn * 64 + nt * 8 + (lane & 3) * 2;
            __nv_bfloat162 h2, l2;
            split2(accO[nt][0] * il0, accO[nt][1] * il0, h2, l2);
            *(__nv_bfloat162*)(d0 + col)          = h2;
            *(__nv_bfloat162*)(d0 + AK + col)     = l2;
            *(__nv_bfloat162*)(d0 + 2 * AK + col) = h2;
            split2(accO[nt][2] * il1, accO[nt][3] * il1, h2, l2);
            *(__nv_bfloat162*)(d1 + col)          = h2;
            *(__nv_bfloat162*)(d1 + AK + col)     = l2;
            *(__nv_bfloat162*)(d1 + 2 * AK + col) = h2;
        }
    }
#undef ISSUE_TILE
}

// ---------------- host orchestration ----------------------------------------
static inline void launch_split(const float* src, __nv_bfloat16* dst,
                                int rows, int K, int modeB)
{
    dim3 grid((K + 255) / 256, rows);
    split3_kernel<<<grid, 256>>>(src, dst, K, modeB);
}

static inline void launch_gemm3(const __nv_bfloat16* A3, const __nv_bfloat16* B3,
                                float* C, int M, int N, int K)
{
    cudaFuncSetAttribute(gemm_bf16x3_kernel,
                         cudaFuncAttributeMaxDynamicSharedMemorySize, GEMM_SMEM);
    dim3 grid((N + TBN - 1) / TBN, (M + TBM - 1) / TBM);
    gemm_bf16x3_kernel<<<grid, 256, GEMM_SMEM>>>(A3, B3, C, M, N, 3 * K);
}

extern "C" void kernel_launch(void* const* d_in, const int* in_sizes, int n_in,
                              void* d_out, int out_size)
{
    const float* x        = (const float*)d_in[0];
    const float* wq_down  = (const float*)d_in[1];
    const float* q_norm_w = (const float*)d_in[2];
    const float* wq_up    = (const float*)d_in[3];
    const float* wkv_down = (const float*)d_in[4];
    const float* kv_norm_w= (const float*)d_in[5];
    const float* wkv_up   = (const float*)d_in[6];
    const float* wo       = (const float*)d_in[7];
    float* out = (float*)d_out;

    float *down, *kvnorm, *qbuf, *kvu, *kpe;
    __nv_bfloat16 *A3, *B3, *Q2, *K2, *V2;
    cudaGetSymbolAddress((void**)&down,   g_down);
    cudaGetSymbolAddress((void**)&kvnorm, g_kvnorm);
    cudaGetSymbolAddress((void**)&qbuf,   g_q);
    cudaGetSymbolAddress((void**)&kvu,    g_kvu);
    cudaGetSymbolAddress((void**)&kpe,    g_kpe);
    cudaGetSymbolAddress((void**)&A3,     g_A3);
    cudaGetSymbolAddress((void**)&B3,     g_B3);
    cudaGetSymbolAddress((void**)&Q2,     g_Q2);
    cudaGetSymbolAddress((void**)&K2,     g_K2);
    cudaGetSymbolAddress((void**)&V2,     g_V2);

    __nv_bfloat16* B3kv = B3 + (size_t)QL * 3 * DIM;

    // 1) splits + merged down-projection
    launch_split(x, A3, S_LEN, DIM, 0);
    launch_split(wq_down, B3, QL, DIM, 1);
    launch_split(wkv_down, B3kv, KVL + ROPE_D, DIM, 1);
    launch_gemm3(A3, B3, down, S_LEN, NDOWN, DIM);

    // 2) norms
    rms_kernel<<<S_LEN, 256>>>(down + QL, kv_norm_w, kvnorm, KVL, NDOWN, KVL);
    rms_split_kernel<<<S_LEN, 256>>>(down, q_norm_w, A3, QL, NDOWN);

    // 3) q up-projection
    launch_split(wq_up, B3, NHEAD * QKD, QL, 1);
    launch_gemm3(A3, B3, qbuf, S_LEN, NHEAD * QKD, QL);

    // 4) kv up-projection
    launch_split(kvnorm, A3, S_LEN, KVL, 0);
    launch_split(wkv_up, B3, NHEAD * (NOPE + VH), KVL, 1);
    launch_gemm3(A3, B3, kvu, S_LEN, NHEAD * (NOPE + VH), KVL);

    // 5) rope, then pre-split attention operands
    rope_kernel<<<S_LEN, 544>>>(qbuf, down, kpe);
    q2split_kernel<<<S_LEN, 256>>>(qbuf, Q2);
    {
        dim3 g(S_LEN, NHEAD);
        kv2split_kernel<<<g, 320>>>(kvu, kpe, K2, V2);
    }

    // 6) mma flash attention v2 (epilogue writes bf16x3 into A3)
    cudaFuncSetAttribute(attn_mma2_kernel, cudaFuncAttributeMaxDynamicSharedMemorySize,
                         ATTN_SMEM);
    dim3 agrid(S_LEN / 64, NHEAD);
    attn_mma2_kernel<<<agrid, 256, ATTN_SMEM>>>(Q2, K2, V2, A3);

    // 7) output projection
    launch_split(wo, B3, DIM, NHEAD * VH, 1);
    launch_gemm3(A3, B3, out, S_LEN, DIM, NHEAD * VH);
}

// round 12
// speedup vs baseline: 1.9543x; 1.0204x over previous
#include <cuda_runtime.h>
#include <cuda_bf16.h>
#include <math.h>
#include <stdint.h>

// Problem constants
#define S_LEN 2048
#define DIM   2048
#define NHEAD 16
#define KVL   512
#define QL    1536
#define NOPE  128
#define ROPE_D 64
#define VH    128
#define QKD   192
#define EPS   1e-6f
#define NDOWN (QL + KVL + ROPE_D)   // 2112
#define AK (NHEAD * VH)             // 2048

// ---------------- scratch (device globals) ----------------------------------
__device__ float g_down [S_LEN * NDOWN];
__device__ float g_kvnorm[S_LEN * KVL];
__device__ float g_qpe  [S_LEN * NHEAD * QKD];   // only pe cols used (stride 3072)

__device__ __nv_bfloat16 g_A3[(size_t)S_LEN * 3 * DIM];
__device__ __nv_bfloat16 g_B3[(size_t)3072 * 3 * 1536];

// pre-split attention operands (hi|lo bf16)
__device__ __nv_bfloat16 g_Q2[(size_t)S_LEN * NHEAD * 384];
__device__ __nv_bfloat16 g_K2[(size_t)NHEAD * S_LEN * 384];
__device__ __nv_bfloat16 g_V2[(size_t)NHEAD * S_LEN * 256];

// ---------------- small helpers ---------------------------------------------
__device__ __forceinline__ void split2(float a, float b,
                                       __nv_bfloat162& h2, __nv_bfloat162& l2) {
    __nv_bfloat16 ha = __float2bfloat16(a), hb = __float2bfloat16(b);
    h2 = __halves2bfloat162(ha, hb);
    l2 = __halves2bfloat162(__float2bfloat16(a - __bfloat162float(ha)),
                            __float2bfloat16(b - __bfloat162float(hb)));
}
__device__ __forceinline__ unsigned smem_u32(const void* p) {
    return (unsigned)__cvta_generic_to_shared(p);
}
__device__ __forceinline__ void cp16(unsigned s, const void* g, bool pred) {
    int sz = pred ? 16 : 0;
    asm volatile("cp.async.cg.shared.global [%0], [%1], 16, %2;\n"
                 :: "r"(s), "l"(g), "r"(sz));
}
__device__ __forceinline__ void ldsm_x4(uint32_t& r0, uint32_t& r1,
                                        uint32_t& r2, uint32_t& r3, unsigned addr) {
    asm volatile("ldmatrix.sync.aligned.m8n8.x4.shared.b16 {%0,%1,%2,%3}, [%4];"
                 : "=r"(r0), "=r"(r1), "=r"(r2), "=r"(r3) : "r"(addr));
}
__device__ __forceinline__ void ldsm_x4_t(uint32_t& r0, uint32_t& r1,
                                          uint32_t& r2, uint32_t& r3, unsigned addr) {
    asm volatile("ldmatrix.sync.aligned.m8n8.x4.trans.shared.b16 {%0,%1,%2,%3}, [%4];"
                 : "=r"(r0), "=r"(r1), "=r"(r2), "=r"(r3) : "r"(addr));
}
__device__ __forceinline__ void mma16816(float* c, const uint32_t* a, const uint32_t* b) {
    asm volatile(
        "mma.sync.aligned.m16n8k16.row.col.f32.bf16.bf16.f32 "
        "{%0,%1,%2,%3}, {%4,%5,%6,%7}, {%8,%9}, {%0,%1,%2,%3};"
        : "+f"(c[0]), "+f"(c[1]), "+f"(c[2]), "+f"(c[3])
        : "r"(a[0]), "r"(a[1]), "r"(a[2]), "r"(a[3]), "r"(b[0]), "r"(b[1]));
}

// ---------------- fp32 -> (hi,lo) bf16 split kernel --------------------------
__global__ void split3_kernel(const float* __restrict__ src,
                              __nv_bfloat16* __restrict__ dst,
                              int K, int modeB)
{
    const int r = blockIdx.y;
    const int k = blockIdx.x * 256 + threadIdx.x;
    if (k >= K) return;
    const float v = src[(size_t)r * K + k];
    const __nv_bfloat16 h = __float2bfloat16(v);
    const __nv_bfloat16 l = __float2bfloat16(v - __bfloat162float(h));
    __nv_bfloat16* d = dst + (size_t)r * 3 * K;
    d[k] = h;
    d[K + k]     = modeB ? h : l;
    d[2 * K + k] = modeB ? l : h;
}

// ---------------- RMSNorm ----------------------------------------------------
__global__ void rms_kernel(const float* __restrict__ in, const float* __restrict__ w,
                           float* __restrict__ out, int n, int istride, int ostride)
{
    const int row = blockIdx.x;
    const float* x = in + (size_t)row * istride;

    float ss = 0.f;
    for (int i = threadIdx.x; i < n; i += blockDim.x) {
        float v = x[i];
        ss += v * v;
    }
#pragma unroll
    for (int o = 16; o; o >>= 1) ss += __shfl_xor_sync(0xffffffffu, ss, o);

    __shared__ float warpsum[8];
    __shared__ float sScale;
    const int wid = threadIdx.x >> 5;
    if ((threadIdx.x & 31) == 0) warpsum[wid] = ss;
    __syncthreads();
    if (threadIdx.x == 0) {
        float tot = 0.f;
        for (int i = 0; i < (int)(blockDim.x >> 5); i++) tot += warpsum[i];
        sScale = rsqrtf(tot / (float)n + EPS);
    }
    __syncthreads();
    const float sc = sScale;
    for (int i = threadIdx.x; i < n; i += blockDim.x)
        out[(size_t)row * ostride + i] = x[i] * sc * w[i];
}

__global__ void rms_split_kernel(const float* __restrict__ in, const float* __restrict__ w,
                                 __nv_bfloat16* __restrict__ dst, int n, int istride)
{
    const int row = blockIdx.x;
    const float* x = in + (size_t)row * istride;

    float ss = 0.f;
    for (int i = threadIdx.x; i < n; i += blockDim.x) {
        float v = x[i];
        ss += v * v;
    }
#pragma unroll
    for (int o = 16; o; o >>= 1) ss += __shfl_xor_sync(0xffffffffu, ss, o);

    __shared__ float warpsum[8];
    __shared__ float sScale;
    const int wid = threadIdx.x >> 5;
    if ((threadIdx.x & 31) == 0) warpsum[wid] = ss;
    __syncthreads();
    if (threadIdx.x == 0) {
        float tot = 0.f;
        for (int i = 0; i < (int)(blockDim.x >> 5); i++) tot += warpsum[i];
        sScale = rsqrtf(tot / (float)n + EPS);
    }
    __syncthreads();
    const float sc = sScale;
    __nv_bfloat16* d = dst + (size_t)row * 3 * n;
    for (int i = threadIdx.x; i < n; i += blockDim.x) {
        const float v = x[i] * sc * w[i];
        const __nv_bfloat16 h = __float2bfloat16(v);
        const __nv_bfloat16 l = __float2bfloat16(v - __bfloat162float(h));
        d[i] = h; d[n + i] = l; d[2 * n + i] = h;
    }
}

// ---------------- bf16x3 tensor-core GEMM (fused epilogues) -----------------
// mode 0: C fp32 [M,N]
// mode 1 (q up, N=3072): cols h*192+d ; d<128 -> Q2 hi/lo ; d>=128 -> qpe fp32
// mode 2 (kv up, N=4096): cols h*256+j ; j<128 -> K2 hi/lo ; j>=128 -> V2 hi/lo
#define TBM 128
#define TBN 128
#define TBK 32
#define AP  40
#define STAGES 4
#define GEMM_SMEM (STAGES * 2 * TBM * AP * 2)

__device__ __forceinline__ void fused_store(
    int mode, float v0, float v1, int r, int c,
    float* __restrict__ C, int N,
    __nv_bfloat16* __restrict__ Q2, __nv_bfloat16* __restrict__ K2,
    __nv_bfloat16* __restrict__ V2, float* __restrict__ qpe)
{
    if (mode == 0) {
        *(float2*)(C + (size_t)r * N + c) = make_float2(v0, v1);
        return;
    }
    if (mode == 1) {
        const int h = c / QKD, d = c - h * QKD;
        if (d < NOPE) {
            __nv_bfloat162 h2, l2; split2(v0, v1, h2, l2);
            __nv_bfloat16* dst = Q2 + ((size_t)r * NHEAD + h) * 384 + d;
            *(__nv_bfloat162*)dst = h2;
            *(__nv_bfloat162*)(dst + 192) = l2;
        } else {
            *(float2*)(qpe + (size_t)r * 3072 + c) = make_float2(v0, v1);
        }
    } else {
        const int h = c >> 8, j = c & 255;
        __nv_bfloat162 h2, l2; split2(v0, v1, h2, l2);
        if (j < 128) {
            __nv_bfloat16* dst = K2 + ((size_t)h * S_LEN + r) * 384 + j;
            *(__nv_bfloat162*)dst = h2;
            *(__nv_bfloat162*)(dst + 192) = l2;
        } else {
            __nv_bfloat16* dst = V2 + ((size_t)h * S_LEN + r) * 256 + (j - 128);
            *(__nv_bfloat162*)dst = h2;
            *(__nv_bfloat162*)(dst + 128) = l2;
        }
    }
}

__global__ void __launch_bounds__(256, 2) gemm_bf16x3_kernel(
    const __nv_bfloat16* __restrict__ A,
    const __nv_bfloat16* __restrict__ B,
    float* __restrict__ C, int M, int N, int K3, int mode,
    __nv_bfloat16* __restrict__ Q2, __nv_bfloat16* __restrict__ K2,
    __nv_bfloat16* __restrict__ V2, float* __restrict__ qpe)
{
    extern __shared__ __nv_bfloat16 smem[];
    __nv_bfloat16* As = smem;
    __nv_bfloat16* Bs = smem + STAGES * TBM * AP;

    const int tid = threadIdx.x, lane = tid & 31, wid = tid >> 5;
    const int wm = wid & 1;
    const int wn = wid >> 1;
    const int row0 = blockIdx.y * TBM, col0 = blockIdx.x * TBN;

    const int c0 = tid * 2;
    const int lr = c0 >> 2;
    const int lu = c0 & 3;
    const bool aval = (row0 + lr) < M;
    const bool bval = (col0 + lr) < N;
    const __nv_bfloat16* Ag = A + (size_t)(row0 + lr) * K3 + lu * 8;
    const __nv_bfloat16* Bg = B + (size_t)(col0 + lr) * K3 + lu * 8;
    const unsigned soff = (unsigned)((lr * AP + lu * 8) * 2);

    float acc[4][4][4];
#pragma unroll
    for (int i = 0; i < 4; i++)
#pragma unroll
        for (int j = 0; j < 4; j++)
#pragma unroll
            for (int k = 0; k < 4; k++) acc[i][j][k] = 0.f;

    const int NKB = K3 / TBK;

#define ISSUE_STAGE(KB, ST) do {                                              \
        unsigned sa = smem_u32(As + (ST) * TBM * AP) + soff;                  \
        unsigned sb = smem_u32(Bs + (ST) * TBM * AP) + soff;                  \
        const __nv_bfloat16* ga = Ag + (size_t)(KB) * TBK;                    \
        const __nv_bfloat16* gb = Bg + (size_t)(KB) * TBK;                    \
        cp16(sa, ga, aval);  cp16(sa + 16, ga + 8, aval);                     \
        cp16(sb, gb, bval);  cp16(sb + 16, gb + 8, bval);                     \
        asm volatile("cp.async.commit_group;\n" ::: "memory");                \
    } while (0)

    ISSUE_STAGE(0, 0);
    ISSUE_STAGE(1, 1);
    ISSUE_STAGE(2, 2);

    const unsigned aoff = (unsigned)(((wm * 64 + (lane & 15)) * AP + (lane >> 4) * 8) * 2);
    const unsigned boff = (unsigned)(((wn * 32 + (lane >> 4) * 8 + (lane & 7)) * AP
                                      + ((lane >> 3) & 1) * 8) * 2);

    for (int kb = 0; kb < NKB; ++kb) {
        asm volatile("cp.async.wait_group 2;\n" ::: "memory");
        __syncthreads();

        if (kb + 3 < NKB) { ISSUE_STAGE(kb + 3, (kb + 3) & 3); }
        else { asm volatile("cp.async.commit_group;\n" ::: "memory"); }

        const int st = kb & 3;
        const unsigned aAddr = smem_u32(As + st * TBM * AP) + aoff;
        const unsigned bAddr = smem_u32(Bs + st * TBM * AP) + boff;

        uint32_t af[2][4][4];
        uint32_t bfr[2][4][2];
#pragma unroll
        for (int kk = 0; kk < 2; ++kk) {
#pragma unroll
            for (int mt = 0; mt < 4; ++mt)
                ldsm_x4(af[kk][mt][0], af[kk][mt][1], af[kk][mt][2], af[kk][mt][3],
                        aAddr + (unsigned)((mt * 16 * AP + kk * 16) * 2));
#pragma unroll
            for (int bp = 0; bp < 2; ++bp) {
                uint32_t r0, r1, r2, r3;
                ldsm_x4(r0, r1, r2, r3,
                        bAddr + (unsigned)((bp * 16 * AP + kk * 16) * 2));
                bfr[kk][2 * bp][0] = r0;      bfr[kk][2 * bp][1] = r1;
                bfr[kk][2 * bp + 1][0] = r2;  bfr[kk][2 * bp + 1][1] = r3;
            }
        }
#pragma unroll
        for (int kk = 0; kk < 2; ++kk)
#pragma unroll
            for (int mt = 0; mt < 4; ++mt)
#pragma unroll
                for (int nt = 0; nt < 4; ++nt)
                    mma16816(acc[mt][nt], af[kk][mt], bfr[kk][nt]);
    }

#pragma unroll
    for (int mt = 0; mt < 4; ++mt) {
#pragma unroll
        for (int nt = 0; nt < 4; ++nt) {
            const int r = row0 + wm * 64 + mt * 16 + (lane >> 2);
            const int c = col0 + wn * 32 + nt * 8 + (lane & 3) * 2;
            if (c < N) {
                if (r < M)
                    fused_store(mode, acc[mt][nt][0], acc[mt][nt][1], r, c,
                                C, N, Q2, K2, V2, qpe);
                if (r + 8 < M)
                    fused_store(mode, acc[mt][nt][2], acc[mt][nt][3], r + 8, c,
                                C, N, Q2, K2, V2, qpe);
            }
        }
    }
#undef ISSUE_STAGE
}

// ---------------- RoPE: writes roped pe dims into Q2 and K2 ------------------
__global__ void rope_kernel(const float* __restrict__ qpe, const float* __restrict__ down,
                            __nv_bfloat16* __restrict__ Q2, __nv_bfloat16* __restrict__ K2)
{
    const int s = blockIdx.x;
    const int tid = threadIdx.x;     // 544 threads
    const int h = tid >> 5;          // 0..16
    const int i = tid & 31;
    if (h > 16) return;

    const float invf = powf(10000.f, -(float)i / 32.f);
    const float ang = (float)s * invf;
    float sn, c;
    sincosf(ang, &sn, &c);

    if (h < 16) {
        const float* p = qpe + (size_t)s * 3072 + h * QKD + NOPE + 2 * i;
        const float x0 = p[0], x1 = p[1];
        __nv_bfloat162 h2, l2;
        split2(x0 * c - x1 * sn, x0 * sn + x1 * c, h2, l2);
        __nv_bfloat16* dst = Q2 + ((size_t)s * NHEAD + h) * 384 + NOPE + 2 * i;
        *(__nv_bfloat162*)dst = h2;
        *(__nv_bfloat162*)(dst + 192) = l2;
    } else {
        const float* p = down + (size_t)s * NDOWN + QL + KVL + 2 * i;
        const float x0 = p[0], x1 = p[1];
        __nv_bfloat162 h2, l2;
        split2(x0 * c - x1 * sn, x0 * sn + x1 * c, h2, l2);
#pragma unroll
        for (int hh = 0; hh < NHEAD; hh++) {
            __nv_bfloat16* dst = K2 + ((size_t)hh * S_LEN + s) * 384 + NOPE + 2 * i;
            *(__nv_bfloat162*)dst = h2;
            *(__nv_bfloat162*)(dst + 192) = l2;
        }
    }
}

// ---------------- MMA flash attention v2 ------------------------------------
#define QPU 49
#define VPU 33
#define PPU 9
#define FP  36
#define KBUF_B (32 * QPU * 16)
#define VBUF_B (32 * VPU * 16)
#define OFF_QS  0
#define OFF_KS  (64 * QPU * 16)
#define OFF_VS  (OFF_KS + 2 * KBUF_B)
#define OFF_PS  (OFF_VS + 2 * VBUF_B)
#define OFF_PF  (OFF_PS + 64 * PPU * 16)
#define OFF_AL  (OFF_PF + 64 * FP * 4)
#define OFF_SL  (OFF_AL + 256)
#define ATTN_SMEM (OFF_SL + 256)

__device__ __forceinline__ float fexp2(float x) {
    x = fmaxf(x, -126.f);
    const float fl = floorf(x);
    const float f = x - fl;
    float p =          1.525273380e-5f;
    p = fmaf(p, f, 1.540353039e-4f);
    p = fmaf(p, f, 1.333355815e-3f);
    p = fmaf(p, f, 9.618129107e-3f);
    p = fmaf(p, f, 5.550410866e-2f);
    p = fmaf(p, f, 2.402265070e-1f);
    p = fmaf(p, f, 6.931471806e-1f);
    p = fmaf(p, f, 1.0f);
    const int i = (int)fl;
    return __int_as_float((i + 127) << 23) * p;
}

__global__ void __launch_bounds__(256) attn_mma2_kernel(
    const __nv_bfloat16* __restrict__ Q2,
    const __nv_bfloat16* __restrict__ K2,
    const __nv_bfloat16* __restrict__ V2,
    __nv_bfloat16* __restrict__ outA3)
{
    const int qt = (int)gridDim.x - 1 - (int)blockIdx.x;
    const int h  = blockIdx.y;
    extern __shared__ char sm8[];
    const unsigned sQS = smem_u32(sm8 + OFF_QS);
    const unsigned sKS = smem_u32(sm8 + OFF_KS);
    const unsigned sVS = smem_u32(sm8 + OFF_VS);
    const unsigned sPS = smem_u32(sm8 + OFF_PS);
    float* Pf     = (float*)(sm8 + OFF_PF);
    float* sAlpha = (float*)(sm8 + OFF_AL);
    float* sL     = (float*)(sm8 + OFF_SL);

    const int tid = threadIdx.x, lane = tid & 31, wid = tid >> 5;
    const int wm = wid >> 1;
    const int wn = wid & 1;
    const float SCL = 0.07216878364870323f * 1.4426950408889634f;

#define ISSUE_TILE(KT, BUF) do {                                               \
        const __nv_bfloat16* kb_ = K2 + ((size_t)h * S_LEN + (size_t)(KT) * 32) * 384; \
        const __nv_bfloat16* vb_ = V2 + ((size_t)h * S_LEN + (size_t)(KT) * 32) * 256; \
        _Pragma("unroll")                                                      \
        for (int i_ = 0; i_ < 6; i_++) {                                       \
            int c_ = tid + 256 * i_; int r_ = c_ / 48, u_ = c_ - r_ * 48;      \
            cp16(sKS + (BUF) * KBUF_B + (unsigned)((r_ * QPU + u_) * 16),      \
                 kb_ + (size_t)r_ * 384 + u_ * 8, true); }                     \
        _Pragma("unroll")                                                      \
        for (int i_ = 0; i_ < 4; i_++) {                                       \
            int c_ = tid + 256 * i_; int r_ = c_ >> 5, u_ = c_ & 31;           \
            cp16(sVS + (BUF) * VBUF_B + (unsigned)((r_ * VPU + u_) * 16),      \
                 vb_ + (size_t)r_ * 256 + u_ * 8, true); }                     \
        asm volatile("cp.async.commit_group;\n" ::: "memory");                 \
    } while (0)

    {
        const __nv_bfloat16* qb = Q2 + ((size_t)(qt * 64) * NHEAD + h) * 384;
#pragma unroll
        for (int i = 0; i < 12; i++) {
            int c = tid + 256 * i; int r = c / 48, u = c - r * 48;
            cp16(sQS + (unsigned)((r * QPU + u) * 16),
                 qb + (size_t)r * (NHEAD * 384) + u * 8, true);
        }
        ISSUE_TILE(0, 0);
    }

    float accO[8][4];
#pragma unroll
    for (int i = 0; i < 8; i++)
#pragma unroll
        for (int j = 0; j < 4; j++) accO[i][j] = 0.f;

    const int r_sm = tid >> 2, q_sm = tid & 3;
    const int qglob = qt * 64 + r_sm;
    float m_i = -1e30f, l_i = 0.f;

    const unsigned aQ = sQS + (unsigned)((((wm * 16 + (lane & 15)) * QPU) + (lane >> 4)) * 16);
    const unsigned bKo = (unsigned)((((wn * 16 + (lane >> 4) * 8 + (lane & 7)) * QPU)
                                     + ((lane >> 3) & 1)) * 16);
    const unsigned aP = sPS + (unsigned)((((wm * 16 + (lane & 15)) * PPU) + (lane >> 4)) * 16);

    const int nkt = 2 * (qt + 1);
    for (int kt = 0; kt < nkt; ++kt) {
        asm volatile("cp.async.wait_group 0;\n" ::: "memory");
        __syncthreads();
        const int kbuf = kt & 1;

        float acc[2][4] = {{0.f,0.f,0.f,0.f},{0.f,0.f,0.f,0.f}};
        const unsigned bK = sKS + (unsigned)(kbuf * KBUF_B) + bKo;
#pragma unroll
        for (int pass = 0; pass < 3; ++pass) {
            const unsigned qb = (pass == 1) ? 24u * 16u : 0u;
            const unsigned kb = (pass == 2) ? 24u * 16u : 0u;
#pragma unroll 4
            for (int c = 0; c < 12; ++c) {
                uint32_t a[4];
                ldsm_x4(a[0], a[1], a[2], a[3], aQ + qb + (unsigned)(c * 32));
                uint32_t r0, r1, r2, r3;
                ldsm_x4(r0, r1, r2, r3, bK + kb + (unsigned)(c * 32));
                uint32_t bb0[2] = {r0, r1}, bb1[2] = {r2, r3};
                mma16816(acc[0], a, bb0);
                mma16816(acc[1], a, bb1);
            }
        }
        {
            const int rr = wm * 16 + (lane >> 2);
            const int cc = wn * 16 + (lane & 3) * 2;
#pragma unroll
            for (int nt = 0; nt < 2; ++nt) {
                Pf[rr * FP + cc + nt * 8]           = acc[nt][0] * SCL;
                Pf[rr * FP + cc + nt * 8 + 1]       = acc[nt][1] * SCL;
                Pf[(rr + 8) * FP + cc + nt * 8]     = acc[nt][2] * SCL;
                Pf[(rr + 8) * FP + cc + nt * 8 + 1] = acc[nt][3] * SCL;
            }
        }
        __syncthreads();

        {
            const int tg0 = kt * 32;
            float s[8];
            float lmax = -1e30f;
            const int cbase = q_sm * 8;
#pragma unroll
            for (int j = 0; j < 8; j++) {
                const int tglob = tg0 + cbase + j;
                float sv = Pf[r_sm * FP + cbase + j];
                s[j] = (tglob <= qglob) ? sv : -1e30f;
                lmax = fmaxf(lmax, s[j]);
            }
            lmax = fmaxf(lmax, __shfl_xor_sync(0xffffffffu, lmax, 1));
            lmax = fmaxf(lmax, __shfl_xor_sync(0xffffffffu, lmax, 2));
            const float m_new = fmaxf(m_i, lmax);
            const float alpha = fexp2(m_i - m_new);
            float lsum = 0.f;
            float pv[8];
#pragma unroll
            for (int j = 0; j < 8; j++) {
                pv[j] = fexp2(s[j] - m_new);
                lsum += pv[j];
            }
            __nv_bfloat16* pd = (__nv_bfloat16*)(sm8 + OFF_PS) + r_sm * (PPU * 8) + cbase;
#pragma unroll
            for (int j = 0; j < 8; j += 2) {
                __nv_bfloat162 h2, l2;
                split2(pv[j], pv[j + 1], h2, l2);
                *(__nv_bfloat162*)(pd + j)      = h2;
                *(__nv_bfloat162*)(pd + 32 + j) = l2;
            }
            lsum += __shfl_xor_sync(0xffffffffu, lsum, 1);
            lsum += __shfl_xor_sync(0xffffffffu, lsum, 2);
            l_i = l_i * alpha + lsum;
            m_i = m_new;
            if (q_sm == 0) { sAlpha[r_sm] = alpha; sL[r_sm] = l_i; }
        }
        __syncthreads();

        if (kt + 1 < nkt) { ISSUE_TILE(kt + 1, (kt + 1) & 1); }
        else { asm volatile("cp.async.commit_group;\n" ::: "memory"); }

        {
            const float al0 = sAlpha[wm * 16 + (lane >> 2)];
            const float al1 = sAlpha[wm * 16 + (lane >> 2) + 8];
#pragma unroll
            for (int nt = 0; nt < 8; ++nt) {
                accO[nt][0] *= al0; accO[nt][1] *= al0;
                accO[nt][2] *= al1; accO[nt][3] *= al1;
            }
            const unsigned vbase = sVS + (unsigned)(kbuf * VBUF_B);
#pragma unroll
            for (int pass = 0; pass < 3; ++pass) {
                const unsigned ab = (pass == 1) ? 4u * 16u : 0u;
                const unsigned vb = (pass == 2) ? 16u : 0u;
#pragma unroll
                for (int c = 0; c < 2; ++c) {
                    uint32_t a[4];
                    ldsm_x4(a[0], a[1], a[2], a[3], aP + ab + (unsigned)(c * 32));
                    const unsigned bvrow = vbase
                        + (unsigned)((((c * 16 + (lane & 15)) * VPU) + (lane >> 4)) * 16);
#pragma unroll
                    for (int j = 0; j < 4; ++j) {
                        uint32_t r0, r1, r2, r3;
                        ldsm_x4_t(r0, r1, r2, r3,
                                  bvrow + (unsigned)((vb + wn * 8 + 2 * j) * 16));
                        uint32_t bb0[2] = {r0, r1}, bb1[2] = {r2, r3};
                        mma16816(accO[2 * j],     a, bb0);
                        mma16816(accO[2 * j + 1], a, bb1);
                    }
                }
            }
        }
    }

    __syncthreads();
    {
        const int rr = wm * 16 + (lane >> 2);
        const float il0 = 1.f / sL[rr];
        const float il1 = 1.f / sL[rr + 8];
        const int row0 = qt * 64 + rr;
        __nv_bfloat16* d0 = outA3 + (size_t)row0 * 3 * AK;
        __nv_bfloat16* d1 = outA3 + (size_t)(row0 + 8) * 3 * AK;
#pragma unroll
        for (int nt = 0; nt < 8; ++nt) {
            const int col = h * VH + wn * 64 + nt * 8 + (lane & 3) * 2;
            __nv_bfloat162 h2, l2;
            split2(accO[nt][0] * il0, accO[nt][1] * il0, h2, l2);
            *(__nv_bfloat162*)(d0 + col)          = h2;
            *(__nv_bfloat162*)(d0 + AK + col)     = l2;
            *(__nv_bfloat162*)(d0 + 2 * AK + col) = h2;
            split2(accO[nt][2] * il1, accO[nt][3] * il1, h2, l2);
            *(__nv_bfloat162*)(d1 + col)          = h2;
            *(__nv_bfloat162*)(d1 + AK + col)     = l2;
            *(__nv_bfloat162*)(d1 + 2 * AK + col) = h2;
        }
    }
#undef ISSUE_TILE
}

// ---------------- host orchestration ----------------------------------------
static inline void launch_split(const float* src, __nv_bfloat16* dst,
                                int rows, int K, int modeB)
{
    dim3 grid((K + 255) / 256, rows);
    split3_kernel<<<grid, 256>>>(src, dst, K, modeB);
}

static inline void launch_gemm3(const __nv_bfloat16* A3, const __nv_bfloat16* B3,
                                float* C, int M, int N, int K, int mode,
                                __nv_bfloat16* Q2, __nv_bfloat16* K2,
                                __nv_bfloat16* V2, float* qpe)
{
    cudaFuncSetAttribute(gemm_bf16x3_kernel,
                         cudaFuncAttributeMaxDynamicSharedMemorySize, GEMM_SMEM);
    dim3 grid((N + TBN - 1) / TBN, (M + TBM - 1) / TBM);
    gemm_bf16x3_kernel<<<grid, 256, GEMM_SMEM>>>(A3, B3, C, M, N, 3 * K, mode,
                                                 Q2, K2, V2, qpe);
}

extern "C" void kernel_launch(void* const* d_in, const int* in_sizes, int n_in,
                              void* d_out, int out_size)
{
    const float* x        = (const float*)d_in[0];
    const float* wq_down  = (const float*)d_in[1];
    const float* q_norm_w = (const float*)d_in[2];
    const float* wq_up    = (const float*)d_in[3];
    const float* wkv_down = (const float*)d_in[4];
    const float* kv_norm_w= (const float*)d_in[5];
    const float* wkv_up   = (const float*)d_in[6];
    const float* wo       = (const float*)d_in[7];
    float* out = (float*)d_out;

    float *down, *kvnorm, *qpe;
    __nv_bfloat16 *A3, *B3, *Q2, *K2, *V2;
    cudaGetSymbolAddress((void**)&down,   g_down);
    cudaGetSymbolAddress((void**)&kvnorm, g_kvnorm);
    cudaGetSymbolAddress((void**)&qpe,    g_qpe);
    cudaGetSymbolAddress((void**)&A3,     g_A3);
    cudaGetSymbolAddress((void**)&B3,     g_B3);
    cudaGetSymbolAddress((void**)&Q2,     g_Q2);
    cudaGetSymbolAddress((void**)&K2,     g_K2);
    cudaGetSymbolAddress((void**)&V2,     g_V2);

    __nv_bfloat16* B3kv = B3 + (size_t)QL * 3 * DIM;

    // 1) splits + merged down-projection (fp32 out)
    launch_split(x, A3, S_LEN, DIM, 0);
    launch_split(wq_down, B3, QL, DIM, 1);
    launch_split(wkv_down, B3kv, KVL + ROPE_D, DIM, 1);
    launch_gemm3(A3, B3, down, S_LEN, NDOWN, DIM, 0, Q2, K2, V2, qpe);

    // 2) norms
    rms_kernel<<<S_LEN, 256>>>(down + QL, kv_norm_w, kvnorm, KVL, NDOWN, KVL);
    rms_split_kernel<<<S_LEN, 256>>>(down, q_norm_w, A3, QL, NDOWN);

    // 3) q up-projection -> Q2 (nope) + qpe fp32 (pe)
    launch_split(wq_up, B3, NHEAD * QKD, QL, 1);
    launch_gemm3(A3, B3, down, S_LEN, NHEAD * QKD, QL, 1, Q2, K2, V2, qpe);

    // 4) kv up-projection -> K2 (k_nope) + V2 directly
    launch_split(kvnorm, A3, S_LEN, KVL, 0);
    launch_split(wkv_up, B3, NHEAD * (NOPE + VH), KVL, 1);
    launch_gemm3(A3, B3, down, S_LEN, NHEAD * (NOPE + VH), KVL, 2, Q2, K2, V2, qpe);

    // 5) rope -> Q2 pe dims + K2 pe dims (all heads)
    rope_kernel<<<S_LEN, 544>>>(qpe, down, Q2, K2);

    // 6) mma flash attention v2 (epilogue writes bf16x3 into A3)
    cudaFuncSetAttribute(attn_mma2_kernel, cudaFuncAttributeMaxDynamicSharedMemorySize,
                         ATTN_SMEM);
    dim3 agrid(S_LEN / 64, NHEAD);
    attn_mma2_kernel<<<agrid, 256, ATTN_SMEM>>>(Q2, K2, V2, A3);

    // 7) output projection
    launch_split(wo, B3, DIM, NHEAD * VH, 1);
    launch_gemm3(A3, B3, out, S_LEN, DIM, NHEAD * VH, 0, Q2, K2, V2, qpe);
}

// round 14
// speedup vs baseline: 2.0612x; 1.0547x over previous
#include <cuda_runtime.h>
#include <cuda_bf16.h>
#include <math.h>
#include <stdint.h>

// Problem constants
#define S_LEN 2048
#define DIM   2048
#define NHEAD 16
#define KVL   512
#define QL    1536
#define NOPE  128
#define ROPE_D 64
#define VH    128
#define QKD   192
#define EPS   1e-6f
#define NDOWN (QL + KVL + ROPE_D)   // 2112
#define AK (NHEAD * VH)             // 2048

// ---------------- scratch (device globals) ----------------------------------
__device__ float g_down [S_LEN * NDOWN];
__device__ float g_kvnorm[S_LEN * KVL];
__device__ float g_qpe  [S_LEN * NHEAD * QKD];

__device__ __nv_bfloat16 g_A3[(size_t)S_LEN * 3 * DIM];
__device__ __nv_bfloat16 g_B3[(size_t)3072 * 3 * 1536];

__device__ __nv_bfloat16 g_Q2[(size_t)S_LEN * NHEAD * 384];
__device__ __nv_bfloat16 g_K2[(size_t)NHEAD * S_LEN * 384];
__device__ __nv_bfloat16 g_V2[(size_t)NHEAD * S_LEN * 256];

// ---------------- small helpers ---------------------------------------------
__device__ __forceinline__ void split2(float a, float b,
                                       __nv_bfloat162& h2, __nv_bfloat162& l2) {
    __nv_bfloat16 ha = __float2bfloat16(a), hb = __float2bfloat16(b);
    h2 = __halves2bfloat162(ha, hb);
    l2 = __halves2bfloat162(__float2bfloat16(a - __bfloat162float(ha)),
                            __float2bfloat16(b - __bfloat162float(hb)));
}
__device__ __forceinline__ unsigned smem_u32(const void* p) {
    return (unsigned)__cvta_generic_to_shared(p);
}
__device__ __forceinline__ void cp16(unsigned s, const void* g, bool pred) {
    int sz = pred ? 16 : 0;
    asm volatile("cp.async.cg.shared.global [%0], [%1], 16, %2;\n"
                 :: "r"(s), "l"(g), "r"(sz));
}
__device__ __forceinline__ void ldsm_x4(uint32_t& r0, uint32_t& r1,
                                        uint32_t& r2, uint32_t& r3, unsigned addr) {
    asm volatile("ldmatrix.sync.aligned.m8n8.x4.shared.b16 {%0,%1,%2,%3}, [%4];"
                 : "=r"(r0), "=r"(r1), "=r"(r2), "=r"(r3) : "r"(addr));
}
__device__ __forceinline__ void ldsm_x4_t(uint32_t& r0, uint32_t& r1,
                                          uint32_t& r2, uint32_t& r3, unsigned addr) {
    asm volatile("ldmatrix.sync.aligned.m8n8.x4.trans.shared.b16 {%0,%1,%2,%3}, [%4];"
                 : "=r"(r0), "=r"(r1), "=r"(r2), "=r"(r3) : "r"(addr));
}
__device__ __forceinline__ void mma16816(float* c, const uint32_t* a, const uint32_t* b) {
    asm volatile(
        "mma.sync.aligned.m16n8k16.row.col.f32.bf16.bf16.f32 "
        "{%0,%1,%2,%3}, {%4,%5,%6,%7}, {%8,%9}, {%0,%1,%2,%3};"
        : "+f"(c[0]), "+f"(c[1]), "+f"(c[2]), "+f"(c[3])
        : "r"(a[0]), "r"(a[1]), "r"(a[2]), "r"(a[3]), "r"(b[0]), "r"(b[1]));
}

// ---------------- fp32 -> (hi,lo) bf16 split kernel --------------------------
__global__ void split3_kernel(const float* __restrict__ src,
                              __nv_bfloat16* __restrict__ dst,
                              int K, int modeB)
{
    const int r = blockIdx.y;
    const int k = blockIdx.x * 256 + threadIdx.x;
    if (k >= K) return;
    const float v = src[(size_t)r * K + k];
    const __nv_bfloat16 h = __float2bfloat16(v);
    const __nv_bfloat16 l = __float2bfloat16(v - __bfloat162float(h));
    __nv_bfloat16* d = dst + (size_t)r * 3 * K;
    d[k] = h;
    d[K + k]     = modeB ? h : l;
    d[2 * K + k] = modeB ? l : h;
}

// ---------------- RMSNorm ----------------------------------------------------
__global__ void rms_kernel(const float* __restrict__ in, const float* __restrict__ w,
                           float* __restrict__ out, int n, int istride, int ostride)
{
    const int row = blockIdx.x;
    const float* x = in + (size_t)row * istride;

    float ss = 0.f;
    for (int i = threadIdx.x; i < n; i += blockDim.x) {
        float v = x[i];
        ss += v * v;
    }
#pragma unroll
    for (int o = 16; o; o >>= 1) ss += __shfl_xor_sync(0xffffffffu, ss, o);

    __shared__ float warpsum[8];
    __shared__ float sScale;
    const int wid = threadIdx.x >> 5;
    if ((threadIdx.x & 31) == 0) warpsum[wid] = ss;
    __syncthreads();
    if (threadIdx.x == 0) {
        float tot = 0.f;
        for (int i = 0; i < (int)(blockDim.x >> 5); i++) tot += warpsum[i];
        sScale = rsqrtf(tot / (float)n + EPS);
    }
    __syncthreads();
    const float sc = sScale;
    for (int i = threadIdx.x; i < n; i += blockDim.x)
        out[(size_t)row * ostride + i] = x[i] * sc * w[i];
}

__global__ void rms_split_kernel(const float* __restrict__ in, const float* __restrict__ w,
                                 __nv_bfloat16* __restrict__ dst, int n, int istride)
{
    const int row = blockIdx.x;
    const float* x = in + (size_t)row * istride;

    float ss = 0.f;
    for (int i = threadIdx.x; i < n; i += blockDim.x) {
        float v = x[i];
        ss += v * v;
    }
#pragma unroll
    for (int o = 16; o; o >>= 1) ss += __shfl_xor_sync(0xffffffffu, ss, o);

    __shared__ float warpsum[8];
    __shared__ float sScale;
    const int wid = threadIdx.x >> 5;
    if ((threadIdx.x & 31) == 0) warpsum[wid] = ss;
    __syncthreads();
    if (threadIdx.x == 0) {
        float tot = 0.f;
        for (int i = 0; i < (int)(blockDim.x >> 5); i++) tot += warpsum[i];
        sScale = rsqrtf(tot / (float)n + EPS);
    }
    __syncthreads();
    const float sc = sScale;
    __nv_bfloat16* d = dst + (size_t)row * 3 * n;
    for (int i = threadIdx.x; i < n; i += blockDim.x) {
        const float v = x[i] * sc * w[i];
        const __nv_bfloat16 h = __float2bfloat16(v);
        const __nv_bfloat16 l = __float2bfloat16(v - __bfloat162float(h));
        d[i] = h; d[n + i] = l; d[2 * n + i] = h;
    }
}

// ---------------- bf16x3 tensor-core GEMM (fused epilogues) -----------------
#define TBM 128
#define TBN 128
#define TBK 32
#define AP  40
#define STAGES 4
#define GEMM_SMEM (STAGES * 2 * TBM * AP * 2)

__device__ __forceinline__ void fused_store(
    int mode, float v0, float v1, int r, int c,
    float* __restrict__ C, int N,
    __nv_bfloat16* __restrict__ Q2, __nv_bfloat16* __restrict__ K2,
    __nv_bfloat16* __restrict__ V2, float* __restrict__ qpe)
{
    if (mode == 0) {
        *(float2*)(C + (size_t)r * N + c) = make_float2(v0, v1);
        return;
    }
    if (mode == 1) {
        const int h = c / QKD, d = c - h * QKD;
        if (d < NOPE) {
            __nv_bfloat162 h2, l2; split2(v0, v1, h2, l2);
            __nv_bfloat16* dst = Q2 + ((size_t)r * NHEAD + h) * 384 + d;
            *(__nv_bfloat162*)dst = h2;
            *(__nv_bfloat162*)(dst + 192) = l2;
        } else {
            *(float2*)(qpe + (size_t)r * 3072 + c) = make_float2(v0, v1);
        }
    } else {
        const int h = c >> 8, j = c & 255;
        __nv_bfloat162 h2, l2; split2(v0, v1, h2, l2);
        if (j < 128) {
            __nv_bfloat16* dst = K2 + ((size_t)h * S_LEN + r) * 384 + j;
            *(__nv_bfloat162*)dst = h2;
            *(__nv_bfloat162*)(dst + 192) = l2;
        } else {
            __nv_bfloat16* dst = V2 + ((size_t)h * S_LEN + r) * 256 + (j - 128);
            *(__nv_bfloat162*)dst = h2;
            *(__nv_bfloat162*)(dst + 128) = l2;
        }
    }
}

__global__ void __launch_bounds__(256, 2) gemm_bf16x3_kernel(
    const __nv_bfloat16* __restrict__ A,
    const __nv_bfloat16* __restrict__ B,
    float* __restrict__ C, int M, int N, int K3, int mode,
    __nv_bfloat16* __restrict__ Q2, __nv_bfloat16* __restrict__ K2,
    __nv_bfloat16* __restrict__ V2, float* __restrict__ qpe)
{
    extern __shared__ __nv_bfloat16 smem[];
    __nv_bfloat16* As = smem;
    __nv_bfloat16* Bs = smem + STAGES * TBM * AP;

    const int tid = threadIdx.x, lane = tid & 31, wid = tid >> 5;
    const int wm = wid & 1;
    const int wn = wid >> 1;
    const int row0 = blockIdx.y * TBM, col0 = blockIdx.x * TBN;

    const int c0 = tid * 2;
    const int lr = c0 >> 2;
    const int lu = c0 & 3;
    const bool aval = (row0 + lr) < M;
    const bool bval = (col0 + lr) < N;
    const __nv_bfloat16* Ag = A + (size_t)(row0 + lr) * K3 + lu * 8;
    const __nv_bfloat16* Bg = B + (size_t)(col0 + lr) * K3 + lu * 8;
    const unsigned soff = (unsigned)((lr * AP + lu * 8) * 2);

    float acc[4][4][4];
#pragma unroll
    for (int i = 0; i < 4; i++)
#pragma unroll
        for (int j = 0; j < 4; j++)
#pragma unroll
            for (int k = 0; k < 4; k++) acc[i][j][k] = 0.f;

    const int NKB = K3 / TBK;

#define ISSUE_STAGE(KB, ST) do {                                              \
        unsigned sa = smem_u32(As + (ST) * TBM * AP) + soff;                  \
        unsigned sb = smem_u32(Bs + (ST) * TBM * AP) + soff;                  \
        const __nv_bfloat16* ga = Ag + (size_t)(KB) * TBK;                    \
        const __nv_bfloat16* gb = Bg + (size_t)(KB) * TBK;                    \
        cp16(sa, ga, aval);  cp16(sa + 16, ga + 8, aval);                     \
        cp16(sb, gb, bval);  cp16(sb + 16, gb + 8, bval);                     \
        asm volatile("cp.async.commit_group;\n" ::: "memory");                \
    } while (0)

    ISSUE_STAGE(0, 0);
    ISSUE_STAGE(1, 1);
    ISSUE_STAGE(2, 2);

    const unsigned aoff = (unsigned)(((wm * 64 + (lane & 15)) * AP + (lane >> 4) * 8) * 2);
    const unsigned boff = (unsigned)(((wn * 32 + (lane >> 4) * 8 + (lane & 7)) * AP
                                      + ((lane >> 3) & 1) * 8) * 2);

    for (int kb = 0; kb < NKB; ++kb) {
        asm volatile("cp.async.wait_group 2;\n" ::: "memory");
        __syncthreads();

        if (kb + 3 < NKB) { ISSUE_STAGE(kb + 3, (kb + 3) & 3); }
        else { asm volatile("cp.async.commit_group;\n" ::: "memory"); }

        const int st = kb & 3;
        const unsigned aAddr = smem_u32(As + st * TBM * AP) + aoff;
        const unsigned bAddr = smem_u32(Bs + st * TBM * AP) + boff;

        uint32_t af[2][4][4];
        uint32_t bfr[2][4][2];
#pragma unroll
        for (int kk = 0; kk < 2; ++kk) {
#pragma unroll
            for (int mt = 0; mt < 4; ++mt)
                ldsm_x4(af[kk][mt][0], af[kk][mt][1], af[kk][mt][2], af[kk][mt][3],
                        aAddr + (unsigned)((mt * 16 * AP + kk * 16) * 2));
#pragma unroll
            for (int bp = 0; bp < 2; ++bp) {
                uint32_t r0, r1, r2, r3;
                ldsm_x4(r0, r1, r2, r3,
                        bAddr + (unsigned)((bp * 16 * AP + kk * 16) * 2));
                bfr[kk][2 * bp][0] = r0;      bfr[kk][2 * bp][1] = r1;
                bfr[kk][2 * bp + 1][0] = r2;  bfr[kk][2 * bp + 1][1] = r3;
            }
        }
#pragma unroll
        for (int kk = 0; kk < 2; ++kk)
#pragma unroll
            for (int mt = 0; mt < 4; ++mt)
#pragma unroll
                for (int nt = 0; nt < 4; ++nt)
                    mma16816(acc[mt][nt], af[kk][mt], bfr[kk][nt]);
    }

#pragma unroll
    for (int mt = 0; mt < 4; ++mt) {
#pragma unroll
        for (int nt = 0; nt < 4; ++nt) {
            const int r = row0 + wm * 64 + mt * 16 + (lane >> 2);
            const int c = col0 + wn * 32 + nt * 8 + (lane & 3) * 2;
            if (c < N) {
                if (r < M)
                    fused_store(mode, acc[mt][nt][0], acc[mt][nt][1], r, c,
                                C, N, Q2, K2, V2, qpe);
                if (r + 8 < M)
                    fused_store(mode, acc[mt][nt][2], acc[mt][nt][3], r + 8, c,
                                C, N, Q2, K2, V2, qpe);
            }
        }
    }
#undef ISSUE_STAGE
}

// ---------------- RoPE -------------------------------------------------------
__global__ void rope_kernel(const float* __restrict__ qpe, const float* __restrict__ down,
                            __nv_bfloat16* __restrict__ Q2, __nv_bfloat16* __restrict__ K2)
{
    const int s = blockIdx.x;
    const int tid = threadIdx.x;
    const int h = tid >> 5;
    const int i = tid & 31;
    if (h > 16) return;

    const float invf = powf(10000.f, -(float)i / 32.f);
    const float ang = (float)s * invf;
    float sn, c;
    sincosf(ang, &sn, &c);

    if (h < 16) {
        const float* p = qpe + (size_t)s * 3072 + h * QKD + NOPE + 2 * i;
        const float x0 = p[0], x1 = p[1];
        __nv_bfloat162 h2, l2;
        split2(x0 * c - x1 * sn, x0 * sn + x1 * c, h2, l2);
        __nv_bfloat16* dst = Q2 + ((size_t)s * NHEAD + h) * 384 + NOPE + 2 * i;
        *(__nv_bfloat162*)dst = h2;
        *(__nv_bfloat162*)(dst + 192) = l2;
    } else {
        const float* p = down + (size_t)s * NDOWN + QL + KVL + 2 * i;
        const float x0 = p[0], x1 = p[1];
        __nv_bfloat162 h2, l2;
        split2(x0 * c - x1 * sn, x0 * sn + x1 * c, h2, l2);
#pragma unroll
        for (int hh = 0; hh < NHEAD; hh++) {
            __nv_bfloat16* dst = K2 + ((size_t)hh * S_LEN + s) * 384 + NOPE + 2 * i;
            *(__nv_bfloat162*)dst = h2;
            *(__nv_bfloat162*)(dst + 192) = l2;
        }
    }
}

// ---------------- MMA flash attention v3 (register softmax) -----------------
#define QPU 49
#define VPU 33
#define KBUF_B (32 * QPU * 16)
#define VBUF_B (32 * VPU * 16)
#define OFF_QS  0
#define OFF_KS  (64 * QPU * 16)
#define OFF_VS  (OFF_KS + 2 * KBUF_B)
#define OFF_MAX (OFF_VS + 2 * VBUF_B)
#define ATTN_SMEM (OFF_MAX + 512)
#define STG_STRIDE 68    // floats; 272 B, 16B-aligned

__device__ __forceinline__ float fexp2(float x) {
    x = fmaxf(x, -126.f);
    const float fl = floorf(x);
    const float f = x - fl;
    float p =          1.525273380e-5f;
    p = fmaf(p, f, 1.540353039e-4f);
    p = fmaf(p, f, 1.333355815e-3f);
    p = fmaf(p, f, 9.618129107e-3f);
    p = fmaf(p, f, 5.550410866e-2f);
    p = fmaf(p, f, 2.402265070e-1f);
    p = fmaf(p, f, 6.931471806e-1f);
    p = fmaf(p, f, 1.0f);
    const int i = (int)fl;
    return __int_as_float((i + 127) << 23) * p;
}

__global__ void __launch_bounds__(256) attn_mma3_kernel(
    const __nv_bfloat16* __restrict__ Q2,
    const __nv_bfloat16* __restrict__ K2,
    const __nv_bfloat16* __restrict__ V2,
    __nv_bfloat16* __restrict__ outA3)
{
    const int qt = (int)gridDim.x - 1 - (int)blockIdx.x;
    const int h  = blockIdx.y;
    extern __shared__ char sm8[];
    const unsigned sQS = smem_u32(sm8 + OFF_QS);
    const unsigned sKS = smem_u32(sm8 + OFF_KS);
    const unsigned sVS = smem_u32(sm8 + OFF_VS);
    float* sMax = (float*)(sm8 + OFF_MAX);     // [2][64]

    const int tid = threadIdx.x, lane = tid & 31, wid = tid >> 5;
    const int wm = wid >> 1;     // 0..3 : row slab (16 rows)
    const int wn = wid & 1;      // 0..1 : key half (16 keys)
    const float SCL = 0.07216878364870323f * 1.4426950408889634f;

#define ISSUE_TILE(KT, BUF) do {                                               \
        const __nv_bfloat16* kb_ = K2 + ((size_t)h * S_LEN + (size_t)(KT) * 32) * 384; \
        const __nv_bfloat16* vb_ = V2 + ((size_t)h * S_LEN + (size_t)(KT) * 32) * 256; \
        _Pragma("unroll")                                                      \
        for (int i_ = 0; i_ < 6; i_++) {                                       \
            int c_ = tid + 256 * i_; int r_ = c_ / 48, u_ = c_ - r_ * 48;      \
            cp16(sKS + (BUF) * KBUF_B + (unsigned)((r_ * QPU + u_) * 16),      \
                 kb_ + (size_t)r_ * 384 + u_ * 8, true); }                     \
        _Pragma("unroll")                                                      \
        for (int i_ = 0; i_ < 4; i_++) {                                       \
            int c_ = tid + 256 * i_; int r_ = c_ >> 5, u_ = c_ & 31;           \
            cp16(sVS + (BUF) * VBUF_B + (unsigned)((r_ * VPU + u_) * 16),      \
                 vb_ + (size_t)r_ * 256 + u_ * 8, true); }                     \
        asm volatile("cp.async.commit_group;\n" ::: "memory");                 \
    } while (0)

    {
        const __nv_bfloat16* qb = Q2 + ((size_t)(qt * 64) * NHEAD + h) * 384;
#pragma unroll
        for (int i = 0; i < 12; i++) {
            int c = tid + 256 * i; int r = c / 48, u = c - r * 48;
            cp16(sQS + (unsigned)((r * QPU + u) * 16),
                 qb + (size_t)r * (NHEAD * 384) + u * 8, true);
        }
        ISSUE_TILE(0, 0);
    }

    float accO[16][4];
#pragma unroll
    for (int i = 0; i < 16; i++)
#pragma unroll
        for (int j = 0; j < 4; j++) accO[i][j] = 0.f;

    const int rloc = wm * 16 + (lane >> 2);
    const int qg0 = qt * 64 + rloc;
    const int qg1 = qg0 + 8;
    float m0 = -1e30f, m1 = -1e30f, l0 = 0.f, l1 = 0.f;

    const unsigned aQ = sQS + (unsigned)((((wm * 16 + (lane & 15)) * QPU) + (lane >> 4)) * 16);
    const unsigned bKo = (unsigned)((((wn * 16 + (lane >> 4) * 8 + (lane & 7)) * QPU)
                                     + ((lane >> 3) & 1)) * 16);

    const int nkt = 2 * (qt + 1);
    for (int kt = 0; kt < nkt; ++kt) {
        asm volatile("cp.async.wait_group 0;\n" ::: "memory");
        __syncthreads();
        const int kbuf = kt & 1;

        // ---- QK: 12 chunks, 4 ldsm + 6 mma each ----
        float acc[2][4] = {{0.f,0.f,0.f,0.f},{0.f,0.f,0.f,0.f}};
        const unsigned bK = sKS + (unsigned)(kbuf * KBUF_B) + bKo;
#pragma unroll 4
        for (int c = 0; c < 12; ++c) {
            uint32_t aH[4], aL[4];
            ldsm_x4(aH[0], aH[1], aH[2], aH[3], aQ + (unsigned)(c * 32));
            ldsm_x4(aL[0], aL[1], aL[2], aL[3], aQ + 384u + (unsigned)(c * 32));
            uint32_t h0, h1, h2r, h3;
            ldsm_x4(h0, h1, h2r, h3, bK + (unsigned)(c * 32));
            uint32_t bH0[2] = {h0, h1}, bH1[2] = {h2r, h3};
            uint32_t l0r, l1r, l2r, l3r;
            ldsm_x4(l0r, l1r, l2r, l3r, bK + 384u + (unsigned)(c * 32));
            uint32_t bL0[2] = {l0r, l1r}, bL1[2] = {l2r, l3r};
            mma16816(acc[0], aH, bH0);  mma16816(acc[1], aH, bH1);
            mma16816(acc[0], aL, bH0);  mma16816(acc[1], aL, bH1);
            mma16816(acc[0], aH, bL0);  mma16816(acc[1], aH, bL1);
        }

        // ---- scale + causal mask ----
        const int tg0 = kt * 32;
        const int kbase = tg0 + wn * 16 + (lane & 3) * 2;
        if (kt >= 2 * qt) {
#pragma unroll
            for (int nt = 0; nt < 2; ++nt) {
                const int k0 = kbase + nt * 8, k1 = k0 + 1;
                acc[nt][0] = (k0 <= qg0) ? acc[nt][0] * SCL : -1e30f;
                acc[nt][1] = (k1 <= qg0) ? acc[nt][1] * SCL : -1e30f;
                acc[nt][2] = (k0 <= qg1) ? acc[nt][2] * SCL : -1e30f;
                acc[nt][3] = (k1 <= qg1) ? acc[nt][3] * SCL : -1e30f;
            }
        } else {
#pragma unroll
            for (int nt = 0; nt < 2; ++nt)
#pragma unroll
                for (int e = 0; e < 4; ++e) acc[nt][e] *= SCL;
        }

        // ---- row max (quad shuffles + cross-half via smem) ----
        float mx0 = fmaxf(fmaxf(acc[0][0], acc[0][1]), fmaxf(acc[1][0], acc[1][1]));
        float mx1 = fmaxf(fmaxf(acc[0][2], acc[0][3]), fmaxf(acc[1][2], acc[1][3]));
        mx0 = fmaxf(mx0, __shfl_xor_sync(0xffffffffu, mx0, 1));
        mx0 = fmaxf(mx0, __shfl_xor_sync(0xffffffffu, mx0, 2));
        mx1 = fmaxf(mx1, __shfl_xor_sync(0xffffffffu, mx1, 1));
        mx1 = fmaxf(mx1, __shfl_xor_sync(0xffffffffu, mx1, 2));
        if ((lane & 3) == 0) {
            sMax[wn * 64 + rloc]     = mx0;
            sMax[wn * 64 + rloc + 8] = mx1;
        }
        __syncthreads();
        const float om0 = sMax[(1 - wn) * 64 + rloc];
        const float om1 = sMax[(1 - wn) * 64 + rloc + 8];
        const float mn0 = fmaxf(m0, fmaxf(mx0, om0));
        const float mn1 = fmaxf(m1, fmaxf(mx1, om1));
        const float al0 = fexp2(m0 - mn0);
        const float al1 = fexp2(m1 - mn1);
        m0 = mn0; m1 = mn1;

        // ---- exp + P frags in register ----
        float p00 = fexp2(acc[0][0] - mn0), p01 = fexp2(acc[0][1] - mn0);
        float p02 = fexp2(acc[0][2] - mn1), p03 = fexp2(acc[0][3] - mn1);
        float p10 = fexp2(acc[1][0] - mn0), p11 = fexp2(acc[1][1] - mn0);
        float p12 = fexp2(acc[1][2] - mn1), p13 = fexp2(acc[1][3] - mn1);
        {
            float s0 = p00 + p01 + p10 + p11;
            float s1 = p02 + p03 + p12 + p13;
            s0 += __shfl_xor_sync(0xffffffffu, s0, 1);
            s0 += __shfl_xor_sync(0xffffffffu, s0, 2);
            s1 += __shfl_xor_sync(0xffffffffu, s1, 1);
            s1 += __shfl_xor_sync(0xffffffffu, s1, 2);
            l0 = l0 * al0 + s0;
            l1 = l1 * al1 + s1;
        }
        uint32_t aPh[4], aPl[4];
        {
            __nv_bfloat162 h2, l2;
            split2(p00, p01, h2, l2);
            aPh[0] = *(uint32_t*)&h2; aPl[0] = *(uint32_t*)&l2;
            split2(p02, p03, h2, l2);
            aPh[1] = *(uint32_t*)&h2; aPl[1] = *(uint32_t*)&l2;
            split2(p10, p11, h2, l2);
            aPh[2] = *(uint32_t*)&h2; aPl[2] = *(uint32_t*)&l2;
            split2(p12, p13, h2, l2);
            aPh[3] = *(uint32_t*)&h2; aPl[3] = *(uint32_t*)&l2;
        }

        if (kt + 1 < nkt) { ISSUE_TILE(kt + 1, (kt + 1) & 1); }
        else { asm volatile("cp.async.commit_group;\n" ::: "memory"); }

        // ---- PV: rescale + contraction over this warp's 16 keys ----
#pragma unroll
        for (int nt = 0; nt < 16; ++nt) {
            accO[nt][0] *= al0; accO[nt][1] *= al0;
            accO[nt][2] *= al1; accO[nt][3] *= al1;
        }
        const unsigned vrow = sVS + (unsigned)(kbuf * VBUF_B)
            + (unsigned)((((wn * 16 + (lane & 15)) * VPU) + (lane >> 4)) * 16);
#pragma unroll
        for (int j = 0; j < 8; ++j) {
            uint32_t r0, r1, r2, r3;
            ldsm_x4_t(r0, r1, r2, r3, vrow + (unsigned)((2 * j) * 16));
            uint32_t b0[2] = {r0, r1}, b1[2] = {r2, r3};
            mma16816(accO[2 * j],     aPh, b0);
            mma16816(accO[2 * j + 1], aPh, b1);
            mma16816(accO[2 * j],     aPl, b0);
            mma16816(accO[2 * j + 1], aPl, b1);
        }
#pragma unroll
        for (int j = 0; j < 8; ++j) {
            uint32_t r0, r1, r2, r3;
            ldsm_x4_t(r0, r1, r2, r3, vrow + (unsigned)((16 + 2 * j) * 16));
            uint32_t b0[2] = {r0, r1}, b1[2] = {r2, r3};
            mma16816(accO[2 * j],     aPh, b0);
            mma16816(accO[2 * j + 1], aPh, b1);
        }
    }

    // ---- merge wn halves (stage in smem aliased on K region) ----
    __syncthreads();
    float* stage = (float*)(sm8 + OFF_KS);     // [4][32][STG_STRIDE]
    float* st = stage + (wm * 32 + lane) * STG_STRIDE;
    if (wn == 1) {
#pragma unroll
        for (int nt = 0; nt < 16; ++nt)
            *(float4*)(st + nt * 4) = make_float4(accO[nt][0], accO[nt][1],
                                                  accO[nt][2], accO[nt][3]);
        st[64] = l0; st[65] = l1;
    }
    __syncthreads();
    if (wn == 0) {
#pragma unroll
        for (int nt = 0; nt < 16; ++nt) {
            float4 v = *(float4*)(st + nt * 4);
            accO[nt][0] += v.x; accO[nt][1] += v.y;
            accO[nt][2] += v.z; accO[nt][3] += v.w;
        }
        const float il0 = 1.f / (l0 + st[64]);
        const float il1 = 1.f / (l1 + st[65]);
        const int row0 = qt * 64 + rloc;
        __nv_bfloat16* d0 = outA3 + (size_t)row0 * 3 * AK;
        __nv_bfloat16* d1 = outA3 + (size_t)(row0 + 8) * 3 * AK;
#pragma unroll
        for (int nt = 0; nt < 16; ++nt) {
            const int col = h * VH + nt * 8 + (lane & 3) * 2;
            __nv_bfloat162 h2, l2;
            split2(accO[nt][0] * il0, accO[nt][1] * il0, h2, l2);
            *(__nv_bfloat162*)(d0 + col)          = h2;
            *(__nv_bfloat162*)(d0 + AK + col)     = l2;
            *(__nv_bfloat162*)(d0 + 2 * AK + col) = h2;
            split2(accO[nt][2] * il1, accO[nt][3] * il1, h2, l2);
            *(__nv_bfloat162*)(d1 + col)          = h2;
            *(__nv_bfloat162*)(d1 + AK + col)     = l2;
            *(__nv_bfloat162*)(d1 + 2 * AK + col) = h2;
        }
    }
#undef ISSUE_TILE
}

// ---------------- host orchestration ----------------------------------------
static inline void launch_split(const float* src, __nv_bfloat16* dst,
                                int rows, int K, int modeB)
{
    dim3 grid((K + 255) / 256, rows);
    split3_kernel<<<grid, 256>>>(src, dst, K, modeB);
}

static inline void launch_gemm3(const __nv_bfloat16* A3, const __nv_bfloat16* B3,
                                float* C, int M, int N, int K, int mode,
                                __nv_bfloat16* Q2, __nv_bfloat16* K2,
                                __nv_bfloat16* V2, float* qpe)
{
    cudaFuncSetAttribute(gemm_bf16x3_kernel,
                         cudaFuncAttributeMaxDynamicSharedMemorySize, GEMM_SMEM);
    dim3 grid((N + TBN - 1) / TBN, (M + TBM - 1) / TBM);
    gemm_bf16x3_kernel<<<grid, 256, GEMM_SMEM>>>(A3, B3, C, M, N, 3 * K, mode,
                                                 Q2, K2, V2, qpe);
}

extern "C" void kernel_launch(void* const* d_in, const int* in_sizes, int n_in,
                              void* d_out, int out_size)
{
    const float* x        = (const float*)d_in[0];
    const float* wq_down  = (const float*)d_in[1];
    const float* q_norm_w = (const float*)d_in[2];
    const float* wq_up    = (const float*)d_in[3];
    const float* wkv_down = (const float*)d_in[4];
    const float* kv_norm_w= (const float*)d_in[5];
    const float* wkv_up   = (const float*)d_in[6];
    const float* wo       = (const float*)d_in[7];
    float* out = (float*)d_out;

    float *down, *kvnorm, *qpe;
    __nv_bfloat16 *A3, *B3, *Q2, *K2, *V2;
    cudaGetSymbolAddress((void**)&down,   g_down);
    cudaGetSymbolAddress((void**)&kvnorm, g_kvnorm);
    cudaGetSymbolAddress((void**)&qpe,    g_qpe);
    cudaGetSymbolAddress((void**)&A3,     g_A3);
    cudaGetSymbolAddress((void**)&B3,     g_B3);
    cudaGetSymbolAddress((void**)&Q2,     g_Q2);
    cudaGetSymbolAddress((void**)&K2,     g_K2);
    cudaGetSymbolAddress((void**)&V2,     g_V2);

    __nv_bfloat16* B3kv = B3 + (size_t)QL * 3 * DIM;

    // 1) splits + merged down-projection (fp32 out)
    launch_split(x, A3, S_LEN, DIM, 0);
    launch_split(wq_down, B3, QL, DIM, 1);
    launch_split(wkv_down, B3kv, KVL + ROPE_D, DIM, 1);
    launch_gemm3(A3, B3, down, S_LEN, NDOWN, DIM, 0, Q2, K2, V2, qpe);

    // 2) norms
    rms_kernel<<<S_LEN, 256>>>(down + QL, kv_norm_w, kvnorm, KVL, NDOWN, KVL);
    rms_split_kernel<<<S_LEN, 256>>>(down, q_norm_w, A3, QL, NDOWN);

    // 3) q up-projection -> Q2 (nope) + qpe fp32 (pe)
    launch_split(wq_up, B3, NHEAD * QKD, QL, 1);
    launch_gemm3(A3, B3, down, S_LEN, NHEAD * QKD, QL, 1, Q2, K2, V2, qpe);

    // 4) kv up-projection -> K2 + V2 directly
    launch_split(kvnorm, A3, S_LEN, KVL, 0);
    launch_split(wkv_up, B3, NHEAD * (NOPE + VH), KVL, 1);
    launch_gemm3(A3, B3, down, S_LEN, NHEAD * (NOPE + VH), KVL, 2, Q2, K2, V2, qpe);

    // 5) rope -> Q2 pe dims + K2 pe dims (all heads)
    rope_kernel<<<S_LEN, 544>>>(qpe, down, Q2, K2);

    // 6) mma flash attention v3 (epilogue writes bf16x3 into A3)
    cudaFuncSetAttribute(attn_mma3_kernel, cudaFuncAttributeMaxDynamicSharedMemorySize,
                         ATTN_SMEM);
    dim3 agrid(S_LEN / 64, NHEAD);
    attn_mma3_kernel<<<agrid, 256, ATTN_SMEM>>>(Q2, K2, V2, A3);

    // 7) output projection
    launch_split(wo, B3, DIM, NHEAD * VH, 1);
    launch_gemm3(A3, B3, out, S_LEN, DIM, NHEAD * VH, 0, Q2, K2, V2, qpe);
}

// round 15
// speedup vs baseline: 2.6438x; 1.2826x over previous
#include <cuda_runtime.h>
#include <cuda_bf16.h>
#include <cuda_fp16.h>
#include <math.h>
#include <stdint.h>

// Problem constants
#define S_LEN 2048
#define DIM   2048
#define NHEAD 16
#define KVL   512
#define QL    1536
#define NOPE  128
#define ROPE_D 64
#define VH    128
#define QKD   192
#define EPS   1e-6f
#define NDOWN (QL + KVL + ROPE_D)   // 2112
#define AK (NHEAD * VH)             // 2048

// ---------------- scratch (device globals) ----------------------------------
__device__ float g_down [S_LEN * NDOWN];
__device__ float g_kvnorm[S_LEN * KVL];
__device__ float g_qpe  [S_LEN * NHEAD * QKD];

__device__ __half g_A2[(size_t)S_LEN * 2 * DIM];       // fp16x2 A operands
__device__ __half g_B2[(size_t)3072 * 2 * 1536];       // fp16x2 B operands

__device__ __nv_bfloat16 g_Q2[(size_t)S_LEN * NHEAD * 384];
__device__ __nv_bfloat16 g_K2[(size_t)NHEAD * S_LEN * 384];
__device__ __nv_bfloat16 g_V2[(size_t)NHEAD * S_LEN * 256];

// ---------------- small helpers ---------------------------------------------
__device__ __forceinline__ void split2(float a, float b,
                                       __nv_bfloat162& h2, __nv_bfloat162& l2) {
    __nv_bfloat16 ha = __float2bfloat16(a), hb = __float2bfloat16(b);
    h2 = __halves2bfloat162(ha, hb);
    l2 = __halves2bfloat162(__float2bfloat16(a - __bfloat162float(ha)),
                            __float2bfloat16(b - __bfloat162float(hb)));
}
__device__ __forceinline__ void split2h(float a, float b,
                                        __half2& h2, __half2& l2) {
    __half ha = __float2half(a), hb = __float2half(b);
    h2 = __halves2half2(ha, hb);
    l2 = __halves2half2(__float2half(a - __half2float(ha)),
                        __float2half(b - __half2float(hb)));
}
__device__ __forceinline__ unsigned smem_u32(const void* p) {
    return (unsigned)__cvta_generic_to_shared(p);
}
__device__ __forceinline__ void cp16(unsigned s, const void* g, bool pred) {
    int sz = pred ? 16 : 0;
    asm volatile("cp.async.cg.shared.global [%0], [%1], 16, %2;\n"
                 :: "r"(s), "l"(g), "r"(sz));
}
__device__ __forceinline__ void ldsm_x4(uint32_t& r0, uint32_t& r1,
                                        uint32_t& r2, uint32_t& r3, unsigned addr) {
    asm volatile("ldmatrix.sync.aligned.m8n8.x4.shared.b16 {%0,%1,%2,%3}, [%4];"
                 : "=r"(r0), "=r"(r1), "=r"(r2), "=r"(r3) : "r"(addr));
}
__device__ __forceinline__ void ldsm_x4_t(uint32_t& r0, uint32_t& r1,
                                          uint32_t& r2, uint32_t& r3, unsigned addr) {
    asm volatile("ldmatrix.sync.aligned.m8n8.x4.trans.shared.b16 {%0,%1,%2,%3}, [%4];"
                 : "=r"(r0), "=r"(r1), "=r"(r2), "=r"(r3) : "r"(addr));
}
__device__ __forceinline__ void mma16816(float* c, const uint32_t* a, const uint32_t* b) {
    asm volatile(
        "mma.sync.aligned.m16n8k16.row.col.f32.bf16.bf16.f32 "
        "{%0,%1,%2,%3}, {%4,%5,%6,%7}, {%8,%9}, {%0,%1,%2,%3};"
        : "+f"(c[0]), "+f"(c[1]), "+f"(c[2]), "+f"(c[3])
        : "r"(a[0]), "r"(a[1]), "r"(a[2]), "r"(a[3]), "r"(b[0]), "r"(b[1]));
}
__device__ __forceinline__ void mma16816h(float* c, const uint32_t* a, const uint32_t* b) {
    asm volatile(
        "mma.sync.aligned.m16n8k16.row.col.f32.f16.f16.f32 "
        "{%0,%1,%2,%3}, {%4,%5,%6,%7}, {%8,%9}, {%0,%1,%2,%3};"
        : "+f"(c[0]), "+f"(c[1]), "+f"(c[2]), "+f"(c[3])
        : "r"(a[0]), "r"(a[1]), "r"(a[2]), "r"(a[3]), "r"(b[0]), "r"(b[1]));
}

// ---------------- fp32 -> fp16 (hi,lo)/(hi,hi) split kernel ------------------
__global__ void split2_kernel(const float* __restrict__ src,
                              __half* __restrict__ dst,
                              int K, int modeB)
{
    const int r = blockIdx.y;
    const int k = blockIdx.x * 256 + threadIdx.x;
    if (k >= K) return;
    const float v = src[(size_t)r * K + k];
    const __half h = __float2half(v);
    __half* d = dst + (size_t)r * 2 * K;
    d[k] = h;
    d[K + k] = modeB ? h : __float2half(v - __half2float(h));
}

// ---------------- RMSNorm ----------------------------------------------------
__global__ void rms_kernel(const float* __restrict__ in, const float* __restrict__ w,
                           float* __restrict__ out, int n, int istride, int ostride)
{
    const int row = blockIdx.x;
    const float* x = in + (size_t)row * istride;

    float ss = 0.f;
    for (int i = threadIdx.x; i < n; i += blockDim.x) {
        float v = x[i];
        ss += v * v;
    }
#pragma unroll
    for (int o = 16; o; o >>= 1) ss += __shfl_xor_sync(0xffffffffu, ss, o);

    __shared__ float warpsum[8];
    __shared__ float sScale;
    const int wid = threadIdx.x >> 5;
    if ((threadIdx.x & 31) == 0) warpsum[wid] = ss;
    __syncthreads();
    if (threadIdx.x == 0) {
        float tot = 0.f;
        for (int i = 0; i < (int)(blockDim.x >> 5); i++) tot += warpsum[i];
        sScale = rsqrtf(tot / (float)n + EPS);
    }
    __syncthreads();
    const float sc = sScale;
    for (int i = threadIdx.x; i < n; i += blockDim.x)
        out[(size_t)row * ostride + i] = x[i] * sc * w[i];
}

__global__ void rms_split_kernel(const float* __restrict__ in, const float* __restrict__ w,
                                 __half* __restrict__ dst, int n, int istride)
{
    const int row = blockIdx.x;
    const float* x = in + (size_t)row * istride;

    float ss = 0.f;
    for (int i = threadIdx.x; i < n; i += blockDim.x) {
        float v = x[i];
        ss += v * v;
    }
#pragma unroll
    for (int o = 16; o; o >>= 1) ss += __shfl_xor_sync(0xffffffffu, ss, o);

    __shared__ float warpsum[8];
    __shared__ float sScale;
    const int wid = threadIdx.x >> 5;
    if ((threadIdx.x & 31) == 0) warpsum[wid] = ss;
    __syncthreads();
    if (threadIdx.x == 0) {
        float tot = 0.f;
        for (int i = 0; i < (int)(blockDim.x >> 5); i++) tot += warpsum[i];
        sScale = rsqrtf(tot / (float)n + EPS);
    }
    __syncthreads();
    const float sc = sScale;
    __half* d = dst + (size_t)row * 2 * n;
    for (int i = threadIdx.x; i < n; i += blockDim.x) {
        const float v = x[i] * sc * w[i];
        const __half h = __float2half(v);
        d[i] = h;
        d[n + i] = __float2half(v - __half2float(h));
    }
}

// ---------------- fp16x2 tensor-core GEMM (fused epilogues) ------------------
// C[M,N] = (Ah+Al)[M,K2] * Bh[N,K2]^T with A2=[Ah|Al], B2=[Bh|Bh], K2=2K
// mode 0: C fp32; mode 1: q up -> Q2/qpe; mode 2: kv up -> K2g/V2g
#define TBM 128
#define TBN 128
#define TBK 32
#define AP  40
#define STAGES 4
#define GEMM_SMEM (STAGES * 2 * TBM * AP * 2)

__device__ __forceinline__ void fused_store(
    int mode, float v0, float v1, int r, int c,
    float* __restrict__ C, int N,
    __nv_bfloat16* __restrict__ Q2, __nv_bfloat16* __restrict__ K2g,
    __nv_bfloat16* __restrict__ V2g, float* __restrict__ qpe)
{
    if (mode == 0) {
        *(float2*)(C + (size_t)r * N + c) = make_float2(v0, v1);
        return;
    }
    if (mode == 1) {
        const int h = c / QKD, d = c - h * QKD;
        if (d < NOPE) {
            __nv_bfloat162 h2, l2; split2(v0, v1, h2, l2);
            __nv_bfloat16* dst = Q2 + ((size_t)r * NHEAD + h) * 384 + d;
            *(__nv_bfloat162*)dst = h2;
            *(__nv_bfloat162*)(dst + 192) = l2;
        } else {
            *(float2*)(qpe + (size_t)r * 3072 + c) = make_float2(v0, v1);
        }
    } else {
        const int h = c >> 8, j = c & 255;
        __nv_bfloat162 h2, l2; split2(v0, v1, h2, l2);
        if (j < 128) {
            __nv_bfloat16* dst = K2g + ((size_t)h * S_LEN + r) * 384 + j;
            *(__nv_bfloat162*)dst = h2;
            *(__nv_bfloat162*)(dst + 192) = l2;
        } else {
            __nv_bfloat16* dst = V2g + ((size_t)h * S_LEN + r) * 256 + (j - 128);
            *(__nv_bfloat162*)dst = h2;
            *(__nv_bfloat162*)(dst + 128) = l2;
        }
    }
}

__global__ void __launch_bounds__(256, 2) gemm_fp16x2_kernel(
    const __half* __restrict__ A,
    const __half* __restrict__ B,
    float* __restrict__ C, int M, int N, int K2, int mode,
    __nv_bfloat16* __restrict__ Q2, __nv_bfloat16* __restrict__ K2g,
    __nv_bfloat16* __restrict__ V2g, float* __restrict__ qpe)
{
    extern __shared__ __half smem[];
    __half* As = smem;
    __half* Bs = smem + STAGES * TBM * AP;

    const int tid = threadIdx.x, lane = tid & 31, wid = tid >> 5;
    const int wm = wid & 1;
    const int wn = wid >> 1;
    const int row0 = blockIdx.y * TBM, col0 = blockIdx.x * TBN;

    const int c0 = tid * 2;
    const int lr = c0 >> 2;
    const int lu = c0 & 3;
    const bool aval = (row0 + lr) < M;
    const bool bval = (col0 + lr) < N;
    const __half* Ag = A + (size_t)(row0 + lr) * K2 + lu * 8;
    const __half* Bg = B + (size_t)(col0 + lr) * K2 + lu * 8;
    const unsigned soff = (unsigned)((lr * AP + lu * 8) * 2);

    float acc[4][4][4];
#pragma unroll
    for (int i = 0; i < 4; i++)
#pragma unroll
        for (int j = 0; j < 4; j++)
#pragma unroll
            for (int k = 0; k < 4; k++) acc[i][j][k] = 0.f;

    const int NKB = K2 / TBK;

#define ISSUE_STAGE(KB, ST) do {                                              \
        unsigned sa = smem_u32(As + (ST) * TBM * AP) + soff;                  \
        unsigned sb = smem_u32(Bs + (ST) * TBM * AP) + soff;                  \
        const __half* ga = Ag + (size_t)(KB) * TBK;                           \
        const __half* gb = Bg + (size_t)(KB) * TBK;                           \
        cp16(sa, ga, aval);  cp16(sa + 16, ga + 8, aval);                     \
        cp16(sb, gb, bval);  cp16(sb + 16, gb + 8, bval);                     \
        asm volatile("cp.async.commit_group;\n" ::: "memory");                \
    } while (0)

    ISSUE_STAGE(0, 0);
    ISSUE_STAGE(1, 1);
    ISSUE_STAGE(2, 2);

    const unsigned aoff = (unsigned)(((wm * 64 + (lane & 15)) * AP + (lane >> 4) * 8) * 2);
    const unsigned boff = (unsigned)(((wn * 32 + (lane >> 4) * 8 + (lane & 7)) * AP
                                      + ((lane >> 3) & 1) * 8) * 2);

    for (int kb = 0; kb < NKB; ++kb) {
        asm volatile("cp.async.wait_group 2;\n" ::: "memory");
        __syncthreads();

        if (kb + 3 < NKB) { ISSUE_STAGE(kb + 3, (kb + 3) & 3); }
        else { asm volatile("cp.async.commit_group;\n" ::: "memory"); }

        const int st = kb & 3;
        const unsigned aAddr = smem_u32(As + st * TBM * AP) + aoff;
        const unsigned bAddr = smem_u32(Bs + st * TBM * AP) + boff;

        uint32_t af[2][4][4];
        uint32_t bfr[2][4][2];
#pragma unroll
        for (int kk = 0; kk < 2; ++kk) {
#pragma unroll
            for (int mt = 0; mt < 4; ++mt)
                ldsm_x4(af[kk][mt][0], af[kk][mt][1], af[kk][mt][2], af[kk][mt][3],
                        aAddr + (unsigned)((mt * 16 * AP + kk * 16) * 2));
#pragma unroll
            for (int bp = 0; bp < 2; ++bp) {
                uint32_t r0, r1, r2, r3;
                ldsm_x4(r0, r1, r2, r3,
                        bAddr + (unsigned)((bp * 16 * AP + kk * 16) * 2));
                bfr[kk][2 * bp][0] = r0;      bfr[kk][2 * bp][1] = r1;
                bfr[kk][2 * bp + 1][0] = r2;  bfr[kk][2 * bp + 1][1] = r3;
            }
        }
#pragma unroll
        for (int kk = 0; kk < 2; ++kk)
#pragma unroll
            for (int mt = 0; mt < 4; ++mt)
#pragma unroll
                for (int nt = 0; nt < 4; ++nt)
                    mma16816h(acc[mt][nt], af[kk][mt], bfr[kk][nt]);
    }

#pragma unroll
    for (int mt = 0; mt < 4; ++mt) {
#pragma unroll
        for (int nt = 0; nt < 4; ++nt) {
            const int r = row0 + wm * 64 + mt * 16 + (lane >> 2);
            const int c = col0 + wn * 32 + nt * 8 + (lane & 3) * 2;
            if (c < N) {
                if (r < M)
                    fused_store(mode, acc[mt][nt][0], acc[mt][nt][1], r, c,
                                C, N, Q2, K2g, V2g, qpe);
                if (r + 8 < M)
                    fused_store(mode, acc[mt][nt][2], acc[mt][nt][3], r + 8, c,
                                C, N, Q2, K2g, V2g, qpe);
            }
        }
    }
#undef ISSUE_STAGE
}

// ---------------- RoPE -------------------------------------------------------
__global__ void rope_kernel(const float* __restrict__ qpe, const float* __restrict__ down,
                            __nv_bfloat16* __restrict__ Q2, __nv_bfloat16* __restrict__ K2g)
{
    const int s = blockIdx.x;
    const int tid = threadIdx.x;
    const int h = tid >> 5;
    const int i = tid & 31;
    if (h > 16) return;

    const float invf = powf(10000.f, -(float)i / 32.f);
    const float ang = (float)s * invf;
    float sn, c;
    sincosf(ang, &sn, &c);

    if (h < 16) {
        const float* p = qpe + (size_t)s * 3072 + h * QKD + NOPE + 2 * i;
        const float x0 = p[0], x1 = p[1];
        __nv_bfloat162 h2, l2;
        split2(x0 * c - x1 * sn, x0 * sn + x1 * c, h2, l2);
        __nv_bfloat16* dst = Q2 + ((size_t)s * NHEAD + h) * 384 + NOPE + 2 * i;
        *(__nv_bfloat162*)dst = h2;
        *(__nv_bfloat162*)(dst + 192) = l2;
    } else {
        const float* p = down + (size_t)s * NDOWN + QL + KVL + 2 * i;
        const float x0 = p[0], x1 = p[1];
        __nv_bfloat162 h2, l2;
        split2(x0 * c - x1 * sn, x0 * sn + x1 * c, h2, l2);
#pragma unroll
        for (int hh = 0; hh < NHEAD; hh++) {
            __nv_bfloat16* dst = K2g + ((size_t)hh * S_LEN + s) * 384 + NOPE + 2 * i;
            *(__nv_bfloat162*)dst = h2;
            *(__nv_bfloat162*)(dst + 192) = l2;
        }
    }
}

// ---------------- MMA flash attention v3 (register softmax, bf16x3) ---------
#define QPU 49
#define VPU 33
#define KBUF_B (32 * QPU * 16)
#define VBUF_B (32 * VPU * 16)
#define OFF_QS  0
#define OFF_KS  (64 * QPU * 16)
#define OFF_VS  (OFF_KS + 2 * KBUF_B)
#define OFF_MAX (OFF_VS + 2 * VBUF_B)
#define ATTN_SMEM (OFF_MAX + 512)
#define STG_STRIDE 68

__device__ __forceinline__ float fexp2(float x) {
    x = fmaxf(x, -126.f);
    const float fl = floorf(x);
    const float f = x - fl;
    float p =          1.525273380e-5f;
    p = fmaf(p, f, 1.540353039e-4f);
    p = fmaf(p, f, 1.333355815e-3f);
    p = fmaf(p, f, 9.618129107e-3f);
    p = fmaf(p, f, 5.550410866e-2f);
    p = fmaf(p, f, 2.402265070e-1f);
    p = fmaf(p, f, 6.931471806e-1f);
    p = fmaf(p, f, 1.0f);
    const int i = (int)fl;
    return __int_as_float((i + 127) << 23) * p;
}

__global__ void __launch_bounds__(256) attn_mma3_kernel(
    const __nv_bfloat16* __restrict__ Q2,
    const __nv_bfloat16* __restrict__ K2g,
    const __nv_bfloat16* __restrict__ V2g,
    __half* __restrict__ outA2)    // [S][2*2048] fp16 [hi|lo] A-layout
{
    const int qt = (int)gridDim.x - 1 - (int)blockIdx.x;
    const int h  = blockIdx.y;
    extern __shared__ char sm8[];
    const unsigned sQS = smem_u32(sm8 + OFF_QS);
    const unsigned sKS = smem_u32(sm8 + OFF_KS);
    const unsigned sVS = smem_u32(sm8 + OFF_VS);
    float* sMax = (float*)(sm8 + OFF_MAX);

    const int tid = threadIdx.x, lane = tid & 31, wid = tid >> 5;
    const int wm = wid >> 1;
    const int wn = wid & 1;
    const float SCL = 0.07216878364870323f * 1.4426950408889634f;

#define ISSUE_TILE(KT, BUF) do {                                               \
        const __nv_bfloat16* kb_ = K2g + ((size_t)h * S_LEN + (size_t)(KT) * 32) * 384; \
        const __nv_bfloat16* vb_ = V2g + ((size_t)h * S_LEN + (size_t)(KT) * 32) * 256; \
        _Pragma("unroll")                                                      \
        for (int i_ = 0; i_ < 6; i_++) {                                       \
            int c_ = tid + 256 * i_; int r_ = c_ / 48, u_ = c_ - r_ * 48;      \
            cp16(sKS + (BUF) * KBUF_B + (unsigned)((r_ * QPU + u_) * 16),      \
                 kb_ + (size_t)r_ * 384 + u_ * 8, true); }                     \
        _Pragma("unroll")                                                      \
        for (int i_ = 0; i_ < 4; i_++) {                                       \
            int c_ = tid + 256 * i_; int r_ = c_ >> 5, u_ = c_ & 31;           \
            cp16(sVS + (BUF) * VBUF_B + (unsigned)((r_ * VPU + u_) * 16),      \
                 vb_ + (size_t)r_ * 256 + u_ * 8, true); }                     \
        asm volatile("cp.async.commit_group;\n" ::: "memory");                 \
    } while (0)

    {
        const __nv_bfloat16* qb = Q2 + ((size_t)(qt * 64) * NHEAD + h) * 384;
#pragma unroll
        for (int i = 0; i < 12; i++) {
            int c = tid + 256 * i; int r = c / 48, u = c - r * 48;
            cp16(sQS + (unsigned)((r * QPU + u) * 16),
                 qb + (size_t)r * (NHEAD * 384) + u * 8, true);
        }
        ISSUE_TILE(0, 0);
    }

    float accO[16][4];
#pragma unroll
    for (int i = 0; i < 16; i++)
#pragma unroll
        for (int j = 0; j < 4; j++) accO[i][j] = 0.f;

    const int rloc = wm * 16 + (lane >> 2);
    const int qg0 = qt * 64 + rloc;
    const int qg1 = qg0 + 8;
    float m0 = -1e30f, m1 = -1e30f, l0 = 0.f, l1 = 0.f;

    const unsigned aQ = sQS + (unsigned)((((wm * 16 + (lane & 15)) * QPU) + (lane >> 4)) * 16);
    const unsigned bKo = (unsigned)((((wn * 16 + (lane >> 4) * 8 + (lane & 7)) * QPU)
                                     + ((lane >> 3) & 1)) * 16);

    const int nkt = 2 * (qt + 1);
    for (int kt = 0; kt < nkt; ++kt) {
        asm volatile("cp.async.wait_group 0;\n" ::: "memory");
        __syncthreads();
        const int kbuf = kt & 1;

        float acc[2][4] = {{0.f,0.f,0.f,0.f},{0.f,0.f,0.f,0.f}};
        const unsigned bK = sKS + (unsigned)(kbuf * KBUF_B) + bKo;
#pragma unroll 4
        for (int c = 0; c < 12; ++c) {
            uint32_t aH[4], aL[4];
            ldsm_x4(aH[0], aH[1], aH[2], aH[3], aQ + (unsigned)(c * 32));
            ldsm_x4(aL[0], aL[1], aL[2], aL[3], aQ + 384u + (unsigned)(c * 32));
            uint32_t h0, h1, h2r, h3;
            ldsm_x4(h0, h1, h2r, h3, bK + (unsigned)(c * 32));
            uint32_t bH0[2] = {h0, h1}, bH1[2] = {h2r, h3};
            uint32_t l0r, l1r, l2r, l3r;
            ldsm_x4(l0r, l1r, l2r, l3r, bK + 384u + (unsigned)(c * 32));
            uint32_t bL0[2] = {l0r, l1r}, bL1[2] = {l2r, l3r};
            mma16816(acc[0], aH, bH0);  mma16816(acc[1], aH, bH1);
            mma16816(acc[0], aL, bH0);  mma16816(acc[1], aL, bH1);
            mma16816(acc[0], aH, bL0);  mma16816(acc[1], aH, bL1);
        }

        const int tg0 = kt * 32;
        const int kbase = tg0 + wn * 16 + (lane & 3) * 2;
        if (kt >= 2 * qt) {
#pragma unroll
            for (int nt = 0; nt < 2; ++nt) {
                const int k0 = kbase + nt * 8, k1 = k0 + 1;
                acc[nt][0] = (k0 <= qg0) ? acc[nt][0] * SCL : -1e30f;
                acc[nt][1] = (k1 <= qg0) ? acc[nt][1] * SCL : -1e30f;
                acc[nt][2] = (k0 <= qg1) ? acc[nt][2] * SCL : -1e30f;
                acc[nt][3] = (k1 <= qg1) ? acc[nt][3] * SCL : -1e30f;
            }
        } else {
#pragma unroll
            for (int nt = 0; nt < 2; ++nt)
#pragma unroll
                for (int e = 0; e < 4; ++e) acc[nt][e] *= SCL;
        }

        float mx0 = fmaxf(fmaxf(acc[0][0], acc[0][1]), fmaxf(acc[1][0], acc[1][1]));
        float mx1 = fmaxf(fmaxf(acc[0][2], acc[0][3]), fmaxf(acc[1][2], acc[1][3]));
        mx0 = fmaxf(mx0, __shfl_xor_sync(0xffffffffu, mx0, 1));
        mx0 = fmaxf(mx0, __shfl_xor_sync(0xffffffffu, mx0, 2));
        mx1 = fmaxf(mx1, __shfl_xor_sync(0xffffffffu, mx1, 1));
        mx1 = fmaxf(mx1, __shfl_xor_sync(0xffffffffu, mx1, 2));
        if ((lane & 3) == 0) {
            sMax[wn * 64 + rloc]     = mx0;
            sMax[wn * 64 + rloc + 8] = mx1;
        }
        __syncthreads();
        const float om0 = sMax[(1 - wn) * 64 + rloc];
        const float om1 = sMax[(1 - wn) * 64 + rloc + 8];
        const float mn0 = fmaxf(m0, fmaxf(mx0, om0));
        const float mn1 = fmaxf(m1, fmaxf(mx1, om1));
        const float al0 = fexp2(m0 - mn0);
        const float al1 = fexp2(m1 - mn1);
        m0 = mn0; m1 = mn1;

        float p00 = fexp2(acc[0][0] - mn0), p01 = fexp2(acc[0][1] - mn0);
        float p02 = fexp2(acc[0][2] - mn1), p03 = fexp2(acc[0][3] - mn1);
        float p10 = fexp2(acc[1][0] - mn0), p11 = fexp2(acc[1][1] - mn0);
        float p12 = fexp2(acc[1][2] - mn1), p13 = fexp2(acc[1][3] - mn1);
        {
            float s0 = p00 + p01 + p10 + p11;
            float s1 = p02 + p03 + p12 + p13;
            s0 += __shfl_xor_sync(0xffffffffu, s0, 1);
            s0 += __shfl_xor_sync(0xffffffffu, s0, 2);
            s1 += __shfl_xor_sync(0xffffffffu, s1, 1);
            s1 += __shfl_xor_sync(0xffffffffu, s1, 2);
            l0 = l0 * al0 + s0;
            l1 = l1 * al1 + s1;
        }
        uint32_t aPh[4], aPl[4];
        {
            __nv_bfloat162 h2, l2;
            split2(p00, p01, h2, l2);
            aPh[0] = *(uint32_t*)&h2; aPl[0] = *(uint32_t*)&l2;
            split2(p02, p03, h2, l2);
            aPh[1] = *(uint32_t*)&h2; aPl[1] = *(uint32_t*)&l2;
            split2(p10, p11, h2, l2);
            aPh[2] = *(uint32_t*)&h2; aPl[2] = *(uint32_t*)&l2;
            split2(p12, p13, h2, l2);
            aPh[3] = *(uint32_t*)&h2; aPl[3] = *(uint32_t*)&l2;
        }

        if (kt + 1 < nkt) { ISSUE_TILE(kt + 1, (kt + 1) & 1); }
        else { asm volatile("cp.async.commit_group;\n" ::: "memory"); }

#pragma unroll
        for (int nt = 0; nt < 16; ++nt) {
            accO[nt][0] *= al0; accO[nt][1] *= al0;
            accO[nt][2] *= al1; accO[nt][3] *= al1;
        }
        const unsigned vrow = sVS + (unsigned)(kbuf * VBUF_B)
            + (unsigned)((((wn * 16 + (lane & 15)) * VPU) + (lane >> 4)) * 16);
#pragma unroll
        for (int j = 0; j < 8; ++j) {
            uint32_t r0, r1, r2, r3;
            ldsm_x4_t(r0, r1, r2, r3, vrow + (unsigned)((2 * j) * 16));
            uint32_t b0[2] = {r0, r1}, b1[2] = {r2, r3};
            mma16816(accO[2 * j],     aPh, b0);
            mma16816(accO[2 * j + 1], aPh, b1);
            mma16816(accO[2 * j],     aPl, b0);
            mma16816(accO[2 * j + 1], aPl, b1);
        }
#pragma unroll
        for (int j = 0; j < 8; ++j) {
            uint32_t r0, r1, r2, r3;
            ldsm_x4_t(r0, r1, r2, r3, vrow + (unsigned)((16 + 2 * j) * 16));
            uint32_t b0[2] = {r0, r1}, b1[2] = {r2, r3};
            mma16816(accO[2 * j],     aPh, b0);
            mma16816(accO[2 * j + 1], aPh, b1);
        }
    }

    // ---- merge wn halves ----
    __syncthreads();
    float* stage = (float*)(sm8 + OFF_KS);     // [4][32][STG_STRIDE]
    float* st = stage + (wm * 32 + lane) * STG_STRIDE;
    if (wn == 1) {
#pragma unroll
        for (int nt = 0; nt < 16; ++nt)
            *(float4*)(st + nt * 4) = make_float4(accO[nt][0], accO[nt][1],
                                                  accO[nt][2], accO[nt][3]);
        st[64] = l0; st[65] = l1;
    }
    __syncthreads();
    if (wn == 0) {
#pragma unroll
        for (int nt = 0; nt < 16; ++nt) {
            float4 v = *(float4*)(st + nt * 4);
            accO[nt][0] += v.x; accO[nt][1] += v.y;
            accO[nt][2] += v.z; accO[nt][3] += v.w;
        }
        const float il0 = 1.f / (l0 + st[64]);
        const float il1 = 1.f / (l1 + st[65]);
        const int row0 = qt * 64 + rloc;
        __half* d0 = outA2 + (size_t)row0 * 2 * AK;
        __half* d1 = outA2 + (size_t)(row0 + 8) * 2 * AK;
#pragma unroll
        for (int nt = 0; nt < 16; ++nt) {
            const int col = h * VH + nt * 8 + (lane & 3) * 2;
            __half2 h2, l2;
            split2h(accO[nt][0] * il0, accO[nt][1] * il0, h2, l2);
            *(__half2*)(d0 + col)      = h2;
            *(__half2*)(d0 + AK + col) = l2;
            split2h(accO[nt][2] * il1, accO[nt][3] * il1, h2, l2);
            *(__half2*)(d1 + col)      = h2;
            *(__half2*)(d1 + AK + col) = l2;
        }
    }
#undef ISSUE_TILE
}

// ---------------- host orchestration ----------------------------------------
static inline void launch_split(const float* src, __half* dst,
                                int rows, int K, int modeB)
{
    dim3 grid((K + 255) / 256, rows);
    split2_kernel<<<grid, 256>>>(src, dst, K, modeB);
}

static inline void launch_gemm2(const __half* A2, const __half* B2,
                                float* C, int M, int N, int K, int mode,
                                __nv_bfloat16* Q2, __nv_bfloat16* K2g,
                                __nv_bfloat16* V2g, float* qpe)
{
    cudaFuncSetAttribute(gemm_fp16x2_kernel,
                         cudaFuncAttributeMaxDynamicSharedMemorySize, GEMM_SMEM);
    dim3 grid((N + TBN - 1) / TBN, (M + TBM - 1) / TBM);
    gemm_fp16x2_kernel<<<grid, 256, GEMM_SMEM>>>(A2, B2, C, M, N, 2 * K, mode,
                                                 Q2, K2g, V2g, qpe);
}

extern "C" void kernel_launch(void* const* d_in, const int* in_sizes, int n_in,
                              void* d_out, int out_size)
{
    const float* x        = (const float*)d_in[0];
    const float* wq_down  = (const float*)d_in[1];
    const float* q_norm_w = (const float*)d_in[2];
    const float* wq_up    = (const float*)d_in[3];
    const float* wkv_down = (const float*)d_in[4];
    const float* kv_norm_w= (const float*)d_in[5];
    const float* wkv_up   = (const float*)d_in[6];
    const float* wo       = (const float*)d_in[7];
    float* out = (float*)d_out;

    float *down, *kvnorm, *qpe;
    __half *A2, *B2;
    __nv_bfloat16 *Q2, *K2g, *V2g;
    cudaGetSymbolAddress((void**)&down,   g_down);
    cudaGetSymbolAddress((void**)&kvnorm, g_kvnorm);
    cudaGetSymbolAddress((void**)&qpe,    g_qpe);
    cudaGetSymbolAddress((void**)&A2,     g_A2);
    cudaGetSymbolAddress((void**)&B2,     g_B2);
    cudaGetSymbolAddress((void**)&Q2,     g_Q2);
    cudaGetSymbolAddress((void**)&K2g,    g_K2);
    cudaGetSymbolAddress((void**)&V2g,    g_V2);

    __half* B2kv = B2 + (size_t)QL * 2 * DIM;

    // 1) splits + merged down-projection (fp32 out)
    launch_split(x, A2, S_LEN, DIM, 0);
    launch_split(wq_down, B2, QL, DIM, 1);
    launch_split(wkv_down, B2kv, KVL + ROPE_D, DIM, 1);
    launch_gemm2(A2, B2, down, S_LEN, NDOWN, DIM, 0, Q2, K2g, V2g, qpe);

    // 2) norms
    rms_kernel<<<S_LEN, 256>>>(down + QL, kv_norm_w, kvnorm, KVL, NDOWN, KVL);
    rms_split_kernel<<<S_LEN, 256>>>(down, q_norm_w, A2, QL, NDOWN);

    // 3) q up-projection -> Q2 (nope) + qpe fp32 (pe)
    launch_split(wq_up, B2, NHEAD * QKD, QL, 1);
    launch_gemm2(A2, B2, down, S_LEN, NHEAD * QKD, QL, 1, Q2, K2g, V2g, qpe);

    // 4) kv up-projection -> K2g + V2g directly
    launch_split(kvnorm, A2, S_LEN, KVL, 0);
    launch_split(wkv_up, B2, NHEAD * (NOPE + VH), KVL, 1);
    launch_gemm2(A2, B2, down, S_LEN, NHEAD * (NOPE + VH), KVL, 2, Q2, K2g, V2g, qpe);

    // 5) rope -> Q2 pe dims + K2g pe dims (all heads)
    rope_kernel<<<S_LEN, 544>>>(qpe, down, Q2, K2g);

    // 6) mma flash attention v3 (epilogue writes fp16x2 into A2)
    cudaFuncSetAttribute(attn_mma3_kernel, cudaFuncAttributeMaxDynamicSharedMemorySize,
                         ATTN_SMEM);
    dim3 agrid(S_LEN / 64, NHEAD);
    attn_mma3_kernel<<<agrid, 256, ATTN_SMEM>>>(Q2, K2g, V2g, A2);

    // 7) output projection
    launch_split(wo, B2, DIM, NHEAD * VH, 1);
    launch_gemm2(A2, B2, out, S_LEN, DIM, NHEAD * VH, 0, Q2, K2g, V2g, qpe);
}

// round 16
// speedup vs baseline: 3.0297x; 1.1460x over previous
#include <cuda_runtime.h>
#include <cuda_bf16.h>
#include <cuda_fp16.h>
#include <math.h>
#include <stdint.h>

// Problem constants
#define S_LEN 2048
#define DIM   2048
#define NHEAD 16
#define KVL   512
#define QL    1536
#define NOPE  128
#define ROPE_D 64
#define VH    128
#define QKD   192
#define EPS   1e-6f
#define NDOWN (QL + KVL + ROPE_D)   // 2112
#define AK (NHEAD * VH)             // 2048

// ---------------- scratch (device globals) ----------------------------------
__device__ float g_down [S_LEN * NDOWN];
__device__ float g_kvnorm[S_LEN * KVL];
__device__ float g_qpe  [S_LEN * NHEAD * QKD];

__device__ __half g_A2[(size_t)S_LEN * 2 * DIM];       // fp16x2 A operands
__device__ __half g_B2[(size_t)3072 * 2 * 1536];       // fp16x2 B operands

__device__ __half g_Q2[(size_t)S_LEN * NHEAD * 384];   // [S][H][hi192|lo192]
__device__ __half g_K2[(size_t)NHEAD * S_LEN * 192];   // [H][S][hi192]
__device__ __half g_V2[(size_t)NHEAD * S_LEN * 128];   // [H][S][hi128]

// ---------------- small helpers ---------------------------------------------
__device__ __forceinline__ void split2h(float a, float b,
                                        __half2& h2, __half2& l2) {
    __half ha = __float2half(a), hb = __float2half(b);
    h2 = __halves2half2(ha, hb);
    l2 = __halves2half2(__float2half(a - __half2float(ha)),
                        __float2half(b - __half2float(hb)));
}
__device__ __forceinline__ unsigned smem_u32(const void* p) {
    return (unsigned)__cvta_generic_to_shared(p);
}
__device__ __forceinline__ void cp16(unsigned s, const void* g, bool pred) {
    int sz = pred ? 16 : 0;
    asm volatile("cp.async.cg.shared.global [%0], [%1], 16, %2;\n"
                 :: "r"(s), "l"(g), "r"(sz));
}
__device__ __forceinline__ void ldsm_x4(uint32_t& r0, uint32_t& r1,
                                        uint32_t& r2, uint32_t& r3, unsigned addr) {
    asm volatile("ldmatrix.sync.aligned.m8n8.x4.shared.b16 {%0,%1,%2,%3}, [%4];"
                 : "=r"(r0), "=r"(r1), "=r"(r2), "=r"(r3) : "r"(addr));
}
__device__ __forceinline__ void ldsm_x4_t(uint32_t& r0, uint32_t& r1,
                                          uint32_t& r2, uint32_t& r3, unsigned addr) {
    asm volatile("ldmatrix.sync.aligned.m8n8.x4.trans.shared.b16 {%0,%1,%2,%3}, [%4];"
                 : "=r"(r0), "=r"(r1), "=r"(r2), "=r"(r3) : "r"(addr));
}
__device__ __forceinline__ void mma16816h(float* c, const uint32_t* a, const uint32_t* b) {
    asm volatile(
        "mma.sync.aligned.m16n8k16.row.col.f32.f16.f16.f32 "
        "{%0,%1,%2,%3}, {%4,%5,%6,%7}, {%8,%9}, {%0,%1,%2,%3};"
        : "+f"(c[0]), "+f"(c[1]), "+f"(c[2]), "+f"(c[3])
        : "r"(a[0]), "r"(a[1]), "r"(a[2]), "r"(a[3]), "r"(b[0]), "r"(b[1]));
}

// ---------------- fp32 -> fp16 (hi,lo)/(hi,hi) split kernel ------------------
__global__ void split2_kernel(const float* __restrict__ src,
                              __half* __restrict__ dst,
                              int K, int modeB)
{
    const int r = blockIdx.y;
    const int k = blockIdx.x * 256 + threadIdx.x;
    if (k >= K) return;
    const float v = src[(size_t)r * K + k];
    const __half h = __float2half(v);
    __half* d = dst + (size_t)r * 2 * K;
    d[k] = h;
    d[K + k] = modeB ? h : __float2half(v - __half2float(h));
}

// ---------------- RMSNorm ----------------------------------------------------
__global__ void rms_kernel(const float* __restrict__ in, const float* __restrict__ w,
                           float* __restrict__ out, int n, int istride, int ostride)
{
    const int row = blockIdx.x;
    const float* x = in + (size_t)row * istride;

    float ss = 0.f;
    for (int i = threadIdx.x; i < n; i += blockDim.x) {
        float v = x[i];
        ss += v * v;
    }
#pragma unroll
    for (int o = 16; o; o >>= 1) ss += __shfl_xor_sync(0xffffffffu, ss, o);

    __shared__ float warpsum[8];
    __shared__ float sScale;
    const int wid = threadIdx.x >> 5;
    if ((threadIdx.x & 31) == 0) warpsum[wid] = ss;
    __syncthreads();
    if (threadIdx.x == 0) {
        float tot = 0.f;
        for (int i = 0; i < (int)(blockDim.x >> 5); i++) tot += warpsum[i];
        sScale = rsqrtf(tot / (float)n + EPS);
    }
    __syncthreads();
    const float sc = sScale;
    for (int i = threadIdx.x; i < n; i += blockDim.x)
        out[(size_t)row * ostride + i] = x[i] * sc * w[i];
}

__global__ void rms_split_kernel(const float* __restrict__ in, const float* __restrict__ w,
                                 __half* __restrict__ dst, int n, int istride)
{
    const int row = blockIdx.x;
    const float* x = in + (size_t)row * istride;

    float ss = 0.f;
    for (int i = threadIdx.x; i < n; i += blockDim.x) {
        float v = x[i];
        ss += v * v;
    }
#pragma unroll
    for (int o = 16; o; o >>= 1) ss += __shfl_xor_sync(0xffffffffu, ss, o);

    __shared__ float warpsum[8];
    __shared__ float sScale;
    const int wid = threadIdx.x >> 5;
    if ((threadIdx.x & 31) == 0) warpsum[wid] = ss;
    __syncthreads();
    if (threadIdx.x == 0) {
        float tot = 0.f;
        for (int i = 0; i < (int)(blockDim.x >> 5); i++) tot += warpsum[i];
        sScale = rsqrtf(tot / (float)n + EPS);
    }
    __syncthreads();
    const float sc = sScale;
    __half* d = dst + (size_t)row * 2 * n;
    for (int i = threadIdx.x; i < n; i += blockDim.x) {
        const float v = x[i] * sc * w[i];
        const __half h = __float2half(v);
        d[i] = h;
        d[n + i] = __float2half(v - __half2float(h));
    }
}

// ---------------- fp16x2 tensor-core GEMM (fused epilogues) ------------------
// C[M,N] = (Ah+Al)[M,K2] * Bh[N,K2]^T with A2=[Ah|Al], B2=[Bh|Bh], K2=2K
// mode 0: C fp32; mode 1: q up -> Q2/qpe; mode 2: kv up -> K2h/V2h (hi only)
#define TBM 128
#define TBN 128
#define TBK 32
#define AP  40
#define STAGES 4
#define GEMM_SMEM (STAGES * 2 * TBM * AP * 2)

__device__ __forceinline__ void fused_store(
    int mode, float v0, float v1, int r, int c,
    float* __restrict__ C, int N,
    __half* __restrict__ Q2, __half* __restrict__ K2h,
    __half* __restrict__ V2h, float* __restrict__ qpe)
{
    if (mode == 0) {
        *(float2*)(C + (size_t)r * N + c) = make_float2(v0, v1);
        return;
    }
    if (mode == 1) {
        const int h = c / QKD, d = c - h * QKD;
        if (d < NOPE) {
            __half2 h2, l2; split2h(v0, v1, h2, l2);
            __half* dst = Q2 + ((size_t)r * NHEAD + h) * 384 + d;
            *(__half2*)dst = h2;
            *(__half2*)(dst + 192) = l2;
        } else {
            *(float2*)(qpe + (size_t)r * 3072 + c) = make_float2(v0, v1);
        }
    } else {
        const int h = c >> 8, j = c & 255;
        __half2 h2 = __halves2half2(__float2half(v0), __float2half(v1));
        if (j < 128) {
            *(__half2*)(K2h + ((size_t)h * S_LEN + r) * 192 + j) = h2;
        } else {
            *(__half2*)(V2h + ((size_t)h * S_LEN + r) * 128 + (j - 128)) = h2;
        }
    }
}

__global__ void __launch_bounds__(256, 2) gemm_fp16x2_kernel(
    const __half* __restrict__ A,
    const __half* __restrict__ B,
    float* __restrict__ C, int M, int N, int K2, int mode,
    __half* __restrict__ Q2, __half* __restrict__ K2h,
    __half* __restrict__ V2h, float* __restrict__ qpe)
{
    extern __shared__ __half smem[];
    __half* As = smem;
    __half* Bs = smem + STAGES * TBM * AP;

    const int tid = threadIdx.x, lane = tid & 31, wid = tid >> 5;
    const int wm = wid & 1;
    const int wn = wid >> 1;
    const int row0 = blockIdx.y * TBM, col0 = blockIdx.x * TBN;

    const int c0 = tid * 2;
    const int lr = c0 >> 2;
    const int lu = c0 & 3;
    const bool aval = (row0 + lr) < M;
    const bool bval = (col0 + lr) < N;
    const __half* Ag = A + (size_t)(row0 + lr) * K2 + lu * 8;
    const __half* Bg = B + (size_t)(col0 + lr) * K2 + lu * 8;
    const unsigned soff = (unsigned)((lr * AP + lu * 8) * 2);

    float acc[4][4][4];
#pragma unroll
    for (int i = 0; i < 4; i++)
#pragma unroll
        for (int j = 0; j < 4; j++)
#pragma unroll
            for (int k = 0; k < 4; k++) acc[i][j][k] = 0.f;

    const int NKB = K2 / TBK;

#define ISSUE_STAGE(KB, ST) do {                                              \
        unsigned sa = smem_u32(As + (ST) * TBM * AP) + soff;                  \
        unsigned sb = smem_u32(Bs + (ST) * TBM * AP) + soff;                  \
        const __half* ga = Ag + (size_t)(KB) * TBK;                           \
        const __half* gb = Bg + (size_t)(KB) * TBK;                           \
        cp16(sa, ga, aval);  cp16(sa + 16, ga + 8, aval);                     \
        cp16(sb, gb, bval);  cp16(sb + 16, gb + 8, bval);                     \
        asm volatile("cp.async.commit_group;\n" ::: "memory");                \
    } while (0)

    ISSUE_STAGE(0, 0);
    ISSUE_STAGE(1, 1);
    ISSUE_STAGE(2, 2);

    const unsigned aoff = (unsigned)(((wm * 64 + (lane & 15)) * AP + (lane >> 4) * 8) * 2);
    const unsigned boff = (unsigned)(((wn * 32 + (lane >> 4) * 8 + (lane & 7)) * AP
                                      + ((lane >> 3) & 1) * 8) * 2);

    for (int kb = 0; kb < NKB; ++kb) {
        asm volatile("cp.async.wait_group 2;\n" ::: "memory");
        __syncthreads();

        if (kb + 3 < NKB) { ISSUE_STAGE(kb + 3, (kb + 3) & 3); }
        else { asm volatile("cp.async.commit_group;\n" ::: "memory"); }

        const int st = kb & 3;
        const unsigned aAddr = smem_u32(As + st * TBM * AP) + aoff;
        const unsigned bAddr = smem_u32(Bs + st * TBM * AP) + boff;

        uint32_t af[2][4][4];
        uint32_t bfr[2][4][2];
#pragma unroll
        for (int kk = 0; kk < 2; ++kk) {
#pragma unroll
            for (int mt = 0; mt < 4; ++mt)
                ldsm_x4(af[kk][mt][0], af[kk][mt][1], af[kk][mt][2], af[kk][mt][3],
                        aAddr + (unsigned)((mt * 16 * AP + kk * 16) * 2));
#pragma unroll
            for (int bp = 0; bp < 2; ++bp) {
                uint32_t r0, r1, r2, r3;
                ldsm_x4(r0, r1, r2, r3,
                        bAddr + (unsigned)((bp * 16 * AP + kk * 16) * 2));
                bfr[kk][2 * bp][0] = r0;      bfr[kk][2 * bp][1] = r1;
                bfr[kk][2 * bp + 1][0] = r2;  bfr[kk][2 * bp + 1][1] = r3;
            }
        }
#pragma unroll
        for (int kk = 0; kk < 2; ++kk)
#pragma unroll
            for (int mt = 0; mt < 4; ++mt)
#pragma unroll
                for (int nt = 0; nt < 4; ++nt)
                    mma16816h(acc[mt][nt], af[kk][mt], bfr[kk][nt]);
    }

#pragma unroll
    for (int mt = 0; mt < 4; ++mt) {
#pragma unroll
        for (int nt = 0; nt < 4; ++nt) {
            const int r = row0 + wm * 64 + mt * 16 + (lane >> 2);
            const int c = col0 + wn * 32 + nt * 8 + (lane & 3) * 2;
            if (c < N) {
                if (r < M)
                    fused_store(mode, acc[mt][nt][0], acc[mt][nt][1], r, c,
                                C, N, Q2, K2h, V2h, qpe);
                if (r + 8 < M)
                    fused_store(mode, acc[mt][nt][2], acc[mt][nt][3], r + 8, c,
                                C, N, Q2, K2h, V2h, qpe);
            }
        }
    }
#undef ISSUE_STAGE
}

// ---------------- RoPE -------------------------------------------------------
__global__ void rope_kernel(const float* __restrict__ qpe, const float* __restrict__ down,
                            __half* __restrict__ Q2, __half* __restrict__ K2h)
{
    const int s = blockIdx.x;
    const int tid = threadIdx.x;
    const int h = tid >> 5;
    const int i = tid & 31;
    if (h > 16) return;

    const float invf = powf(10000.f, -(float)i / 32.f);
    const float ang = (float)s * invf;
    float sn, c;
    sincosf(ang, &sn, &c);

    if (h < 16) {
        const float* p = qpe + (size_t)s * 3072 + h * QKD + NOPE + 2 * i;
        const float x0 = p[0], x1 = p[1];
        __half2 h2, l2;
        split2h(x0 * c - x1 * sn, x0 * sn + x1 * c, h2, l2);
        __half* dst = Q2 + ((size_t)s * NHEAD + h) * 384 + NOPE + 2 * i;
        *(__half2*)dst = h2;
        *(__half2*)(dst + 192) = l2;
    } else {
        const float* p = down + (size_t)s * NDOWN + QL + KVL + 2 * i;
        const float x0 = p[0], x1 = p[1];
        __half2 h2 = __halves2half2(__float2half(x0 * c - x1 * sn),
                                    __float2half(x0 * sn + x1 * c));
#pragma unroll
        for (int hh = 0; hh < NHEAD; hh++)
            *(__half2*)(K2h + ((size_t)hh * S_LEN + s) * 192 + NOPE + 2 * i) = h2;
    }
}

// ---------------- MMA flash attention v4 (fp16x2, register softmax) ---------
#define QPU 49            // Q row: 384 fp16 = 48 units + 1 pad
#define KPU 25            // K row: 192 fp16 = 24 units + 1 pad
#define VPU 17            // V row: 128 fp16 = 16 units + 1 pad
#define KBUF_B (32 * KPU * 16)    // 12800
#define VBUF_B (32 * VPU * 16)    // 8704
#define OFF_QS  0
#define OFF_KS  (64 * QPU * 16)           // 50176
#define OFF_VS  (OFF_KS + 2 * KBUF_B)     // 75776
#define OFF_MAX (OFF_VS + 2 * VBUF_B)     // 93184
#define ATTN_SMEM (OFF_MAX + 512)         // 93696
#define STG_STRIDE 68

__device__ __forceinline__ float fexp2(float x) {
    x = fmaxf(x, -126.f);
    const float fl = floorf(x);
    const float f = x - fl;
    float p =          1.525273380e-5f;
    p = fmaf(p, f, 1.540353039e-4f);
    p = fmaf(p, f, 1.333355815e-3f);
    p = fmaf(p, f, 9.618129107e-3f);
    p = fmaf(p, f, 5.550410866e-2f);
    p = fmaf(p, f, 2.402265070e-1f);
    p = fmaf(p, f, 6.931471806e-1f);
    p = fmaf(p, f, 1.0f);
    const int i = (int)fl;
    return __int_as_float((i + 127) << 23) * p;
}

__global__ void __launch_bounds__(256) attn_mma4_kernel(
    const __half* __restrict__ Q2,
    const __half* __restrict__ K2h,
    const __half* __restrict__ V2h,
    __half* __restrict__ outA2)    // [S][2*2048] fp16 [hi|lo] A-layout
{
    const int qt = (int)gridDim.x - 1 - (int)blockIdx.x;
    const int h  = blockIdx.y;
    extern __shared__ char sm8[];
    const unsigned sQS = smem_u32(sm8 + OFF_QS);
    const unsigned sKS = smem_u32(sm8 + OFF_KS);
    const unsigned sVS = smem_u32(sm8 + OFF_VS);
    float* sMax = (float*)(sm8 + OFF_MAX);

    const int tid = threadIdx.x, lane = tid & 31, wid = tid >> 5;
    const int wm = wid >> 1;
    const int wn = wid & 1;
    const float SCL = 0.07216878364870323f * 1.4426950408889634f;

#define ISSUE_TILE(KT, BUF) do {                                               \
        const __half* kb_ = K2h + ((size_t)h * S_LEN + (size_t)(KT) * 32) * 192; \
        const __half* vb_ = V2h + ((size_t)h * S_LEN + (size_t)(KT) * 32) * 128; \
        _Pragma("unroll")                                                      \
        for (int i_ = 0; i_ < 3; i_++) {                                       \
            int c_ = tid + 256 * i_; int r_ = c_ / 24, u_ = c_ - r_ * 24;      \
            cp16(sKS + (BUF) * KBUF_B + (unsigned)((r_ * KPU + u_) * 16),      \
                 kb_ + (size_t)r_ * 192 + u_ * 8, true); }                     \
        _Pragma("unroll")                                                      \
        for (int i_ = 0; i_ < 2; i_++) {                                       \
            int c_ = tid + 256 * i_; int r_ = c_ >> 4, u_ = c_ & 15;           \
            cp16(sVS + (BUF) * VBUF_B + (unsigned)((r_ * VPU + u_) * 16),      \
                 vb_ + (size_t)r_ * 128 + u_ * 8, true); }                     \
        asm volatile("cp.async.commit_group;\n" ::: "memory");                 \
    } while (0)

    {
        const __half* qb = Q2 + ((size_t)(qt * 64) * NHEAD + h) * 384;
#pragma unroll
        for (int i = 0; i < 12; i++) {
            int c = tid + 256 * i; int r = c / 48, u = c - r * 48;
            cp16(sQS + (unsigned)((r * QPU + u) * 16),
                 qb + (size_t)r * (NHEAD * 384) + u * 8, true);
        }
        ISSUE_TILE(0, 0);
    }

    float accO[16][4];
#pragma unroll
    for (int i = 0; i < 16; i++)
#pragma unroll
        for (int j = 0; j < 4; j++) accO[i][j] = 0.f;

    const int rloc = wm * 16 + (lane >> 2);
    const int qg0 = qt * 64 + rloc;
    const int qg1 = qg0 + 8;
    float m0 = -1e30f, m1 = -1e30f, l0 = 0.f, l1 = 0.f;

    const unsigned aQ = sQS + (unsigned)((((wm * 16 + (lane & 15)) * QPU) + (lane >> 4)) * 16);
    const unsigned bKo = (unsigned)((((wn * 16 + (lane >> 4) * 8 + (lane & 7)) * KPU)
                                     + ((lane >> 3) & 1)) * 16);

    const int nkt = 2 * (qt + 1);
    for (int kt = 0; kt < nkt; ++kt) {
        asm volatile("cp.async.wait_group 0;\n" ::: "memory");
        __syncthreads();
        const int kbuf = kt & 1;

        // ---- QK: 12 chunks, 3 ldsm + 4 mma each ----
        float acc[2][4] = {{0.f,0.f,0.f,0.f},{0.f,0.f,0.f,0.f}};
        const unsigned bK = sKS + (unsigned)(kbuf * KBUF_B) + bKo;
#pragma unroll 4
        for (int c = 0; c < 12; ++c) {
            uint32_t aH[4], aL[4];
            ldsm_x4(aH[0], aH[1], aH[2], aH[3], aQ + (unsigned)(c * 32));
            ldsm_x4(aL[0], aL[1], aL[2], aL[3], aQ + 384u + (unsigned)(c * 32));
            uint32_t h0, h1, h2r, h3;
            ldsm_x4(h0, h1, h2r, h3, bK + (unsigned)(c * 32));
            uint32_t bH0[2] = {h0, h1}, bH1[2] = {h2r, h3};
            mma16816h(acc[0], aH, bH0);  mma16816h(acc[1], aH, bH1);
            mma16816h(acc[0], aL, bH0);  mma16816h(acc[1], aL, bH1);
        }

        const int tg0 = kt * 32;
        const int kbase = tg0 + wn * 16 + (lane & 3) * 2;
        if (kt >= 2 * qt) {
#pragma unroll
            for (int nt = 0; nt < 2; ++nt) {
                const int k0 = kbase + nt * 8, k1 = k0 + 1;
                acc[nt][0] = (k0 <= qg0) ? acc[nt][0] * SCL : -1e30f;
                acc[nt][1] = (k1 <= qg0) ? acc[nt][1] * SCL : -1e30f;
                acc[nt][2] = (k0 <= qg1) ? acc[nt][2] * SCL : -1e30f;
                acc[nt][3] = (k1 <= qg1) ? acc[nt][3] * SCL : -1e30f;
            }
        } else {
#pragma unroll
            for (int nt = 0; nt < 2; ++nt)
#pragma unroll
                for (int e = 0; e < 4; ++e) acc[nt][e] *= SCL;
        }

        float mx0 = fmaxf(fmaxf(acc[0][0], acc[0][1]), fmaxf(acc[1][0], acc[1][1]));
        float mx1 = fmaxf(fmaxf(acc[0][2], acc[0][3]), fmaxf(acc[1][2], acc[1][3]));
        mx0 = fmaxf(mx0, __shfl_xor_sync(0xffffffffu, mx0, 1));
        mx0 = fmaxf(mx0, __shfl_xor_sync(0xffffffffu, mx0, 2));
        mx1 = fmaxf(mx1, __shfl_xor_sync(0xffffffffu, mx1, 1));
        mx1 = fmaxf(mx1, __shfl_xor_sync(0xffffffffu, mx1, 2));
        if ((lane & 3) == 0) {
            sMax[wn * 64 + rloc]     = mx0;
            sMax[wn * 64 + rloc + 8] = mx1;
        }
        __syncthreads();
        const float om0 = sMax[(1 - wn) * 64 + rloc];
        const float om1 = sMax[(1 - wn) * 64 + rloc + 8];
        const float mn0 = fmaxf(m0, fmaxf(mx0, om0));
        const float mn1 = fmaxf(m1, fmaxf(mx1, om1));
        const float al0 = fexp2(m0 - mn0);
        const float al1 = fexp2(m1 - mn1);
        m0 = mn0; m1 = mn1;

        float p00 = fexp2(acc[0][0] - mn0), p01 = fexp2(acc[0][1] - mn0);
        float p02 = fexp2(acc[0][2] - mn1), p03 = fexp2(acc[0][3] - mn1);
        float p10 = fexp2(acc[1][0] - mn0), p11 = fexp2(acc[1][1] - mn0);
        float p12 = fexp2(acc[1][2] - mn1), p13 = fexp2(acc[1][3] - mn1);
        {
            float s0 = p00 + p01 + p10 + p11;
            float s1 = p02 + p03 + p12 + p13;
            s0 += __shfl_xor_sync(0xffffffffu, s0, 1);
            s0 += __shfl_xor_sync(0xffffffffu, s0, 2);
            s1 += __shfl_xor_sync(0xffffffffu, s1, 1);
            s1 += __shfl_xor_sync(0xffffffffu, s1, 2);
            l0 = l0 * al0 + s0;
            l1 = l1 * al1 + s1;
        }
        uint32_t aPh[4], aPl[4];
        {
            __half2 h2, l2;
            split2h(p00, p01, h2, l2);
            aPh[0] = *(uint32_t*)&h2; aPl[0] = *(uint32_t*)&l2;
            split2h(p02, p03, h2, l2);
            aPh[1] = *(uint32_t*)&h2; aPl[1] = *(uint32_t*)&l2;
            split2h(p10, p11, h2, l2);
            aPh[2] = *(uint32_t*)&h2; aPl[2] = *(uint32_t*)&l2;
            split2h(p12, p13, h2, l2);
            aPh[3] = *(uint32_t*)&h2; aPl[3] = *(uint32_t*)&l2;
        }

        if (kt + 1 < nkt) { ISSUE_TILE(kt + 1, (kt + 1) & 1); }
        else { asm volatile("cp.async.commit_group;\n" ::: "memory"); }

        // ---- PV: rescale + contraction over this warp's 16 keys ----
#pragma unroll
        for (int nt = 0; nt < 16; ++nt) {
            accO[nt][0] *= al0; accO[nt][1] *= al0;
            accO[nt][2] *= al1; accO[nt][3] *= al1;
        }
        const unsigned vrow = sVS + (unsigned)(kbuf * VBUF_B)
            + (unsigned)((((wn * 16 + (lane & 15)) * VPU) + (lane >> 4)) * 16);
#pragma unroll
        for (int j = 0; j < 8; ++j) {
            uint32_t r0, r1, r2, r3;
            ldsm_x4_t(r0, r1, r2, r3, vrow + (unsigned)((2 * j) * 16));
            uint32_t b0[2] = {r0, r1}, b1[2] = {r2, r3};
            mma16816h(accO[2 * j],     aPh, b0);
            mma16816h(accO[2 * j + 1], aPh, b1);
            mma16816h(accO[2 * j],     aPl, b0);
            mma16816h(accO[2 * j + 1], aPl, b1);
        }
    }

    // ---- merge wn halves (stage in smem aliased on K/V region) ----
    __syncthreads();
    float* stage = (float*)(sm8 + OFF_KS);     // [4][32][STG_STRIDE]
    float* st = stage + (wm * 32 + lane) * STG_STRIDE;
    if (wn == 1) {
#pragma unroll
        for (int nt = 0; nt < 16; ++nt)
            *(float4*)(st + nt * 4) = make_float4(accO[nt][0], accO[nt][1],
                                                  accO[nt][2], accO[nt][3]);
        st[64] = l0; st[65] = l1;
    }
    __syncthreads();
    if (wn == 0) {
#pragma unroll
        for (int nt = 0; nt < 16; ++nt) {
            float4 v = *(float4*)(st + nt * 4);
            accO[nt][0] += v.x; accO[nt][1] += v.y;
            accO[nt][2] += v.z; accO[nt][3] += v.w;
        }
        const float il0 = 1.f / (l0 + st[64]);
        const float il1 = 1.f / (l1 + st[65]);
        const int row0 = qt * 64 + rloc;
        __half* d0 = outA2 + (size_t)row0 * 2 * AK;
        __half* d1 = outA2 + (size_t)(row0 + 8) * 2 * AK;
#pragma unroll
        for (int nt = 0; nt < 16; ++nt) {
            const int col = h * VH + nt * 8 + (lane & 3) * 2;
            __half2 h2, l2;
            split2h(accO[nt][0] * il0, accO[nt][1] * il0, h2, l2);
            *(__half2*)(d0 + col)      = h2;
            *(__half2*)(d0 + AK + col) = l2;
            split2h(accO[nt][2] * il1, accO[nt][3] * il1, h2, l2);
            *(__half2*)(d1 + col)      = h2;
            *(__half2*)(d1 + AK + col) = l2;
        }
    }
#undef ISSUE_TILE
}

// ---------------- host orchestration ----------------------------------------
static inline void launch_split(const float* src, __half* dst,
                                int rows, int K, int modeB)
{
    dim3 grid((K + 255) / 256, rows);
    split2_kernel<<<grid, 256>>>(src, dst, K, modeB);
}

static inline void launch_gemm2(const __half* A2, const __half* B2,
                                float* C, int M, int N, int K, int mode,
                                __half* Q2, __half* K2h, __half* V2h, float* qpe)
{
    cudaFuncSetAttribute(gemm_fp16x2_kernel,
                         cudaFuncAttributeMaxDynamicSharedMemorySize, GEMM_SMEM);
    dim3 grid((N + TBN - 1) / TBN, (M + TBM - 1) / TBM);
    gemm_fp16x2_kernel<<<grid, 256, GEMM_SMEM>>>(A2, B2, C, M, N, 2 * K, mode,
                                                 Q2, K2h, V2h, qpe);
}

extern "C" void kernel_launch(void* const* d_in, const int* in_sizes, int n_in,
                              void* d_out, int out_size)
{
    const float* x        = (const float*)d_in[0];
    const float* wq_down  = (const float*)d_in[1];
    const float* q_norm_w = (const float*)d_in[2];
    const float* wq_up    = (const float*)d_in[3];
    const float* wkv_down = (const float*)d_in[4];
    const float* kv_norm_w= (const float*)d_in[5];
    const float* wkv_up   = (const float*)d_in[6];
    const float* wo       = (const float*)d_in[7];
    float* out = (float*)d_out;

    float *down, *kvnorm, *qpe;
    __half *A2, *B2, *Q2, *K2h, *V2h;
    cudaGetSymbolAddress((void**)&down,   g_down);
    cudaGetSymbolAddress((void**)&kvnorm, g_kvnorm);
    cudaGetSymbolAddress((void**)&qpe,    g_qpe);
    cudaGetSymbolAddress((void**)&A2,     g_A2);
    cudaGetSymbolAddress((void**)&B2,     g_B2);
    cudaGetSymbolAddress((void**)&Q2,     g_Q2);
    cudaGetSymbolAddress((void**)&K2h,    g_K2);
    cudaGetSymbolAddress((void**)&V2h,    g_V2);

    __half* B2kv = B2 + (size_t)QL * 2 * DIM;

    // 1) splits + merged down-projection (fp32 out)
    launch_split(x, A2, S_LEN, DIM, 0);
    launch_split(wq_down, B2, QL, DIM, 1);
    launch_split(wkv_down, B2kv, KVL + ROPE_D, DIM, 1);
    launch_gemm2(A2, B2, down, S_LEN, NDOWN, DIM, 0, Q2, K2h, V2h, qpe);

    // 2) norms
    rms_kernel<<<S_LEN, 256>>>(down + QL, kv_norm_w, kvnorm, KVL, NDOWN, KVL);
    rms_split_kernel<<<S_LEN, 256>>>(down, q_norm_w, A2, QL, NDOWN);

    // 3) q up-projection -> Q2 (nope) + qpe fp32 (pe)
    launch_split(wq_up, B2, NHEAD * QKD, QL, 1);
    launch_gemm2(A2, B2, down, S_LEN, NHEAD * QKD, QL, 1, Q2, K2h, V2h, qpe);

    // 4) kv up-projection -> K2h + V2h (hi only)
    launch_split(kvnorm, A2, S_LEN, KVL, 0);
    launch_split(wkv_up, B2, NHEAD * (NOPE + VH), KVL, 1);
    launch_gemm2(A2, B2, down, S_LEN, NHEAD * (NOPE + VH), KVL, 2, Q2, K2h, V2h, qpe);

    // 5) rope -> Q2 pe dims + K2h pe dims (all heads)
    rope_kernel<<<S_LEN, 544>>>(qpe, down, Q2, K2h);

    // 6) mma flash attention v4 (fp16x2; epilogue writes fp16x2 into A2)
    cudaFuncSetAttribute(attn_mma4_kernel, cudaFuncAttributeMaxDynamicSharedMemorySize,
                         ATTN_SMEM);
    dim3 agrid(S_LEN / 64, NHEAD);
    attn_mma4_kernel<<<agrid, 256, ATTN_SMEM>>>(Q2, K2h, V2h, A2);

    // 7) output projection
    launch_split(wo, B2, DIM, NHEAD * VH, 1);
    launch_gemm2(A2, B2, out, S_LEN, DIM, NHEAD * VH, 0, Q2, K2h, V2h, qpe);
}

// round 17
// speedup vs baseline: 3.5264x; 1.1639x over previous
#include <cuda_runtime.h>
#include <cuda_bf16.h>
#include <cuda_fp16.h>
#include <math.h>
#include <stdint.h>

// Problem constants
#define S_LEN 2048
#define DIM   2048
#define NHEAD 16
#define KVL   512
#define QL    1536
#define NOPE  128
#define ROPE_D 64
#define VH    128
#define QKD   192
#define EPS   1e-6f
#define NDOWN (QL + KVL + ROPE_D)   // 2112
#define AK (NHEAD * VH)             // 2048

// ---------------- scratch (device globals) ----------------------------------
__device__ float g_down [S_LEN * NDOWN];
__device__ float g_kvnorm[S_LEN * KVL];
__device__ float g_qpe  [S_LEN * NHEAD * QKD];

__device__ __half g_A2[(size_t)S_LEN * 2 * DIM];
__device__ __half g_B2[(size_t)3072 * 2 * 1536];

__device__ __half g_Q2[(size_t)S_LEN * NHEAD * 384];   // [S][H][hi192|lo192]
__device__ __half g_K2[(size_t)NHEAD * S_LEN * 192];   // [H][S][hi192]
__device__ __half g_V2[(size_t)NHEAD * S_LEN * 128];   // [H][S][hi128]

// ---------------- small helpers ---------------------------------------------
__device__ __forceinline__ void split2h(float a, float b,
                                        __half2& h2, __half2& l2) {
    __half ha = __float2half(a), hb = __float2half(b);
    h2 = __halves2half2(ha, hb);
    l2 = __halves2half2(__float2half(a - __half2float(ha)),
                        __float2half(b - __half2float(hb)));
}
__device__ __forceinline__ unsigned smem_u32(const void* p) {
    return (unsigned)__cvta_generic_to_shared(p);
}
__device__ __forceinline__ void cp16(unsigned s, const void* g, bool pred) {
    int sz = pred ? 16 : 0;
    asm volatile("cp.async.cg.shared.global [%0], [%1], 16, %2;\n"
                 :: "r"(s), "l"(g), "r"(sz));
}
__device__ __forceinline__ void ldsm_x4(uint32_t& r0, uint32_t& r1,
                                        uint32_t& r2, uint32_t& r3, unsigned addr) {
    asm volatile("ldmatrix.sync.aligned.m8n8.x4.shared.b16 {%0,%1,%2,%3}, [%4];"
                 : "=r"(r0), "=r"(r1), "=r"(r2), "=r"(r3) : "r"(addr));
}
__device__ __forceinline__ void ldsm_x4_t(uint32_t& r0, uint32_t& r1,
                                          uint32_t& r2, uint32_t& r3, unsigned addr) {
    asm volatile("ldmatrix.sync.aligned.m8n8.x4.trans.shared.b16 {%0,%1,%2,%3}, [%4];"
                 : "=r"(r0), "=r"(r1), "=r"(r2), "=r"(r3) : "r"(addr));
}
__device__ __forceinline__ void mma16816h(float* c, const uint32_t* a, const uint32_t* b) {
    asm volatile(
        "mma.sync.aligned.m16n8k16.row.col.f32.f16.f16.f32 "
        "{%0,%1,%2,%3}, {%4,%5,%6,%7}, {%8,%9}, {%0,%1,%2,%3};"
        : "+f"(c[0]), "+f"(c[1]), "+f"(c[2]), "+f"(c[3])
        : "r"(a[0]), "r"(a[1]), "r"(a[2]), "r"(a[3]), "r"(b[0]), "r"(b[1]));
}

// ---------------- fp32 -> fp16 (hi,lo)/(hi,hi) split kernel ------------------
__global__ void split2_kernel(const float* __restrict__ src,
                              __half* __restrict__ dst,
                              int K, int modeB)
{
    const int r = blockIdx.y;
    const int k = blockIdx.x * 256 + threadIdx.x;
    if (k >= K) return;
    const float v = src[(size_t)r * K + k];
    const __half h = __float2half(v);
    __half* d = dst + (size_t)r * 2 * K;
    d[k] = h;
    d[K + k] = modeB ? h : __float2half(v - __half2float(h));
}

// ---------------- RMSNorm ----------------------------------------------------
__global__ void rms_kernel(const float* __restrict__ in, const float* __restrict__ w,
                           float* __restrict__ out, int n, int istride, int ostride)
{
    const int row = blockIdx.x;
    const float* x = in + (size_t)row * istride;

    float ss = 0.f;
    for (int i = threadIdx.x; i < n; i += blockDim.x) {
        float v = x[i];
        ss += v * v;
    }
#pragma unroll
    for (int o = 16; o; o >>= 1) ss += __shfl_xor_sync(0xffffffffu, ss, o);

    __shared__ float warpsum[8];
    __shared__ float sScale;
    const int wid = threadIdx.x >> 5;
    if ((threadIdx.x & 31) == 0) warpsum[wid] = ss;
    __syncthreads();
    if (threadIdx.x == 0) {
        float tot = 0.f;
        for (int i = 0; i < (int)(blockDim.x >> 5); i++) tot += warpsum[i];
        sScale = rsqrtf(tot / (float)n + EPS);
    }
    __syncthreads();
    const float sc = sScale;
    for (int i = threadIdx.x; i < n; i += blockDim.x)
        out[(size_t)row * ostride + i] = x[i] * sc * w[i];
}

__global__ void rms_split_kernel(const float* __restrict__ in, const float* __restrict__ w,
                                 __half* __restrict__ dst, int n, int istride)
{
    const int row = blockIdx.x;
    const float* x = in + (size_t)row * istride;

    float ss = 0.f;
    for (int i = threadIdx.x; i < n; i += blockDim.x) {
        float v = x[i];
        ss += v * v;
    }
#pragma unroll
    for (int o = 16; o; o >>= 1) ss += __shfl_xor_sync(0xffffffffu, ss, o);

    __shared__ float warpsum[8];
    __shared__ float sScale;
    const int wid = threadIdx.x >> 5;
    if ((threadIdx.x & 31) == 0) warpsum[wid] = ss;
    __syncthreads();
    if (threadIdx.x == 0) {
        float tot = 0.f;
        for (int i = 0; i < (int)(blockDim.x >> 5); i++) tot += warpsum[i];
        sScale = rsqrtf(tot / (float)n + EPS);
    }
    __syncthreads();
    const float sc = sScale;
    __half* d = dst + (size_t)row * 2 * n;
    for (int i = threadIdx.x; i < n; i += blockDim.x) {
        const float v = x[i] * sc * w[i];
        const __half h = __float2half(v);
        d[i] = h;
        d[n + i] = __float2half(v - __half2float(h));
    }
}

// ---------------- fp16x2 tensor-core GEMM (TBK=64, fused epilogues) ----------
// C[M,N] = (Ah+Al)[M,K2] * Bh[N,K2]^T with A2=[Ah|Al], B2=[Bh|Bh], K2=2K
#define TBM 128
#define TBN 128
#define TBK 64
#define AP  72      // halfs per row: 64 data + 8 pad (9 x16B units, odd)
#define STAGES 3
#define GEMM_SMEM (STAGES * 2 * TBM * AP * 2)   // 110592 B -> 2 CTAs/SM

__device__ __forceinline__ void fused_store(
    int mode, float v0, float v1, int r, int c,
    float* __restrict__ C, int N,
    __half* __restrict__ Q2, __half* __restrict__ K2h,
    __half* __restrict__ V2h, float* __restrict__ qpe)
{
    if (mode == 0) {
        *(float2*)(C + (size_t)r * N + c) = make_float2(v0, v1);
        return;
    }
    if (mode == 1) {
        const int h = c / QKD, d = c - h * QKD;
        if (d < NOPE) {
            __half2 h2, l2; split2h(v0, v1, h2, l2);
            __half* dst = Q2 + ((size_t)r * NHEAD + h) * 384 + d;
            *(__half2*)dst = h2;
            *(__half2*)(dst + 192) = l2;
        } else {
            *(float2*)(qpe + (size_t)r * 3072 + c) = make_float2(v0, v1);
        }
    } else {
        const int h = c >> 8, j = c & 255;
        __half2 h2 = __halves2half2(__float2half(v0), __float2half(v1));
        if (j < 128) {
            *(__half2*)(K2h + ((size_t)h * S_LEN + r) * 192 + j) = h2;
        } else {
            *(__half2*)(V2h + ((size_t)h * S_LEN + r) * 128 + (j - 128)) = h2;
        }
    }
}

__global__ void __launch_bounds__(256, 2) gemm_fp16x2_kernel(
    const __half* __restrict__ A,
    const __half* __restrict__ B,
    float* __restrict__ C, int M, int N, int K2, int mode,
    __half* __restrict__ Q2, __half* __restrict__ K2h,
    __half* __restrict__ V2h, float* __restrict__ qpe)
{
    extern __shared__ __half smem[];
    __half* As = smem;                         // [STAGES][TBM*AP]
    __half* Bs = smem + STAGES * TBM * AP;

    const int tid = threadIdx.x, lane = tid & 31, wid = tid >> 5;
    const int wm = wid & 1;
    const int wn = wid >> 1;
    const int row0 = blockIdx.y * TBM, col0 = blockIdx.x * TBN;

    float acc[4][4][4];
#pragma unroll
    for (int i = 0; i < 4; i++)
#pragma unroll
        for (int j = 0; j < 4; j++)
#pragma unroll
            for (int k = 0; k < 4; k++) acc[i][j][k] = 0.f;

    const int NKB = K2 / TBK;

#define ISSUE_STAGE(KB, ST) do {                                              \
        _Pragma("unroll")                                                     \
        for (int i_ = 0; i_ < 4; i_++) {                                      \
            int c_ = tid + 256 * i_; int r_ = c_ >> 3, u_ = c_ & 7;           \
            cp16(smem_u32(As + (ST) * TBM * AP) + (unsigned)((r_ * AP + u_ * 8) * 2), \
                 A + (size_t)(row0 + r_) * K2 + (size_t)(KB) * TBK + u_ * 8,  \
                 (row0 + r_) < M);                                            \
        }                                                                     \
        _Pragma("unroll")                                                     \
        for (int i_ = 0; i_ < 4; i_++) {                                      \
            int c_ = tid + 256 * i_; int r_ = c_ >> 3, u_ = c_ & 7;           \
            cp16(smem_u32(Bs + (ST) * TBM * AP) + (unsigned)((r_ * AP + u_ * 8) * 2), \
                 B + (size_t)(col0 + r_) * K2 + (size_t)(KB) * TBK + u_ * 8,  \
                 (col0 + r_) < N);                                            \
        }                                                                     \
        asm volatile("cp.async.commit_group;\n" ::: "memory");                \
    } while (0)

    ISSUE_STAGE(0, 0);
    ISSUE_STAGE(1, 1);

    const unsigned aoff = (unsigned)(((wm * 64 + (lane & 15)) * AP + (lane >> 4) * 8) * 2);
    const unsigned boff = (unsigned)(((wn * 32 + (lane >> 4) * 8 + (lane & 7)) * AP
                                      + ((lane >> 3) & 1) * 8) * 2);

    int st = 0;
    for (int kb = 0; kb < NKB; ++kb) {
        asm volatile("cp.async.wait_group 1;\n" ::: "memory");
        __syncthreads();

        if (kb + 2 < NKB) {
            const int ist = (st + 2 >= STAGES) ? st + 2 - STAGES : st + 2;
            ISSUE_STAGE(kb + 2, ist);
        } else {
            asm volatile("cp.async.commit_group;\n" ::: "memory");
        }

        const unsigned aAddr = smem_u32(As + st * TBM * AP) + aoff;
        const unsigned bAddr = smem_u32(Bs + st * TBM * AP) + boff;

#pragma unroll
        for (int kp = 0; kp < 2; ++kp) {
            const unsigned kpo = (unsigned)(kp * 64);   // 2 k16 steps = 32 halfs
            uint32_t af[2][4][4];
            uint32_t bfr[2][4][2];
#pragma unroll
            for (int kk = 0; kk < 2; ++kk) {
#pragma unroll
                for (int mt = 0; mt < 4; ++mt)
                    ldsm_x4(af[kk][mt][0], af[kk][mt][1], af[kk][mt][2], af[kk][mt][3],
                            aAddr + kpo + (unsigned)((mt * 16 * AP) * 2 + kk * 32));
#pragma unroll
                for (int bp = 0; bp < 2; ++bp) {
                    uint32_t r0, r1, r2, r3;
                    ldsm_x4(r0, r1, r2, r3,
                            bAddr + kpo + (unsigned)((bp * 16 * AP) * 2 + kk * 32));
                    bfr[kk][2 * bp][0] = r0;      bfr[kk][2 * bp][1] = r1;
                    bfr[kk][2 * bp + 1][0] = r2;  bfr[kk][2 * bp + 1][1] = r3;
                }
            }
#pragma unroll
            for (int kk = 0; kk < 2; ++kk)
#pragma unroll
                for (int mt = 0; mt < 4; ++mt)
#pragma unroll
                    for (int nt = 0; nt < 4; ++nt)
                        mma16816h(acc[mt][nt], af[kk][mt], bfr[kk][nt]);
        }

        st = (st + 1 == STAGES) ? 0 : st + 1;
    }

#pragma unroll
    for (int mt = 0; mt < 4; ++mt) {
#pragma unroll
        for (int nt = 0; nt < 4; ++nt) {
            const int r = row0 + wm * 64 + mt * 16 + (lane >> 2);
            const int c = col0 + wn * 32 + nt * 8 + (lane & 3) * 2;
            if (c < N) {
                if (r < M)
                    fused_store(mode, acc[mt][nt][0], acc[mt][nt][1], r, c,
                                C, N, Q2, K2h, V2h, qpe);
                if (r + 8 < M)
                    fused_store(mode, acc[mt][nt][2], acc[mt][nt][3], r + 8, c,
                                C, N, Q2, K2h, V2h, qpe);
            }
        }
    }
#undef ISSUE_STAGE
}

// ---------------- RoPE -------------------------------------------------------
__global__ void rope_kernel(const float* __restrict__ qpe, const float* __restrict__ down,
                            __half* __restrict__ Q2, __half* __restrict__ K2h)
{
    const int s = blockIdx.x;
    const int tid = threadIdx.x;
    const int h = tid >> 5;
    const int i = tid & 31;
    if (h > 16) return;

    const float invf = powf(10000.f, -(float)i / 32.f);
    const float ang = (float)s * invf;
    float sn, c;
    sincosf(ang, &sn, &c);

    if (h < 16) {
        const float* p = qpe + (size_t)s * 3072 + h * QKD + NOPE + 2 * i;
        const float x0 = p[0], x1 = p[1];
        __half2 h2, l2;
        split2h(x0 * c - x1 * sn, x0 * sn + x1 * c, h2, l2);
        __half* dst = Q2 + ((size_t)s * NHEAD + h) * 384 + NOPE + 2 * i;
        *(__half2*)dst = h2;
        *(__half2*)(dst + 192) = l2;
    } else {
        const float* p = down + (size_t)s * NDOWN + QL + KVL + 2 * i;
        const float x0 = p[0], x1 = p[1];
        __half2 h2 = __halves2half2(__float2half(x0 * c - x1 * sn),
                                    __float2half(x0 * sn + x1 * c));
#pragma unroll
        for (int hh = 0; hh < NHEAD; hh++)
            *(__half2*)(K2h + ((size_t)hh * S_LEN + s) * 192 + NOPE + 2 * i) = h2;
    }
}

// ---------------- MMA flash attention v4 (fp16x2, 2 CTAs/SM) ----------------
#define QPU 49
#define KPU 25
#define VPU 17
#define KBUF_B (32 * KPU * 16)
#define VBUF_B (32 * VPU * 16)
#define OFF_QS  0
#define OFF_KS  (64 * QPU * 16)
#define OFF_VS  (OFF_KS + 2 * KBUF_B)
#define OFF_MAX (OFF_VS + 2 * VBUF_B)
#define ATTN_SMEM (OFF_MAX + 512)
#define STG_STRIDE 68

__device__ __forceinline__ float fexp2(float x) {
    x = fmaxf(x, -126.f);
    const float fl = floorf(x);
    const float f = x - fl;
    float p =          1.525273380e-5f;
    p = fmaf(p, f, 1.540353039e-4f);
    p = fmaf(p, f, 1.333355815e-3f);
    p = fmaf(p, f, 9.618129107e-3f);
    p = fmaf(p, f, 5.550410866e-2f);
    p = fmaf(p, f, 2.402265070e-1f);
    p = fmaf(p, f, 6.931471806e-1f);
    p = fmaf(p, f, 1.0f);
    const int i = (int)fl;
    return __int_as_float((i + 127) << 23) * p;
}

__global__ void __launch_bounds__(256, 2) attn_mma4_kernel(
    const __half* __restrict__ Q2,
    const __half* __restrict__ K2h,
    const __half* __restrict__ V2h,
    __half* __restrict__ outA2)
{
    const int qt = (int)gridDim.x - 1 - (int)blockIdx.x;
    const int h  = blockIdx.y;
    extern __shared__ char sm8[];
    const unsigned sQS = smem_u32(sm8 + OFF_QS);
    const unsigned sKS = smem_u32(sm8 + OFF_KS);
    const unsigned sVS = smem_u32(sm8 + OFF_VS);
    float* sMax = (float*)(sm8 + OFF_MAX);

    const int tid = threadIdx.x, lane = tid & 31, wid = tid >> 5;
    const int wm = wid >> 1;
    const int wn = wid & 1;
    const float SCL = 0.07216878364870323f * 1.4426950408889634f;

#define ISSUE_TILE(KT, BUF) do {                                               \
        const __half* kb_ = K2h + ((size_t)h * S_LEN + (size_t)(KT) * 32) * 192; \
        const __half* vb_ = V2h + ((size_t)h * S_LEN + (size_t)(KT) * 32) * 128; \
        _Pragma("unroll")                                                      \
        for (int i_ = 0; i_ < 3; i_++) {                                       \
            int c_ = tid + 256 * i_; int r_ = c_ / 24, u_ = c_ - r_ * 24;      \
            cp16(sKS + (BUF) * KBUF_B + (unsigned)((r_ * KPU + u_) * 16),      \
                 kb_ + (size_t)r_ * 192 + u_ * 8, true); }                     \
        _Pragma("unroll")                                                      \
        for (int i_ = 0; i_ < 2; i_++) {                                       \
            int c_ = tid + 256 * i_; int r_ = c_ >> 4, u_ = c_ & 15;           \
            cp16(sVS + (BUF) * VBUF_B + (unsigned)((r_ * VPU + u_) * 16),      \
                 vb_ + (size_t)r_ * 128 + u_ * 8, true); }                     \
        asm volatile("cp.async.commit_group;\n" ::: "memory");                 \
    } while (0)

    {
        const __half* qb = Q2 + ((size_t)(qt * 64) * NHEAD + h) * 384;
#pragma unroll
        for (int i = 0; i < 12; i++) {
            int c = tid + 256 * i; int r = c / 48, u = c - r * 48;
            cp16(sQS + (unsigned)((r * QPU + u) * 16),
                 qb + (size_t)r * (NHEAD * 384) + u * 8, true);
        }
        ISSUE_TILE(0, 0);
    }

    float accO[16][4];
#pragma unroll
    for (int i = 0; i < 16; i++)
#pragma unroll
        for (int j = 0; j < 4; j++) accO[i][j] = 0.f;

    const int rloc = wm * 16 + (lane >> 2);
    const int qg0 = qt * 64 + rloc;
    const int qg1 = qg0 + 8;
    float m0 = -1e30f, m1 = -1e30f, l0 = 0.f, l1 = 0.f;

    const unsigned aQ = sQS + (unsigned)((((wm * 16 + (lane & 15)) * QPU) + (lane >> 4)) * 16);
    const unsigned bKo = (unsigned)((((wn * 16 + (lane >> 4) * 8 + (lane & 7)) * KPU)
                                     + ((lane >> 3) & 1)) * 16);

    const int nkt = 2 * (qt + 1);
    for (int kt = 0; kt < nkt; ++kt) {
        asm volatile("cp.async.wait_group 0;\n" ::: "memory");
        __syncthreads();
        const int kbuf = kt & 1;

        float acc[2][4] = {{0.f,0.f,0.f,0.f},{0.f,0.f,0.f,0.f}};
        const unsigned bK = sKS + (unsigned)(kbuf * KBUF_B) + bKo;
#pragma unroll 4
        for (int c = 0; c < 12; ++c) {
            uint32_t aH[4], aL[4];
            ldsm_x4(aH[0], aH[1], aH[2], aH[3], aQ + (unsigned)(c * 32));
            ldsm_x4(aL[0], aL[1], aL[2], aL[3], aQ + 384u + (unsigned)(c * 32));
            uint32_t h0, h1, h2r, h3;
            ldsm_x4(h0, h1, h2r, h3, bK + (unsigned)(c * 32));
            uint32_t bH0[2] = {h0, h1}, bH1[2] = {h2r, h3};
            mma16816h(acc[0], aH, bH0);  mma16816h(acc[1], aH, bH1);
            mma16816h(acc[0], aL, bH0);  mma16816h(acc[1], aL, bH1);
        }

        const int tg0 = kt * 32;
        const int kbase = tg0 + wn * 16 + (lane & 3) * 2;
        if (kt >= 2 * qt) {
#pragma unroll
            for (int nt = 0; nt < 2; ++nt) {
                const int k0 = kbase + nt * 8, k1 = k0 + 1;
                acc[nt][0] = (k0 <= qg0) ? acc[nt][0] * SCL : -1e30f;
                acc[nt][1] = (k1 <= qg0) ? acc[nt][1] * SCL : -1e30f;
                acc[nt][2] = (k0 <= qg1) ? acc[nt][2] * SCL : -1e30f;
                acc[nt][3] = (k1 <= qg1) ? acc[nt][3] * SCL : -1e30f;
            }
        } else {
#pragma unroll
            for (int nt = 0; nt < 2; ++nt)
#pragma unroll
                for (int e = 0; e < 4; ++e) acc[nt][e] *= SCL;
        }

        float mx0 = fmaxf(fmaxf(acc[0][0], acc[0][1]), fmaxf(acc[1][0], acc[1][1]));
        float mx1 = fmaxf(fmaxf(acc[0][2], acc[0][3]), fmaxf(acc[1][2], acc[1][3]));
        mx0 = fmaxf(mx0, __shfl_xor_sync(0xffffffffu, mx0, 1));
        mx0 = fmaxf(mx0, __shfl_xor_sync(0xffffffffu, mx0, 2));
        mx1 = fmaxf(mx1, __shfl_xor_sync(0xffffffffu, mx1, 1));
        mx1 = fmaxf(mx1, __shfl_xor_sync(0xffffffffu, mx1, 2));
        if ((lane & 3) == 0) {
            sMax[wn * 64 + rloc]     = mx0;
            sMax[wn * 64 + rloc + 8] = mx1;
        }
        __syncthreads();
        const float om0 = sMax[(1 - wn) * 64 + rloc];
        const float om1 = sMax[(1 - wn) * 64 + rloc + 8];
        const float mn0 = fmaxf(m0, fmaxf(mx0, om0));
        const float mn1 = fmaxf(m1, fmaxf(mx1, om1));
        const float al0 = fexp2(m0 - mn0);
        const float al1 = fexp2(m1 - mn1);
        m0 = mn0; m1 = mn1;

        float p00 = fexp2(acc[0][0] - mn0), p01 = fexp2(acc[0][1] - mn0);
        float p02 = fexp2(acc[0][2] - mn1), p03 = fexp2(acc[0][3] - mn1);
        float p10 = fexp2(acc[1][0] - mn0), p11 = fexp2(acc[1][1] - mn0);
        float p12 = fexp2(acc[1][2] - mn1), p13 = fexp2(acc[1][3] - mn1);
        {
            float s0 = p00 + p01 + p10 + p11;
            float s1 = p02 + p03 + p12 + p13;
            s0 += __shfl_xor_sync(0xffffffffu, s0, 1);
            s0 += __shfl_xor_sync(0xffffffffu, s0, 2);
            s1 += __shfl_xor_sync(0xffffffffu, s1, 1);
            s1 += __shfl_xor_sync(0xffffffffu, s1, 2);
            l0 = l0 * al0 + s0;
            l1 = l1 * al1 + s1;
        }
        uint32_t aPh[4], aPl[4];
        {
            __half2 h2, l2;
            split2h(p00, p01, h2, l2);
            aPh[0] = *(uint32_t*)&h2; aPl[0] = *(uint32_t*)&l2;
            split2h(p02, p03, h2, l2);
            aPh[1] = *(uint32_t*)&h2; aPl[1] = *(uint32_t*)&l2;
            split2h(p10, p11, h2, l2);
            aPh[2] = *(uint32_t*)&h2; aPl[2] = *(uint32_t*)&l2;
            split2h(p12, p13, h2, l2);
            aPh[3] = *(uint32_t*)&h2; aPl[3] = *(uint32_t*)&l2;
        }

        if (kt + 1 < nkt) { ISSUE_TILE(kt + 1, (kt + 1) & 1); }
        else { asm volatile("cp.async.commit_group;\n" ::: "memory"); }

#pragma unroll
        for (int nt = 0; nt < 16; ++nt) {
            accO[nt][0] *= al0; accO[nt][1] *= al0;
            accO[nt][2] *= al1; accO[nt][3] *= al1;
        }
        const unsigned vrow = sVS + (unsigned)(kbuf * VBUF_B)
            + (unsigned)((((wn * 16 + (lane & 15)) * VPU) + (lane >> 4)) * 16);
#pragma unroll
        for (int j = 0; j < 8; ++j) {
            uint32_t r0, r1, r2, r3;
            ldsm_x4_t(r0, r1, r2, r3, vrow + (unsigned)((2 * j) * 16));
            uint32_t b0[2] = {r0, r1}, b1[2] = {r2, r3};
            mma16816h(accO[2 * j],     aPh, b0);
            mma16816h(accO[2 * j + 1], aPh, b1);
            mma16816h(accO[2 * j],     aPl, b0);
            mma16816h(accO[2 * j + 1], aPl, b1);
        }
    }

    // ---- merge wn halves (stage in smem aliased on K/V region) ----
    __syncthreads();
    float* stage = (float*)(sm8 + OFF_KS);
    float* st = stage + (wm * 32 + lane) * STG_STRIDE;
    if (wn == 1) {
#pragma unroll
        for (int nt = 0; nt < 16; ++nt)
            *(float4*)(st + nt * 4) = make_float4(accO[nt][0], accO[nt][1],
                                                  accO[nt][2], accO[nt][3]);
        st[64] = l0; st[65] = l1;
    }
    __syncthreads();
    if (wn == 0) {
#pragma unroll
        for (int nt = 0; nt < 16; ++nt) {
            float4 v = *(float4*)(st + nt * 4);
            accO[nt][0] += v.x; accO[nt][1] += v.y;
            accO[nt][2] += v.z; accO[nt][3] += v.w;
        }
        const float il0 = 1.f / (l0 + st[64]);
        const float il1 = 1.f / (l1 + st[65]);
        const int row0 = qt * 64 + rloc;
        __half* d0 = outA2 + (size_t)row0 * 2 * AK;
        __half* d1 = outA2 + (size_t)(row0 + 8) * 2 * AK;
#pragma unroll
        for (int nt = 0; nt < 16; ++nt) {
            const int col = h * VH + nt * 8 + (lane & 3) * 2;
            __half2 h2, l2;
            split2h(accO[nt][0] * il0, accO[nt][1] * il0, h2, l2);
            *(__half2*)(d0 + col)      = h2;
            *(__half2*)(d0 + AK + col) = l2;
            split2h(accO[nt][2] * il1, accO[nt][3] * il1, h2, l2);
            *(__half2*)(d1 + col)      = h2;
            *(__half2*)(d1 + AK + col) = l2;
        }
    }
#undef ISSUE_TILE
}

// ---------------- host orchestration ----------------------------------------
static inline void launch_split(const float* src, __half* dst,
                                int rows, int K, int modeB)
{
    dim3 grid((K + 255) / 256, rows);
    split2_kernel<<<grid, 256>>>(src, dst, K, modeB);
}

static inline void launch_gemm2(const __half* A2, const __half* B2,
                                float* C, int M, int N, int K, int mode,
                                __half* Q2, __half* K2h, __half* V2h, float* qpe)
{
    cudaFuncSetAttribute(gemm_fp16x2_kernel,
                         cudaFuncAttributeMaxDynamicSharedMemorySize, GEMM_SMEM);
    dim3 grid((N + TBN - 1) / TBN, (M + TBM - 1) / TBM);
    gemm_fp16x2_kernel<<<grid, 256, GEMM_SMEM>>>(A2, B2, C, M, N, 2 * K, mode,
                                                 Q2, K2h, V2h, qpe);
}

extern "C" void kernel_launch(void* const* d_in, const int* in_sizes, int n_in,
                              void* d_out, int out_size)
{
    const float* x        = (const float*)d_in[0];
    const float* wq_down  = (const float*)d_in[1];
    const float* q_norm_w = (const float*)d_in[2];
    const float* wq_up    = (const float*)d_in[3];
    const float* wkv_down = (const float*)d_in[4];
    const float* kv_norm_w= (const float*)d_in[5];
    const float* wkv_up   = (const float*)d_in[6];
    const float* wo       = (const float*)d_in[7];
    float* out = (float*)d_out;

    float *down, *kvnorm, *qpe;
    __half *A2, *B2, *Q2, *K2h, *V2h;
    cudaGetSymbolAddress((void**)&down,   g_down);
    cudaGetSymbolAddress((void**)&kvnorm, g_kvnorm);
    cudaGetSymbolAddress((void**)&qpe,    g_qpe);
    cudaGetSymbolAddress((void**)&A2,     g_A2);
    cudaGetSymbolAddress((void**)&B2,     g_B2);
    cudaGetSymbolAddress((void**)&Q2,     g_Q2);
    cudaGetSymbolAddress((void**)&K2h,    g_K2);
    cudaGetSymbolAddress((void**)&V2h,    g_V2);

    __half* B2kv = B2 + (size_t)QL * 2 * DIM;

    // 1) splits + merged down-projection (fp32 out)
    launch_split(x, A2, S_LEN, DIM, 0);
    launch_split(wq_down, B2, QL, DIM, 1);
    launch_split(wkv_down, B2kv, KVL + ROPE_D, DIM, 1);
    launch_gemm2(A2, B2, down, S_LEN, NDOWN, DIM, 0, Q2, K2h, V2h, qpe);

    // 2) norms
    rms_kernel<<<S_LEN, 256>>>(down + QL, kv_norm_w, kvnorm, KVL, NDOWN, KVL);
    rms_split_kernel<<<S_LEN, 256>>>(down, q_norm_w, A2, QL, NDOWN);

    // 3) q up-projection -> Q2 (nope) + qpe fp32 (pe)
    launch_split(wq_up, B2, NHEAD * QKD, QL, 1);
    launch_gemm2(A2, B2, down, S_LEN, NHEAD * QKD, QL, 1, Q2, K2h, V2h, qpe);

    // 4) kv up-projection -> K2h + V2h (hi only)
    launch_split(kvnorm, A2, S_LEN, KVL, 0);
    launch_split(wkv_up, B2, NHEAD * (NOPE + VH), KVL, 1);
    launch_gemm2(A2, B2, down, S_LEN, NHEAD * (NOPE + VH), KVL, 2, Q2, K2h, V2h, qpe);

    // 5) rope -> Q2 pe dims + K2h pe dims (all heads)
    rope_kernel<<<S_LEN, 544>>>(qpe, down, Q2, K2h);

    // 6) mma flash attention v4 (fp16x2, 2 CTAs/SM)
    cudaFuncSetAttribute(attn_mma4_kernel, cudaFuncAttributeMaxDynamicSharedMemorySize,
                         ATTN_SMEM);
    dim3 agrid(S_LEN / 64, NHEAD);
    attn_mma4_kernel<<<agrid, 256, ATTN_SMEM>>>(Q2, K2h, V2h, A2);

    // 7) output projection
    launch_split(wo, B2, DIM, NHEAD * VH, 1);
    launch_gemm2(A2, B2, out, S_LEN, DIM, NHEAD * VH, 0, Q2, K2h, V2h, qpe);
}